// round 1
// baseline (speedup 1.0000x reference)
#include <cuda_runtime.h>
#include <cuda_bf16.h>
#include <cstdint>

#define N_SOTU  100000
#define N_TAXON 20000
#define NE      800000
#define NEL     200000
#define DS      256
#define DT      128
#define HID     256

// ---------------- scratch (device globals; no allocation) ----------------
// layout: [aggT (20000*256)] [aggS (100000*256)] [cntT (20000)] [cntS (100000)]
__device__ float g_scratch[(size_t)N_TAXON*HID + (size_t)N_SOTU*HID + N_TAXON + N_SOTU];
__device__ float g_h1t[(size_t)N_TAXON*HID];
__device__ float g_h1s[(size_t)N_SOTU*HID];
__device__ float g_h2t[(size_t)N_TAXON*HID];
__device__ float g_h2s[(size_t)N_SOTU*HID];
__device__ float g_us[(size_t)N_SOTU*HID];
__device__ float g_ut[(size_t)N_TAXON*HID];
__device__ float g_Wcs[HID*HID];
__device__ float g_Wct[HID*HID];
__device__ float g_bdc[HID];

// ---------------- utility kernels ----------------
__global__ void zero_kernel(float4* p, long long n4) {
    long long i = blockIdx.x * (long long)blockDim.x + threadIdx.x;
    if (i < n4) p[i] = make_float4(0.f, 0.f, 0.f, 0.f);
}

__global__ void count_kernel(const int* __restrict__ src, const int* __restrict__ dst,
                             float* cntS, float* cntT, int E) {
    int e = blockIdx.x * blockDim.x + threadIdx.x;
    if (e < E) {
        atomicAdd(cntS + src[e], 1.f);
        atomicAdd(cntT + dst[e], 1.f);
    }
}

__global__ void inv_kernel(float* p, int n) {
    int i = blockIdx.x * blockDim.x + threadIdx.x;
    if (i < n) p[i] = 1.f / fmaxf(p[i], 1.f);
}

// scatter-add: agg[to[e]][:] += feat[from[e]][:]   (D4 = D/4 float4 columns)
__global__ void scatter_kernel(const float4* __restrict__ feat,
                               const int* __restrict__ from_i,
                               const int* __restrict__ to_i,
                               float4* __restrict__ agg,
                               int D4, long long total) {
    long long gid = blockIdx.x * (long long)blockDim.x + threadIdx.x;
    if (gid >= total) return;
    int e = (int)(gid / D4);
    int c = (int)(gid % D4);
    int f = __ldg(from_i + e);
    int t = __ldg(to_i + e);
    float4 v = feat[(long long)f * D4 + c];
#if __CUDA_ARCH__ >= 900
    atomicAdd(&agg[(long long)t * D4 + c], v);
#else
    float* a = (float*)&agg[(long long)t * D4 + c];
    atomicAdd(a + 0, v.x); atomicAdd(a + 1, v.y);
    atomicAdd(a + 2, v.z); atomicAdd(a + 3, v.w);
#endif
}

// ---------------- fused concat-K GEMM ----------------
// C[n][h] = act( sum_{k<K1} A1[n][k]*scale[n] * W1[h][k]
//              + sum_{k<K2} A2[n][k]          * W2[h][k] + bias[h] )
// A1 row stride = K1, A2 row stride = K2, W row-major [H][K*].
// K1, K2 multiples of 16. Tile 128x128x16, 256 threads, 8x8 per thread.
#define BM 128
#define BN 128
#define BK 16
#define TM 8
#define TN 8

__global__ void __launch_bounds__(256)
gemm_fused(const float* __restrict__ A1, int K1, const float* __restrict__ scale,
           const float* __restrict__ A2, int K2,
           const float* __restrict__ W1, const float* __restrict__ W2,
           const float* __restrict__ bias,
           float* __restrict__ C, int N, int H, int doRelu) {
    __shared__ float As[BK][BM + 4];
    __shared__ float Ws[BK][BN + 4];

    const int tid = threadIdx.x;
    const int bm = blockIdx.y * BM;
    const int bn = blockIdx.x * BN;
    const int K = K1 + K2;

    const int ty = tid / 16, tx = tid % 16;
    const int lrow = tid / 4;            // 0..63
    const int lk   = (tid % 4) * 4;      // 0,4,8,12

    float acc[TM][TN];
#pragma unroll
    for (int i = 0; i < TM; i++)
#pragma unroll
        for (int j = 0; j < TN; j++) acc[i][j] = 0.f;

    for (int k0 = 0; k0 < K; k0 += BK) {
        // ---- load A tile (transposed into smem) ----
#pragma unroll
        for (int half = 0; half < 2; half++) {
            int r = lrow + half * 64;
            int grow = bm + r;
            float4 v = make_float4(0.f, 0.f, 0.f, 0.f);
            float s = 1.f;
            int k = k0 + lk;
            if (grow < N) {
                if (k < K1) {
                    v = *(const float4*)(A1 + (size_t)grow * K1 + k);
                    if (scale) s = scale[grow];
                } else {
                    v = *(const float4*)(A2 + (size_t)grow * K2 + (k - K1));
                }
            }
            As[lk + 0][r] = v.x * s;
            As[lk + 1][r] = v.y * s;
            As[lk + 2][r] = v.z * s;
            As[lk + 3][r] = v.w * s;
        }
        // ---- load W tile (transposed into smem) ----
#pragma unroll
        for (int half = 0; half < 2; half++) {
            int r = lrow + half * 64;
            int gcol = bn + r;
            float4 v = make_float4(0.f, 0.f, 0.f, 0.f);
            int k = k0 + lk;
            if (gcol < H) {
                if (k < K1) v = *(const float4*)(W1 + (size_t)gcol * K1 + k);
                else        v = *(const float4*)(W2 + (size_t)gcol * K2 + (k - K1));
            }
            Ws[lk + 0][r] = v.x;
            Ws[lk + 1][r] = v.y;
            Ws[lk + 2][r] = v.z;
            Ws[lk + 3][r] = v.w;
        }
        __syncthreads();

#pragma unroll
        for (int kk = 0; kk < BK; kk++) {
            float a[TM], b[TN];
#pragma unroll
            for (int i = 0; i < TM; i++) a[i] = As[kk][ty * TM + i];
#pragma unroll
            for (int j = 0; j < TN; j++) b[j] = Ws[kk][tx * TN + j];
#pragma unroll
            for (int i = 0; i < TM; i++)
#pragma unroll
                for (int j = 0; j < TN; j++) acc[i][j] += a[i] * b[j];
        }
        __syncthreads();
    }

    // ---- epilogue ----
#pragma unroll
    for (int i = 0; i < TM; i++) {
        int row = bm + ty * TM + i;
        if (row >= N) continue;
#pragma unroll
        for (int j = 0; j < TN; j += 4) {
            int col = bn + tx * TN + j;
            float4 v;
            v.x = acc[i][j + 0]; v.y = acc[i][j + 1];
            v.z = acc[i][j + 2]; v.w = acc[i][j + 3];
            if (bias) {
                v.x += bias[col + 0]; v.y += bias[col + 1];
                v.z += bias[col + 2]; v.w += bias[col + 3];
            }
            if (doRelu) {
                v.x = fmaxf(v.x, 0.f); v.y = fmaxf(v.y, 0.f);
                v.z = fmaxf(v.z, 0.f); v.w = fmaxf(v.w, 0.f);
            }
            *(float4*)(C + (size_t)row * H + col) = v;
        }
    }
}

// ---------------- weight composition: Wc = Wd1_half @ Wlin, bdc = bd1 + Wd1@blin ----------------
__global__ void compose_kernel(const float* __restrict__ Wd1,
                               const float* __restrict__ Wlin_s,
                               const float* __restrict__ Wlin_t,
                               const float* __restrict__ blin_s,
                               const float* __restrict__ blin_t,
                               const float* __restrict__ bd1,
                               float* Wcs, float* Wct, float* bdc) {
    int i = blockIdx.x;      // output row (H)
    int m = threadIdx.x;     // input col (H)
    float ss = 0.f, st = 0.f;
    for (int k = 0; k < HID; k++) {
        float wl = Wd1[i * 2 * HID + k];
        float wr = Wd1[i * 2 * HID + HID + k];
        ss += wl * Wlin_s[k * HID + m];
        st += wr * Wlin_t[k * HID + m];
    }
    Wcs[i * HID + m] = ss;
    Wct[i * HID + m] = st;
    if (m == 0) {
        float b = bd1[i];
        for (int k = 0; k < HID; k++) {
            b += Wd1[i * 2 * HID + k] * blin_s[k];
            b += Wd1[i * 2 * HID + HID + k] * blin_t[k];
        }
        bdc[i] = b;
    }
}

// ---------------- decoder: out[l] = relu(u_s[ls]+u_t[ld]+bdc) . Wd2 + bd2 ----------------
__global__ void decode_kernel(const float4* __restrict__ us, const float4* __restrict__ ut,
                              const int* __restrict__ ls, const int* __restrict__ ld,
                              const float4* __restrict__ bdc, const float4* __restrict__ wd2,
                              const float* __restrict__ bd2,
                              float* __restrict__ out, int EL) {
    int g = blockIdx.x * blockDim.x + threadIdx.x;
    int w = g >> 5, lane = g & 31;
    if (w >= EL) return;
    const float4* a = us + (long long)__ldg(ls + w) * (HID / 4);
    const float4* b = ut + (long long)__ldg(ld + w) * (HID / 4);
    float sum = 0.f;
#pragma unroll
    for (int c = lane; c < HID / 4; c += 32) {
        float4 va = a[c], vb = b[c], vc = bdc[c], vw = wd2[c];
        sum += fmaxf(va.x + vb.x + vc.x, 0.f) * vw.x
             + fmaxf(va.y + vb.y + vc.y, 0.f) * vw.y
             + fmaxf(va.z + vb.z + vc.z, 0.f) * vw.z
             + fmaxf(va.w + vb.w + vc.w, 0.f) * vw.w;
    }
#pragma unroll
    for (int o = 16; o; o >>= 1) sum += __shfl_xor_sync(0xffffffffu, sum, o);
    if (lane == 0) out[w] = sum + bd2[0];
}

// ---------------- launcher ----------------
extern "C" void kernel_launch(void* const* d_in, const int* in_sizes, int n_in,
                              void* d_out, int out_size) {
    const float* x_sotu  = (const float*)d_in[0];
    const float* x_taxon = (const float*)d_in[1];
    const int*   esrc    = (const int*)d_in[2];
    const int*   edst    = (const int*)d_in[3];
    const int*   lsrc    = (const int*)d_in[4];
    const int*   ldst    = (const int*)d_in[5];
    const float* Wl1_st  = (const float*)d_in[6];
    const float* bl1_st  = (const float*)d_in[7];
    const float* Wr1_st  = (const float*)d_in[8];
    const float* Wl1_ts  = (const float*)d_in[9];
    const float* bl1_ts  = (const float*)d_in[10];
    const float* Wr1_ts  = (const float*)d_in[11];
    const float* Wl2_st  = (const float*)d_in[12];
    const float* bl2_st  = (const float*)d_in[13];
    const float* Wr2_st  = (const float*)d_in[14];
    const float* Wl2_ts  = (const float*)d_in[15];
    const float* bl2_ts  = (const float*)d_in[16];
    const float* Wr2_ts  = (const float*)d_in[17];
    const float* Wlin_s  = (const float*)d_in[18];
    const float* blin_s  = (const float*)d_in[19];
    const float* Wlin_t  = (const float*)d_in[20];
    const float* blin_t  = (const float*)d_in[21];
    const float* Wd1     = (const float*)d_in[22];
    const float* bd1     = (const float*)d_in[23];
    const float* Wd2     = (const float*)d_in[24];
    const float* bd2     = (const float*)d_in[25];
    float* out = (float*)d_out;

    float *scratch, *h1t, *h1s, *h2t, *h2s, *us, *ut, *Wcs, *Wct, *bdc;
    cudaGetSymbolAddress((void**)&scratch, g_scratch);
    cudaGetSymbolAddress((void**)&h1t, g_h1t);
    cudaGetSymbolAddress((void**)&h1s, g_h1s);
    cudaGetSymbolAddress((void**)&h2t, g_h2t);
    cudaGetSymbolAddress((void**)&h2s, g_h2s);
    cudaGetSymbolAddress((void**)&us,  g_us);
    cudaGetSymbolAddress((void**)&ut,  g_ut);
    cudaGetSymbolAddress((void**)&Wcs, g_Wcs);
    cudaGetSymbolAddress((void**)&Wct, g_Wct);
    cudaGetSymbolAddress((void**)&bdc, g_bdc);

    float* aggT = scratch;
    float* aggS = scratch + (size_t)N_TAXON * HID;
    float* cntT = aggS + (size_t)N_SOTU * HID;
    float* cntS = cntT + N_TAXON;

    const long long ZALL = (long long)N_TAXON * HID + (long long)N_SOTU * HID + N_TAXON + N_SOTU;
    const long long ZAGG = (long long)N_TAXON * HID + (long long)N_SOTU * HID;

    dim3 gT(HID / BN, (N_TAXON + BM - 1) / BM);
    dim3 gS(HID / BN, (N_SOTU + BM - 1) / BM);

    // ---- layer 1 ----
    zero_kernel<<<(unsigned)((ZALL / 4 + 255) / 256), 256>>>((float4*)scratch, ZALL / 4);
    count_kernel<<<(NE + 255) / 256, 256>>>(esrc, edst, cntS, cntT, NE);

    long long totT = (long long)NE * (HID / 4);   // aggT += x_sotu[src] (256 wide)
    scatter_kernel<<<(unsigned)((totT + 255) / 256), 256>>>(
        (const float4*)x_sotu, esrc, edst, (float4*)aggT, HID / 4, totT);
    long long totS1 = (long long)NE * (DT / 4);   // aggS += x_taxon[dst] (128 wide)
    scatter_kernel<<<(unsigned)((totS1 + 255) / 256), 256>>>(
        (const float4*)x_taxon, edst, esrc, (float4*)aggS, DT / 4, totS1);

    inv_kernel<<<(N_TAXON + N_SOTU + 255) / 256, 256>>>(cntT, N_TAXON + N_SOTU);

    gemm_fused<<<gT, 256>>>(aggT, DS, cntT, x_taxon, DT, Wl1_st, Wr1_st, bl1_st,
                            h1t, N_TAXON, HID, 1);
    gemm_fused<<<gS, 256>>>(aggS, DT, cntS, x_sotu, DS, Wl1_ts, Wr1_ts, bl1_ts,
                            h1s, N_SOTU, HID, 1);

    // ---- layer 2 ----
    zero_kernel<<<(unsigned)((ZAGG / 4 + 255) / 256), 256>>>((float4*)scratch, ZAGG / 4);
    scatter_kernel<<<(unsigned)((totT + 255) / 256), 256>>>(
        (const float4*)h1s, esrc, edst, (float4*)aggT, HID / 4, totT);
    long long totS2 = (long long)NE * (HID / 4);
    scatter_kernel<<<(unsigned)((totS2 + 255) / 256), 256>>>(
        (const float4*)h1t, edst, esrc, (float4*)aggS, HID / 4, totS2);

    gemm_fused<<<gT, 256>>>(aggT, HID, cntT, h1t, HID, Wl2_st, Wr2_st, bl2_st,
                            h2t, N_TAXON, HID, 1);
    gemm_fused<<<gS, 256>>>(aggS, HID, cntS, h1s, HID, Wl2_ts, Wr2_ts, bl2_ts,
                            h2s, N_SOTU, HID, 1);

    // ---- composed output projection + decoder halves ----
    compose_kernel<<<HID, HID>>>(Wd1, Wlin_s, Wlin_t, blin_s, blin_t, bd1, Wcs, Wct, bdc);

    gemm_fused<<<gS, 256>>>(h2s, HID, nullptr, nullptr, 0, Wcs, nullptr, nullptr,
                            us, N_SOTU, HID, 0);
    gemm_fused<<<gT, 256>>>(h2t, HID, nullptr, nullptr, 0, Wct, nullptr, nullptr,
                            ut, N_TAXON, HID, 0);

    // ---- decoder ----
    decode_kernel<<<(NEL * 32 + 255) / 256, 256>>>(
        (const float4*)us, (const float4*)ut, lsrc, ldst,
        (const float4*)bdc, (const float4*)Wd2, bd2, out, NEL);
}

// round 3
// speedup vs baseline: 1.5670x; 1.5670x over previous
#include <cuda_runtime.h>
#include <cuda_bf16.h>
#include <cstdint>

#define N_SOTU  100000
#define N_TAXON 20000
#define NE      800000
#define NEL     200000
#define DS      256
#define DT      128
#define HID     256

// ---------------- scratch (device globals; no allocation) ----------------
__device__ float g_scratch[(size_t)N_TAXON*HID + (size_t)N_SOTU*HID + N_TAXON + N_SOTU];
__device__ float g_h1t[(size_t)N_TAXON*HID];
__device__ float g_h1s[(size_t)N_SOTU*HID];
__device__ float g_h2t[(size_t)N_TAXON*HID];
__device__ float g_h2s[(size_t)N_SOTU*HID];
__device__ float g_us[(size_t)N_SOTU*HID];
__device__ float g_ut[(size_t)N_TAXON*HID];
__device__ float g_Wcs[HID*HID];
__device__ float g_Wct[HID*HID];
__device__ float g_bdc[HID];

__device__ __forceinline__ uint32_t f2tf32(float x) {
    uint32_t r; asm("cvt.rna.tf32.f32 %0, %1;" : "=r"(r) : "f"(x)); return r;
}

// ---------------- utility kernels ----------------
__global__ void zero_kernel(float4* p, long long n4) {
    long long i = blockIdx.x * (long long)blockDim.x + threadIdx.x;
    if (i < n4) p[i] = make_float4(0.f, 0.f, 0.f, 0.f);
}

__global__ void count_kernel(const int* __restrict__ src, const int* __restrict__ dst,
                             float* cntS, float* cntT, int E) {
    int e = blockIdx.x * blockDim.x + threadIdx.x;
    if (e < E) {
        atomicAdd(cntS + src[e], 1.f);
        atomicAdd(cntT + dst[e], 1.f);
    }
}

__global__ void inv_kernel(float* p, int n) {
    int i = blockIdx.x * blockDim.x + threadIdx.x;
    if (i < n) p[i] = 1.f / fmaxf(p[i], 1.f);
}

__global__ void scatter_kernel(const float4* __restrict__ feat,
                               const int* __restrict__ from_i,
                               const int* __restrict__ to_i,
                               float4* __restrict__ agg,
                               int D4, long long total) {
    long long gid = blockIdx.x * (long long)blockDim.x + threadIdx.x;
    if (gid >= total) return;
    int e = (int)(gid / D4);
    int c = (int)(gid % D4);
    int f = __ldg(from_i + e);
    int t = __ldg(to_i + e);
    float4 v = feat[(long long)f * D4 + c];
    atomicAdd(&agg[(long long)t * D4 + c], v);
}

// ---------------- tf32 HMMA fused concat-K GEMM ----------------
// C[n][h] = act( sum_{k<K1} A1[n][k]*scale[n]*W1[h][k] + sum_{k<K2} A2[n][k]*W2[h][k] + bias[h] )
// Block 128x256 (BN == HID), BK=16, 8 warps (2m x 4n), warp tile 64x64, m16n8k8 tf32.
#define BM 128
#define BN 256
#define BKT 16
#define SA 137      // padded smem stride for A (k-major [16][SA])
#define SB 265      // padded smem stride for B (k-major [16][SB])
#define GEMM_SMEM ((2*BKT*SA + 2*BKT*SB) * 4)

__device__ __forceinline__ void mma_tf32(float* d, const uint32_t* a, const uint32_t* b) {
    asm volatile(
        "mma.sync.aligned.m16n8k8.row.col.f32.tf32.tf32.f32 "
        "{%0,%1,%2,%3}, {%4,%5,%6,%7}, {%8,%9}, {%0,%1,%2,%3};"
        : "+f"(d[0]), "+f"(d[1]), "+f"(d[2]), "+f"(d[3])
        : "r"(a[0]), "r"(a[1]), "r"(a[2]), "r"(a[3]), "r"(b[0]), "r"(b[1]));
}

__global__ void __launch_bounds__(256, 1)
gemm_mma(const float* __restrict__ A1, int K1, const float* __restrict__ scale,
         const float* __restrict__ A2, int K2,
         const float* __restrict__ W1, const float* __restrict__ W2,
         const float* __restrict__ bias,
         float* __restrict__ C, int Nrows, int doRelu) {
    extern __shared__ uint32_t smem[];
    uint32_t* AsBase = smem;                 // [2][BKT][SA]
    uint32_t* BsBase = smem + 2 * BKT * SA;  // [2][BKT][SB]

    const int tid = threadIdx.x;
    const int wid = tid >> 5, lane = tid & 31;
    const int warpM = wid >> 2, warpN = wid & 3;   // 2 x 4
    const int bm = blockIdx.x * BM;
    const int K = K1 + K2;
    const int nch = K / BKT;

    float acc[4][8][4];
#pragma unroll
    for (int i = 0; i < 4; i++)
#pragma unroll
        for (int j = 0; j < 8; j++)
#pragma unroll
            for (int q = 0; q < 4; q++) acc[i][j][q] = 0.f;

    float4 ra[2];
    float4 rb[4];

    auto load_g = [&](int c) {
        const int k0 = c * BKT;
        const bool inA1 = (k0 < K1);
#pragma unroll
        for (int i = 0; i < 2; i++) {
            int idx = tid + i * 256;
            int row = idx >> 2, k4 = (idx & 3) * 4;
            int grow = bm + row;
            float4 v = make_float4(0.f, 0.f, 0.f, 0.f);
            float s = 1.f;
            if (grow < Nrows) {
                if (inA1) {
                    v = *(const float4*)(A1 + (size_t)grow * K1 + k0 + k4);
                    if (scale) s = __ldg(scale + grow);
                } else {
                    v = *(const float4*)(A2 + (size_t)grow * K2 + (k0 - K1) + k4);
                }
            }
            ra[i] = make_float4(v.x * s, v.y * s, v.z * s, v.w * s);
        }
#pragma unroll
        for (int i = 0; i < 4; i++) {
            int idx = tid + i * 256;
            int row = idx >> 2, k4 = (idx & 3) * 4;
            const float* wp = inA1 ? (W1 + (size_t)row * K1 + k0 + k4)
                                   : (W2 + (size_t)row * K2 + (k0 - K1) + k4);
            rb[i] = *(const float4*)wp;
        }
    };

    auto store_s = [&](int b) {
        uint32_t* Ab = AsBase + b * BKT * SA;
#pragma unroll
        for (int i = 0; i < 2; i++) {
            int idx = tid + i * 256;
            int row = idx >> 2, k4 = (idx & 3) * 4;
            Ab[(k4 + 0) * SA + row] = f2tf32(ra[i].x);
            Ab[(k4 + 1) * SA + row] = f2tf32(ra[i].y);
            Ab[(k4 + 2) * SA + row] = f2tf32(ra[i].z);
            Ab[(k4 + 3) * SA + row] = f2tf32(ra[i].w);
        }
        uint32_t* Bb = BsBase + b * BKT * SB;
#pragma unroll
        for (int i = 0; i < 4; i++) {
            int idx = tid + i * 256;
            int row = idx >> 2, k4 = (idx & 3) * 4;
            Bb[(k4 + 0) * SB + row] = f2tf32(rb[i].x);
            Bb[(k4 + 1) * SB + row] = f2tf32(rb[i].y);
            Bb[(k4 + 2) * SB + row] = f2tf32(rb[i].z);
            Bb[(k4 + 3) * SB + row] = f2tf32(rb[i].w);
        }
    };

    load_g(0);
    store_s(0);
    __syncthreads();

    const int lrow = lane >> 2;     // 0..7
    const int lcol = lane & 3;      // 0..3

    for (int c = 0; c < nch; c++) {
        const int b = c & 1;
        if (c + 1 < nch) load_g(c + 1);

        const uint32_t* Ab = AsBase + b * BKT * SA;
        const uint32_t* Bb = BsBase + b * BKT * SB;
#pragma unroll
        for (int g = 0; g < 2; g++) {
            uint32_t af[4][4];
            const int s0 = g * 8 + lcol;
#pragma unroll
            for (int mt = 0; mt < 4; mt++) {
                const int row = warpM * 64 + mt * 16 + lrow;
                af[mt][0] = Ab[s0 * SA + row];
                af[mt][1] = Ab[s0 * SA + row + 8];
                af[mt][2] = Ab[(s0 + 4) * SA + row];
                af[mt][3] = Ab[(s0 + 4) * SA + row + 8];
            }
            uint32_t bf[8][2];
#pragma unroll
            for (int nt = 0; nt < 8; nt++) {
                const int col = warpN * 64 + nt * 8 + lrow;
                bf[nt][0] = Bb[s0 * SB + col];
                bf[nt][1] = Bb[(s0 + 4) * SB + col];
            }
#pragma unroll
            for (int mt = 0; mt < 4; mt++)
#pragma unroll
                for (int nt = 0; nt < 8; nt++)
                    mma_tf32(acc[mt][nt], af[mt], bf[nt]);
        }
        __syncthreads();
        if (c + 1 < nch) {
            store_s(b ^ 1);
            __syncthreads();
        }
    }

    // ---- epilogue ----
#pragma unroll
    for (int mt = 0; mt < 4; mt++) {
        const int r0 = bm + warpM * 64 + mt * 16 + lrow;
#pragma unroll
        for (int half = 0; half < 2; half++) {
            const int row = r0 + half * 8;
            if (row >= Nrows) continue;
#pragma unroll
            for (int nt = 0; nt < 8; nt++) {
                const int col = warpN * 64 + nt * 8 + 2 * lcol;
                float2 v;
                v.x = acc[mt][nt][half * 2 + 0];
                v.y = acc[mt][nt][half * 2 + 1];
                if (bias) {
                    v.x += __ldg(bias + col + 0);
                    v.y += __ldg(bias + col + 1);
                }
                if (doRelu) {
                    v.x = fmaxf(v.x, 0.f);
                    v.y = fmaxf(v.y, 0.f);
                }
                *(float2*)(C + (size_t)row * BN + col) = v;
            }
        }
    }
}

// ---------------- weight composition ----------------
__global__ void compose_kernel(const float* __restrict__ Wd1,
                               const float* __restrict__ Wlin_s,
                               const float* __restrict__ Wlin_t,
                               const float* __restrict__ blin_s,
                               const float* __restrict__ blin_t,
                               const float* __restrict__ bd1,
                               float* Wcs, float* Wct, float* bdc) {
    int i = blockIdx.x;
    int m = threadIdx.x;
    float ss = 0.f, st = 0.f;
    for (int k = 0; k < HID; k++) {
        float wl = Wd1[i * 2 * HID + k];
        float wr = Wd1[i * 2 * HID + HID + k];
        ss += wl * Wlin_s[k * HID + m];
        st += wr * Wlin_t[k * HID + m];
    }
    Wcs[i * HID + m] = ss;
    Wct[i * HID + m] = st;
    if (m == 0) {
        float b = bd1[i];
        for (int k = 0; k < HID; k++) {
            b += Wd1[i * 2 * HID + k] * blin_s[k];
            b += Wd1[i * 2 * HID + HID + k] * blin_t[k];
        }
        bdc[i] = b;
    }
}

// ---------------- decoder ----------------
__global__ void decode_kernel(const float4* __restrict__ us, const float4* __restrict__ ut,
                              const int* __restrict__ ls, const int* __restrict__ ld,
                              const float4* __restrict__ bdc, const float4* __restrict__ wd2,
                              const float* __restrict__ bd2,
                              float* __restrict__ out, int EL) {
    int g = blockIdx.x * blockDim.x + threadIdx.x;
    int w = g >> 5, lane = g & 31;
    if (w >= EL) return;
    const float4* a = us + (long long)__ldg(ls + w) * (HID / 4);
    const float4* b = ut + (long long)__ldg(ld + w) * (HID / 4);
    float sum = 0.f;
#pragma unroll
    for (int c = lane; c < HID / 4; c += 32) {
        float4 va = a[c], vb = b[c], vc = bdc[c], vw = wd2[c];
        sum += fmaxf(va.x + vb.x + vc.x, 0.f) * vw.x
             + fmaxf(va.y + vb.y + vc.y, 0.f) * vw.y
             + fmaxf(va.z + vb.z + vc.z, 0.f) * vw.z
             + fmaxf(va.w + vb.w + vc.w, 0.f) * vw.w;
    }
#pragma unroll
    for (int o = 16; o; o >>= 1) sum += __shfl_xor_sync(0xffffffffu, sum, o);
    if (lane == 0) out[w] = sum + bd2[0];
}

// ---------------- launcher ----------------
extern "C" void kernel_launch(void* const* d_in, const int* in_sizes, int n_in,
                              void* d_out, int out_size) {
    const float* x_sotu  = (const float*)d_in[0];
    const float* x_taxon = (const float*)d_in[1];
    const int*   esrc    = (const int*)d_in[2];
    const int*   edst    = (const int*)d_in[3];
    const int*   lsrc    = (const int*)d_in[4];
    const int*   ldst    = (const int*)d_in[5];
    const float* Wl1_st  = (const float*)d_in[6];
    const float* bl1_st  = (const float*)d_in[7];
    const float* Wr1_st  = (const float*)d_in[8];
    const float* Wl1_ts  = (const float*)d_in[9];
    const float* bl1_ts  = (const float*)d_in[10];
    const float* Wr1_ts  = (const float*)d_in[11];
    const float* Wl2_st  = (const float*)d_in[12];
    const float* bl2_st  = (const float*)d_in[13];
    const float* Wr2_st  = (const float*)d_in[14];
    const float* Wl2_ts  = (const float*)d_in[15];
    const float* bl2_ts  = (const float*)d_in[16];
    const float* Wr2_ts  = (const float*)d_in[17];
    const float* Wlin_s  = (const float*)d_in[18];
    const float* blin_s  = (const float*)d_in[19];
    const float* Wlin_t  = (const float*)d_in[20];
    const float* blin_t  = (const float*)d_in[21];
    const float* Wd1     = (const float*)d_in[22];
    const float* bd1     = (const float*)d_in[23];
    const float* Wd2     = (const float*)d_in[24];
    const float* bd2     = (const float*)d_in[25];
    float* out = (float*)d_out;

    float *scratch, *h1t, *h1s, *h2t, *h2s, *us, *ut, *Wcs, *Wct, *bdc;
    cudaGetSymbolAddress((void**)&scratch, g_scratch);
    cudaGetSymbolAddress((void**)&h1t, g_h1t);
    cudaGetSymbolAddress((void**)&h1s, g_h1s);
    cudaGetSymbolAddress((void**)&h2t, g_h2t);
    cudaGetSymbolAddress((void**)&h2s, g_h2s);
    cudaGetSymbolAddress((void**)&us,  g_us);
    cudaGetSymbolAddress((void**)&ut,  g_ut);
    cudaGetSymbolAddress((void**)&Wcs, g_Wcs);
    cudaGetSymbolAddress((void**)&Wct, g_Wct);
    cudaGetSymbolAddress((void**)&bdc, g_bdc);

    static int smem_set = 0;
    if (!smem_set) {
        cudaFuncSetAttribute(gemm_mma, cudaFuncAttributeMaxDynamicSharedMemorySize, GEMM_SMEM);
        smem_set = 1;
    }

    float* aggT = scratch;
    float* aggS = scratch + (size_t)N_TAXON * HID;
    float* cntT = aggS + (size_t)N_SOTU * HID;
    float* cntS = cntT + N_TAXON;

    const long long ZALL = (long long)N_TAXON * HID + (long long)N_SOTU * HID + N_TAXON + N_SOTU;
    const long long ZAGG = (long long)N_TAXON * HID + (long long)N_SOTU * HID;

    const unsigned gT = (N_TAXON + BM - 1) / BM;   // 157
    const unsigned gS = (N_SOTU + BM - 1) / BM;    // 782

    // ---- layer 1 ----
    zero_kernel<<<(unsigned)((ZALL / 4 + 255) / 256), 256>>>((float4*)scratch, ZALL / 4);
    count_kernel<<<(NE + 255) / 256, 256>>>(esrc, edst, cntS, cntT, NE);

    long long totT = (long long)NE * (HID / 4);
    scatter_kernel<<<(unsigned)((totT + 255) / 256), 256>>>(
        (const float4*)x_sotu, esrc, edst, (float4*)aggT, HID / 4, totT);
    long long totS1 = (long long)NE * (DT / 4);
    scatter_kernel<<<(unsigned)((totS1 + 255) / 256), 256>>>(
        (const float4*)x_taxon, edst, esrc, (float4*)aggS, DT / 4, totS1);

    inv_kernel<<<(N_TAXON + N_SOTU + 255) / 256, 256>>>(cntT, N_TAXON + N_SOTU);

    gemm_mma<<<gT, 256, GEMM_SMEM>>>(aggT, DS, cntT, x_taxon, DT, Wl1_st, Wr1_st, bl1_st,
                                     h1t, N_TAXON, 1);
    gemm_mma<<<gS, 256, GEMM_SMEM>>>(aggS, DT, cntS, x_sotu, DS, Wl1_ts, Wr1_ts, bl1_ts,
                                     h1s, N_SOTU, 1);

    // ---- layer 2 ----
    zero_kernel<<<(unsigned)((ZAGG / 4 + 255) / 256), 256>>>((float4*)scratch, ZAGG / 4);
    scatter_kernel<<<(unsigned)((totT + 255) / 256), 256>>>(
        (const float4*)h1s, esrc, edst, (float4*)aggT, HID / 4, totT);
    long long totS2 = (long long)NE * (HID / 4);
    scatter_kernel<<<(unsigned)((totS2 + 255) / 256), 256>>>(
        (const float4*)h1t, edst, esrc, (float4*)aggS, HID / 4, totS2);

    gemm_mma<<<gT, 256, GEMM_SMEM>>>(aggT, HID, cntT, h1t, HID, Wl2_st, Wr2_st, bl2_st,
                                     h2t, N_TAXON, 1);
    gemm_mma<<<gS, 256, GEMM_SMEM>>>(aggS, HID, cntS, h1s, HID, Wl2_ts, Wr2_ts, bl2_ts,
                                     h2s, N_SOTU, 1);

    // ---- composed projection + decoder halves ----
    compose_kernel<<<HID, HID>>>(Wd1, Wlin_s, Wlin_t, blin_s, blin_t, bd1, Wcs, Wct, bdc);

    gemm_mma<<<gS, 256, GEMM_SMEM>>>(h2s, HID, nullptr, nullptr, 0, Wcs, nullptr, nullptr,
                                     us, N_SOTU, 0);
    gemm_mma<<<gT, 256, GEMM_SMEM>>>(h2t, HID, nullptr, nullptr, 0, Wct, nullptr, nullptr,
                                     ut, N_TAXON, 0);

    // ---- decoder ----
    decode_kernel<<<(NEL * 32 + 255) / 256, 256>>>(
        (const float4*)us, (const float4*)ut, lsrc, ldst,
        (const float4*)bdc, (const float4*)Wd2, bd2, out, NEL);
}

// round 4
// speedup vs baseline: 2.0217x; 1.2902x over previous
#include <cuda_runtime.h>
#include <cuda_bf16.h>
#include <cstdint>

#define N_SOTU  100000
#define N_TAXON 20000
#define NE      800000
#define NEL     200000
#define DS      256
#define DT      128
#define HID     256

// ---------------- scratch (device globals; no allocation) ----------------
__device__ __align__(128) float g_scratch[(size_t)N_TAXON*HID + (size_t)N_SOTU*HID + N_TAXON + N_SOTU];
__device__ __align__(128) float g_h1t[(size_t)N_TAXON*HID];
__device__ __align__(128) float g_h1s[(size_t)N_SOTU*HID];
__device__ __align__(128) float g_h2t[(size_t)N_TAXON*HID];
__device__ __align__(128) float g_h2s[(size_t)N_SOTU*HID];
__device__ __align__(128) float g_us[(size_t)N_SOTU*HID];
__device__ __align__(128) float g_ut[(size_t)N_TAXON*HID];
__device__ __align__(128) float g_xr_s[(size_t)N_SOTU*DS];
__device__ __align__(128) float g_xr_t[(size_t)N_TAXON*DT];
__device__ __align__(128) float g_wt1_st[384*256];
__device__ __align__(128) float g_wt1_ts[384*256];
__device__ __align__(128) float g_wt2_st[512*256];
__device__ __align__(128) float g_wt2_ts[512*256];
__device__ __align__(128) float g_wcsT[256*256];
__device__ __align__(128) float g_wctT[256*256];
__device__ __align__(128) float g_bdc[256];

__device__ __forceinline__ float rndf(float x) {
    uint32_t r; asm("cvt.rna.tf32.f32 %0, %1;" : "=r"(r) : "f"(x));
    return __uint_as_float(r);
}

// ---------------- utility kernels ----------------
__global__ void zero_kernel(float4* p, long long n4) {
    long long i = blockIdx.x * (long long)blockDim.x + threadIdx.x;
    if (i < n4) p[i] = make_float4(0.f, 0.f, 0.f, 0.f);
}

__global__ void count_kernel(const int* __restrict__ src, const int* __restrict__ dst,
                             float* cntS, float* cntT, int E) {
    int e = blockIdx.x * blockDim.x + threadIdx.x;
    if (e < E) {
        atomicAdd(cntS + src[e], 1.f);
        atomicAdd(cntT + dst[e], 1.f);
    }
}

__global__ void inv_kernel(float* p, int n) {
    int i = blockIdx.x * blockDim.x + threadIdx.x;
    if (i < n) p[i] = 1.f / fmaxf(p[i], 1.f);
}

__global__ void scatter_kernel(const float4* __restrict__ feat,
                               const int* __restrict__ from_i,
                               const int* __restrict__ to_i,
                               float4* __restrict__ agg,
                               int D4, long long total) {
    long long gid = blockIdx.x * (long long)blockDim.x + threadIdx.x;
    if (gid >= total) return;
    int e = (int)(gid / D4);
    int c = (int)(gid % D4);
    int f = __ldg(from_i + e);
    int t = __ldg(to_i + e);
    float4 v = feat[(long long)f * D4 + c];
    atomicAdd(&agg[(long long)t * D4 + c], v);
}

// agg[row] = rnd(agg[row] * inv[row])
__global__ void scale_round_kernel(float4* agg, const float* __restrict__ inv,
                                   long long total4, int D4) {
    long long i = blockIdx.x * (long long)blockDim.x + threadIdx.x;
    if (i >= total4) return;
    int row = (int)(i / D4);
    float s = __ldg(inv + row);
    float4 v = agg[i];
    v.x = rndf(v.x * s); v.y = rndf(v.y * s);
    v.z = rndf(v.z * s); v.w = rndf(v.w * s);
    agg[i] = v;
}

__global__ void round_copy_kernel(const float4* __restrict__ in, float4* out, long long n4) {
    long long i = blockIdx.x * (long long)blockDim.x + threadIdx.x;
    if (i >= n4) return;
    float4 v = in[i];
    v.x = rndf(v.x); v.y = rndf(v.y); v.z = rndf(v.z); v.w = rndf(v.w);
    out[i] = v;
}

// WT[k][h] = rnd(concat(W1,W2)[h][k]); grid = Ktot blocks of 256 (k=block, h=thread)
__global__ void wt_kernel(const float* __restrict__ W1, int K1,
                          const float* __restrict__ W2, int K2,
                          float* __restrict__ WT) {
    int k = blockIdx.x, h = threadIdx.x;
    float v = (k < K1) ? W1[h * K1 + k] : W2[h * K2 + (k - K1)];
    WT[k * 256 + h] = rndf(v);
}

// ---------------- tf32 HMMA GEMM, 4-stage cp.async pipeline ----------------
// C[n][h] = act( A[n][:] @ WT[:][h] + bias[h] ), A = concat(A1,A2) row-major (pre-rounded),
// WT k-major [K][256] (pre-rounded). Block 128x256, BK=16, 8 warps 2x4, m16n8k8.
#define AS_STRIDE 20
#define BS_STRIDE 264
#define A_STAGE (128*AS_STRIDE)
#define B_STAGE (16*BS_STRIDE)
#define STAGE_FLOATS (A_STAGE + B_STAGE)
#define GEMM_SMEM (4*STAGE_FLOATS*4)

__device__ __forceinline__ void mma_tf32(float* d, const uint32_t* a, const uint32_t* b) {
    asm volatile(
        "mma.sync.aligned.m16n8k8.row.col.f32.tf32.tf32.f32 "
        "{%0,%1,%2,%3}, {%4,%5,%6,%7}, {%8,%9}, {%0,%1,%2,%3};"
        : "+f"(d[0]), "+f"(d[1]), "+f"(d[2]), "+f"(d[3])
        : "r"(a[0]), "r"(a[1]), "r"(a[2]), "r"(a[3]), "r"(b[0]), "r"(b[1]));
}

__global__ void __launch_bounds__(256)
gemm_pipe(const float* __restrict__ A1, int K1,
          const float* __restrict__ A2, int K2,
          const float* __restrict__ WT,
          const float* __restrict__ bias,
          float* __restrict__ C, int Nrows, int flags) {  // flags: 1=relu, 2=round
    extern __shared__ float sm[];
    const int tid = threadIdx.x;
    const int wid = tid >> 5, lane = tid & 31;
    const int warpM = wid >> 2, warpN = wid & 3;
    const int lrow = lane >> 2, lcol = lane & 3;
    const int bm = blockIdx.x * 128;
    const int nch = (K1 + K2) >> 4;

    uint32_t sbase = (uint32_t)__cvta_generic_to_shared(sm);

    float2 bv[8];
#pragma unroll
    for (int nt = 0; nt < 8; nt++) {
        int col = warpN * 64 + nt * 8 + 2 * lcol;
        if (bias) { bv[nt].x = __ldg(bias + col); bv[nt].y = __ldg(bias + col + 1); }
        else      { bv[nt].x = 0.f; bv[nt].y = 0.f; }
    }

    float acc[4][8][4];
#pragma unroll
    for (int i = 0; i < 4; i++)
#pragma unroll
        for (int j = 0; j < 8; j++)
#pragma unroll
            for (int q = 0; q < 4; q++) acc[i][j][q] = 0.f;

    const int arow = tid >> 2;
    const int aseg = (tid & 3) * 4;

    auto issue = [&](int c) {
        int slot = c & 3;
        uint32_t aoff = sbase + slot * STAGE_FLOATS * 4;
        uint32_t boff = aoff + A_STAGE * 4;
        int k0 = c << 4;
        bool inA1 = (k0 < K1);
#pragma unroll
        for (int i = 0; i < 2; i++) {
            int row = arow + i * 64;
            int grow = bm + row;
            bool ok = grow < Nrows;
            int gr = ok ? grow : 0;
            const float* src = inA1 ? A1 + (size_t)gr * K1 + k0 + aseg
                                    : A2 + (size_t)gr * K2 + (k0 - K1) + aseg;
            uint32_t dst = aoff + (uint32_t)(row * AS_STRIDE + aseg) * 4;
            int sz = ok ? 16 : 0;
            asm volatile("cp.async.cg.shared.global [%0], [%1], 16, %2;"
                         :: "r"(dst), "l"(src), "r"(sz));
        }
#pragma unroll
        for (int i = 0; i < 4; i++) {
            int idx = tid + i * 256;
            int kr = idx >> 6, seg = (idx & 63) * 4;
            const float* src = WT + (size_t)(k0 + kr) * 256 + seg;
            uint32_t dst = boff + (uint32_t)(kr * BS_STRIDE + seg) * 4;
            asm volatile("cp.async.cg.shared.global [%0], [%1], 16;"
                         :: "r"(dst), "l"(src));
        }
        asm volatile("cp.async.commit_group;");
    };

    issue(0); issue(1); issue(2);

    for (int c = 0; c < nch; c++) {
        asm volatile("cp.async.wait_group 2;");
        __syncthreads();
        if (c + 3 < nch) issue(c + 3);
        else asm volatile("cp.async.commit_group;");

        int slot = c & 3;
        const uint32_t* As = (const uint32_t*)(sm + slot * STAGE_FLOATS);
        const uint32_t* Bs = (const uint32_t*)(sm + slot * STAGE_FLOATS + A_STAGE);
#pragma unroll
        for (int kg = 0; kg < 2; kg++) {
            const int s0 = kg * 8 + lcol;
            uint32_t af[4][4];
#pragma unroll
            for (int mt = 0; mt < 4; mt++) {
                const int row = warpM * 64 + mt * 16 + lrow;
                af[mt][0] = As[row * AS_STRIDE + s0];
                af[mt][1] = As[(row + 8) * AS_STRIDE + s0];
                af[mt][2] = As[row * AS_STRIDE + s0 + 4];
                af[mt][3] = As[(row + 8) * AS_STRIDE + s0 + 4];
            }
            uint32_t bf[8][2];
#pragma unroll
            for (int nt = 0; nt < 8; nt++) {
                const int col = warpN * 64 + nt * 8 + lrow;
                bf[nt][0] = Bs[s0 * BS_STRIDE + col];
                bf[nt][1] = Bs[(s0 + 4) * BS_STRIDE + col];
            }
#pragma unroll
            for (int mt = 0; mt < 4; mt++)
#pragma unroll
                for (int nt = 0; nt < 8; nt++)
                    mma_tf32(acc[mt][nt], af[mt], bf[nt]);
        }
    }

    const bool doRelu = flags & 1;
    const bool doRnd  = flags & 2;
#pragma unroll
    for (int mt = 0; mt < 4; mt++) {
        const int r0 = bm + warpM * 64 + mt * 16 + lrow;
#pragma unroll
        for (int half = 0; half < 2; half++) {
            const int row = r0 + half * 8;
            if (row >= Nrows) continue;
#pragma unroll
            for (int nt = 0; nt < 8; nt++) {
                const int col = warpN * 64 + nt * 8 + 2 * lcol;
                float2 v;
                v.x = acc[mt][nt][half * 2 + 0] + bv[nt].x;
                v.y = acc[mt][nt][half * 2 + 1] + bv[nt].y;
                if (doRelu) { v.x = fmaxf(v.x, 0.f); v.y = fmaxf(v.y, 0.f); }
                if (doRnd)  { v.x = rndf(v.x); v.y = rndf(v.y); }
                *(float2*)(C + (size_t)row * 256 + col) = v;
            }
        }
    }
}

// ---------------- weight composition (transposed, rounded) ----------------
__global__ void compose_kernel(const float* __restrict__ Wd1,
                               const float* __restrict__ Wlin_s,
                               const float* __restrict__ Wlin_t,
                               const float* __restrict__ blin_s,
                               const float* __restrict__ blin_t,
                               const float* __restrict__ bd1,
                               float* WcsT, float* WctT, float* bdc) {
    int i = blockIdx.x;      // decoder row
    int m = threadIdx.x;     // input col
    float ss = 0.f, st = 0.f;
    for (int k = 0; k < HID; k++) {
        float wl = Wd1[i * 2 * HID + k];
        float wr = Wd1[i * 2 * HID + HID + k];
        ss += wl * Wlin_s[k * HID + m];
        st += wr * Wlin_t[k * HID + m];
    }
    WcsT[m * HID + i] = rndf(ss);
    WctT[m * HID + i] = rndf(st);
    if (m == 0) {
        float b = bd1[i];
        for (int k = 0; k < HID; k++) {
            b += Wd1[i * 2 * HID + k] * blin_s[k];
            b += Wd1[i * 2 * HID + HID + k] * blin_t[k];
        }
        bdc[i] = b;
    }
}

// ---------------- decoder ----------------
__global__ void decode_kernel(const float4* __restrict__ us, const float4* __restrict__ ut,
                              const int* __restrict__ ls, const int* __restrict__ ld,
                              const float4* __restrict__ bdc, const float4* __restrict__ wd2,
                              const float* __restrict__ bd2,
                              float* __restrict__ out, int EL) {
    int g = blockIdx.x * blockDim.x + threadIdx.x;
    int w = g >> 5, lane = g & 31;
    if (w >= EL) return;
    const float4* a = us + (long long)__ldg(ls + w) * (HID / 4);
    const float4* b = ut + (long long)__ldg(ld + w) * (HID / 4);
    float sum = 0.f;
#pragma unroll
    for (int c = lane; c < HID / 4; c += 32) {
        float4 va = a[c], vb = b[c], vc = bdc[c], vw = wd2[c];
        sum += fmaxf(va.x + vb.x + vc.x, 0.f) * vw.x
             + fmaxf(va.y + vb.y + vc.y, 0.f) * vw.y
             + fmaxf(va.z + vb.z + vc.z, 0.f) * vw.z
             + fmaxf(va.w + vb.w + vc.w, 0.f) * vw.w;
    }
#pragma unroll
    for (int o = 16; o; o >>= 1) sum += __shfl_xor_sync(0xffffffffu, sum, o);
    if (lane == 0) out[w] = sum + bd2[0];
}

// ---------------- launcher ----------------
extern "C" void kernel_launch(void* const* d_in, const int* in_sizes, int n_in,
                              void* d_out, int out_size) {
    const float* x_sotu  = (const float*)d_in[0];
    const float* x_taxon = (const float*)d_in[1];
    const int*   esrc    = (const int*)d_in[2];
    const int*   edst    = (const int*)d_in[3];
    const int*   lsrc    = (const int*)d_in[4];
    const int*   ldst    = (const int*)d_in[5];
    const float* Wl1_st  = (const float*)d_in[6];
    const float* bl1_st  = (const float*)d_in[7];
    const float* Wr1_st  = (const float*)d_in[8];
    const float* Wl1_ts  = (const float*)d_in[9];
    const float* bl1_ts  = (const float*)d_in[10];
    const float* Wr1_ts  = (const float*)d_in[11];
    const float* Wl2_st  = (const float*)d_in[12];
    const float* bl2_st  = (const float*)d_in[13];
    const float* Wr2_st  = (const float*)d_in[14];
    const float* Wl2_ts  = (const float*)d_in[15];
    const float* bl2_ts  = (const float*)d_in[16];
    const float* Wr2_ts  = (const float*)d_in[17];
    const float* Wlin_s  = (const float*)d_in[18];
    const float* blin_s  = (const float*)d_in[19];
    const float* Wlin_t  = (const float*)d_in[20];
    const float* blin_t  = (const float*)d_in[21];
    const float* Wd1     = (const float*)d_in[22];
    const float* bd1     = (const float*)d_in[23];
    const float* Wd2     = (const float*)d_in[24];
    const float* bd2     = (const float*)d_in[25];
    float* out = (float*)d_out;

    float *scratch, *h1t, *h1s, *h2t, *h2s, *us, *ut;
    float *xrs, *xrt, *wt1st, *wt1ts, *wt2st, *wt2ts, *wcsT, *wctT, *bdc;
    cudaGetSymbolAddress((void**)&scratch, g_scratch);
    cudaGetSymbolAddress((void**)&h1t, g_h1t);
    cudaGetSymbolAddress((void**)&h1s, g_h1s);
    cudaGetSymbolAddress((void**)&h2t, g_h2t);
    cudaGetSymbolAddress((void**)&h2s, g_h2s);
    cudaGetSymbolAddress((void**)&us,  g_us);
    cudaGetSymbolAddress((void**)&ut,  g_ut);
    cudaGetSymbolAddress((void**)&xrs, g_xr_s);
    cudaGetSymbolAddress((void**)&xrt, g_xr_t);
    cudaGetSymbolAddress((void**)&wt1st, g_wt1_st);
    cudaGetSymbolAddress((void**)&wt1ts, g_wt1_ts);
    cudaGetSymbolAddress((void**)&wt2st, g_wt2_st);
    cudaGetSymbolAddress((void**)&wt2ts, g_wt2_ts);
    cudaGetSymbolAddress((void**)&wcsT, g_wcsT);
    cudaGetSymbolAddress((void**)&wctT, g_wctT);
    cudaGetSymbolAddress((void**)&bdc, g_bdc);

    static int smem_set = 0;
    if (!smem_set) {
        cudaFuncSetAttribute(gemm_pipe, cudaFuncAttributeMaxDynamicSharedMemorySize, GEMM_SMEM);
        smem_set = 1;
    }

    float* aggT = scratch;
    float* aggS = scratch + (size_t)N_TAXON * HID;
    float* cntT = aggS + (size_t)N_SOTU * HID;
    float* cntS = cntT + N_TAXON;

    const long long ZALL = (long long)N_TAXON * HID + (long long)N_SOTU * HID + N_TAXON + N_SOTU;
    const long long ZAGG = (long long)N_TAXON * HID + (long long)N_SOTU * HID;

    const unsigned gT = (N_TAXON + 127) / 128;   // 157
    const unsigned gS = (N_SOTU + 127) / 128;    // 782

    const long long aggT4 = (long long)N_TAXON * HID / 4;   // 1.28M
    const long long aggS4 = (long long)N_SOTU * HID / 4;    // 6.4M

    // ---- prep: rounded inputs + transposed rounded weights ----
    long long nxs4 = (long long)N_SOTU * DS / 4, nxt4 = (long long)N_TAXON * DT / 4;
    round_copy_kernel<<<(unsigned)((nxs4 + 255) / 256), 256>>>((const float4*)x_sotu, (float4*)xrs, nxs4);
    round_copy_kernel<<<(unsigned)((nxt4 + 255) / 256), 256>>>((const float4*)x_taxon, (float4*)xrt, nxt4);
    wt_kernel<<<384, 256>>>(Wl1_st, DS, Wr1_st, DT, wt1st);
    wt_kernel<<<384, 256>>>(Wl1_ts, DT, Wr1_ts, DS, wt1ts);
    wt_kernel<<<512, 256>>>(Wl2_st, HID, Wr2_st, HID, wt2st);
    wt_kernel<<<512, 256>>>(Wl2_ts, HID, Wr2_ts, HID, wt2ts);
    compose_kernel<<<HID, HID>>>(Wd1, Wlin_s, Wlin_t, blin_s, blin_t, bd1, wcsT, wctT, bdc);

    // ---- layer 1 ----
    zero_kernel<<<(unsigned)((ZALL / 4 + 255) / 256), 256>>>((float4*)scratch, ZALL / 4);
    count_kernel<<<(NE + 255) / 256, 256>>>(esrc, edst, cntS, cntT, NE);

    long long totT = (long long)NE * (HID / 4);
    scatter_kernel<<<(unsigned)((totT + 255) / 256), 256>>>(
        (const float4*)x_sotu, esrc, edst, (float4*)aggT, HID / 4, totT);
    long long totS1 = (long long)NE * (DT / 4);
    scatter_kernel<<<(unsigned)((totS1 + 255) / 256), 256>>>(
        (const float4*)x_taxon, edst, esrc, (float4*)aggS, DT / 4, totS1);

    inv_kernel<<<(N_TAXON + N_SOTU + 255) / 256, 256>>>(cntT, N_TAXON + N_SOTU);
    scale_round_kernel<<<(unsigned)((aggT4 + 255) / 256), 256>>>((float4*)aggT, cntT, aggT4, HID / 4);
    long long aggS4_1 = (long long)N_SOTU * DT / 4;
    scale_round_kernel<<<(unsigned)((aggS4_1 + 255) / 256), 256>>>((float4*)aggS, cntS, aggS4_1, DT / 4);

    gemm_pipe<<<gT, 256, GEMM_SMEM>>>(aggT, DS, xrt, DT, wt1st, bl1_st, h1t, N_TAXON, 3);
    gemm_pipe<<<gS, 256, GEMM_SMEM>>>(aggS, DT, xrs, DS, wt1ts, bl1_ts, h1s, N_SOTU, 3);

    // ---- layer 2 ----
    zero_kernel<<<(unsigned)((ZAGG / 4 + 255) / 256), 256>>>((float4*)scratch, ZAGG / 4);
    scatter_kernel<<<(unsigned)((totT + 255) / 256), 256>>>(
        (const float4*)h1s, esrc, edst, (float4*)aggT, HID / 4, totT);
    long long totS2 = (long long)NE * (HID / 4);
    scatter_kernel<<<(unsigned)((totS2 + 255) / 256), 256>>>(
        (const float4*)h1t, edst, esrc, (float4*)aggS, HID / 4, totS2);

    scale_round_kernel<<<(unsigned)((aggT4 + 255) / 256), 256>>>((float4*)aggT, cntT, aggT4, HID / 4);
    scale_round_kernel<<<(unsigned)((aggS4 + 255) / 256), 256>>>((float4*)aggS, cntS, aggS4, HID / 4);

    gemm_pipe<<<gT, 256, GEMM_SMEM>>>(aggT, HID, h1t, HID, wt2st, bl2_st, h2t, N_TAXON, 3);
    gemm_pipe<<<gS, 256, GEMM_SMEM>>>(aggS, HID, h1s, HID, wt2ts, bl2_ts, h2s, N_SOTU, 3);

    // ---- composed projection (bias folded into bdc, consumed by decode) ----
    gemm_pipe<<<gS, 256, GEMM_SMEM>>>(h2s, HID, nullptr, 0, wcsT, nullptr, us, N_SOTU, 0);
    gemm_pipe<<<gT, 256, GEMM_SMEM>>>(h2t, HID, nullptr, 0, wctT, nullptr, ut, N_TAXON, 0);

    // ---- decoder ----
    decode_kernel<<<(NEL * 32 + 255) / 256, 256>>>(
        (const float4*)us, (const float4*)ut, lsrc, ldst,
        (const float4*)bdc, (const float4*)Wd2, bd2, out, NEL);
}

// round 5
// speedup vs baseline: 2.5917x; 1.2819x over previous
#include <cuda_runtime.h>
#include <cuda_fp16.h>
#include <cstdint>

#define N_SOTU  100000
#define N_TAXON 20000
#define NE      800000
#define NEL     200000
#define DS      256
#define DT      128
#define HID     256

// ---------------- scratch (device globals; no allocation) ----------------
__device__ __align__(128) float  g_scratch[(size_t)N_TAXON*HID + (size_t)N_SOTU*HID + N_TAXON + N_SOTU];
__device__ __align__(128) __half g_aggTh[(size_t)N_TAXON*HID];
__device__ __align__(128) __half g_aggSh[(size_t)N_SOTU*HID];
__device__ __align__(128) __half g_h1t[(size_t)N_TAXON*HID];
__device__ __align__(128) __half g_h1s[(size_t)N_SOTU*HID];
__device__ __align__(128) __half g_h2t[(size_t)N_TAXON*HID];
__device__ __align__(128) __half g_h2s[(size_t)N_SOTU*HID];
__device__ __align__(128) __half g_us[(size_t)N_SOTU*HID];
__device__ __align__(128) __half g_ut[(size_t)N_TAXON*HID];
__device__ __align__(128) __half g_xr_s[(size_t)N_SOTU*DS];
__device__ __align__(128) __half g_xr_t[(size_t)N_TAXON*DT];
__device__ __align__(128) __half g_wt1_st[384*256];
__device__ __align__(128) __half g_wt1_ts[384*256];
__device__ __align__(128) __half g_wt2_st[512*256];
__device__ __align__(128) __half g_wt2_ts[512*256];
__device__ __align__(128) __half g_wcsT[256*256];
__device__ __align__(128) __half g_wctT[256*256];
__device__ __align__(128) float  g_bdc[256];

// ---------------- utility kernels ----------------
__global__ void zero_kernel(float4* p, long long n4) {
    long long i = blockIdx.x * (long long)blockDim.x + threadIdx.x;
    if (i < n4) p[i] = make_float4(0.f, 0.f, 0.f, 0.f);
}

__global__ void count_kernel(const int* __restrict__ src, const int* __restrict__ dst,
                             float* cntS, float* cntT, int E) {
    int e = blockIdx.x * blockDim.x + threadIdx.x;
    if (e < E) {
        atomicAdd(cntS + src[e], 1.f);
        atomicAdd(cntT + dst[e], 1.f);
    }
}

__global__ void inv_kernel(float* p, int n) {
    int i = blockIdx.x * blockDim.x + threadIdx.x;
    if (i < n) p[i] = 1.f / fmaxf(p[i], 1.f);
}

// scatter-add from half features into fp32 accumulators (vector f32x4 atomic)
__global__ void scatter_h(const __half2* __restrict__ feat,
                          const int* __restrict__ from_i,
                          const int* __restrict__ to_i,
                          float4* __restrict__ agg,
                          int D4, long long total) {
    long long gid = blockIdx.x * (long long)blockDim.x + threadIdx.x;
    if (gid >= total) return;
    int e = (int)(gid / D4);
    int c = (int)(gid % D4);
    int f = __ldg(from_i + e);
    int t = __ldg(to_i + e);
    __half2 p0 = feat[(long long)f * (D4 * 2) + c * 2];
    __half2 p1 = feat[(long long)f * (D4 * 2) + c * 2 + 1];
    float2 f0 = __half22float2(p0), f1 = __half22float2(p1);
    float4 v = make_float4(f0.x, f0.y, f1.x, f1.y);
    atomicAdd(&agg[(long long)t * D4 + c], v);
}

// outH[i] = half(agg[i] * inv[row])
__global__ void scale_half_kernel(const float4* __restrict__ agg, const float* __restrict__ inv,
                                  __half2* __restrict__ outH, long long total4, int D4) {
    long long i = blockIdx.x * (long long)blockDim.x + threadIdx.x;
    if (i >= total4) return;
    int row = (int)(i / D4);
    float s = __ldg(inv + row);
    float4 v = agg[i];
    outH[i * 2 + 0] = __floats2half2_rn(v.x * s, v.y * s);
    outH[i * 2 + 1] = __floats2half2_rn(v.z * s, v.w * s);
}

__global__ void tohalf_kernel(const float4* __restrict__ in, __half2* __restrict__ out, long long n4) {
    long long i = blockIdx.x * (long long)blockDim.x + threadIdx.x;
    if (i >= n4) return;
    float4 v = in[i];
    out[i * 2 + 0] = __floats2half2_rn(v.x, v.y);
    out[i * 2 + 1] = __floats2half2_rn(v.z, v.w);
}

// pack concat(W1,W2) transposed, k-pair interleaved: WTp[(k>>1)*512 + h*2 + (k&1)] = W[h][k]
__global__ void wt_kernel(const float* __restrict__ W1, int K1,
                          const float* __restrict__ W2, int K2,
                          __half* __restrict__ WTp) {
    int k = blockIdx.x, h = threadIdx.x;
    float v = (k < K1) ? W1[h * K1 + k] : W2[h * K2 + (k - K1)];
    WTp[(size_t)(k >> 1) * 512 + h * 2 + (k & 1)] = __float2half_rn(v);
}

// ---------------- fp16 HMMA GEMM, 4-stage cp.async pipeline ----------------
// C[n][h] = act( A[n][:] @ WT[:][h] + bias[h] ); A = concat(A1,A2) row-major half,
// WTp k-pair-interleaved half2 [K/2][256]. Block 128x256, BK=32, 8 warps 2x4, m16n8k16.
#define AS_STRIDE 20            // half2 units per A row (32 halves data + 8 pad)
#define BS_STRIDE 264           // half2 units per B kp-row (256 data + 8 pad)
#define A_STAGE_B (128*AS_STRIDE*4)
#define B_STAGE_B (16*BS_STRIDE*4)
#define STAGE_B   (A_STAGE_B + B_STAGE_B)
#define GEMM_SMEM (4*STAGE_B)

__device__ __forceinline__ void mma_f16(float* d, const uint32_t* a, const uint32_t* b) {
    asm volatile(
        "mma.sync.aligned.m16n8k16.row.col.f32.f16.f16.f32 "
        "{%0,%1,%2,%3}, {%4,%5,%6,%7}, {%8,%9}, {%0,%1,%2,%3};"
        : "+f"(d[0]), "+f"(d[1]), "+f"(d[2]), "+f"(d[3])
        : "r"(a[0]), "r"(a[1]), "r"(a[2]), "r"(a[3]), "r"(b[0]), "r"(b[1]));
}

__global__ void __launch_bounds__(256)
gemm_h(const __half* __restrict__ A1, int K1,
       const __half* __restrict__ A2, int K2,
       const __half2* __restrict__ WTp,
       const float* __restrict__ bias,
       __half* __restrict__ C, int Nrows, int doRelu) {
    extern __shared__ char sm[];
    const int tid = threadIdx.x;
    const int wid = tid >> 5, lane = tid & 31;
    const int warpM = wid >> 2, warpN = wid & 3;
    const int lrow = lane >> 2, lcol = lane & 3;
    const int bm = blockIdx.x * 128;
    const int nch = (K1 + K2) >> 5;

    uint32_t sbase = (uint32_t)__cvta_generic_to_shared(sm);

    float2 bv[8];
#pragma unroll
    for (int nt = 0; nt < 8; nt++) {
        int col = warpN * 64 + nt * 8 + 2 * lcol;
        if (bias) { bv[nt].x = __ldg(bias + col); bv[nt].y = __ldg(bias + col + 1); }
        else      { bv[nt].x = 0.f; bv[nt].y = 0.f; }
    }

    float acc[4][8][4];
#pragma unroll
    for (int i = 0; i < 4; i++)
#pragma unroll
        for (int j = 0; j < 8; j++)
#pragma unroll
            for (int q = 0; q < 4; q++) acc[i][j][q] = 0.f;

    auto issue = [&](int c) {
        int slot = c & 3;
        uint32_t aoff = sbase + slot * STAGE_B;
        uint32_t boff = aoff + A_STAGE_B;
        int k0 = c << 5;
        bool inA1 = (k0 < K1);
        // A: 128 rows x 32 halves (64B) -> 512 x 16B chunks, 2/thread
#pragma unroll
        for (int i = 0; i < 2; i++) {
            int idx = tid + i * 256;
            int row = idx >> 2, seg8 = (idx & 3) * 8;   // halves
            int grow = bm + row;
            bool ok = grow < Nrows;
            int gr = ok ? grow : 0;
            const __half* src = inA1 ? A1 + (size_t)gr * K1 + k0 + seg8
                                     : A2 + (size_t)gr * K2 + (k0 - K1) + seg8;
            uint32_t dst = aoff + (uint32_t)(row * (AS_STRIDE * 4) + seg8 * 2);
            int sz = ok ? 16 : 0;
            asm volatile("cp.async.cg.shared.global [%0], [%1], 16, %2;"
                         :: "r"(dst), "l"(src), "r"(sz));
        }
        // B: 16 kp-rows x 256 half2 (1KB) -> 1024 x 16B chunks, 4/thread
        int kp0 = k0 >> 1;
#pragma unroll
        for (int i = 0; i < 4; i++) {
            int idx = tid + i * 256;
            int kr = idx >> 6, seg = (idx & 63) * 4;    // half2 units
            const __half2* src = WTp + (size_t)(kp0 + kr) * 256 + seg;
            uint32_t dst = boff + (uint32_t)(kr * BS_STRIDE + seg) * 4;
            asm volatile("cp.async.cg.shared.global [%0], [%1], 16;"
                         :: "r"(dst), "l"(src));
        }
        asm volatile("cp.async.commit_group;");
    };

    issue(0); issue(1); issue(2);

    for (int c = 0; c < nch; c++) {
        asm volatile("cp.async.wait_group 2;");
        __syncthreads();
        if (c + 3 < nch) issue(c + 3);
        else asm volatile("cp.async.commit_group;");

        int slot = c & 3;
        const uint32_t* As = (const uint32_t*)(sm + slot * STAGE_B);
        const uint32_t* Bs = (const uint32_t*)(sm + slot * STAGE_B + A_STAGE_B);
#pragma unroll
        for (int s = 0; s < 2; s++) {                 // two k16 steps per chunk
            const int kp = s * 8 + lcol;
            uint32_t af[4][4];
#pragma unroll
            for (int mt = 0; mt < 4; mt++) {
                const int row = warpM * 64 + mt * 16 + lrow;
                af[mt][0] = As[row * AS_STRIDE + kp];
                af[mt][1] = As[(row + 8) * AS_STRIDE + kp];
                af[mt][2] = As[row * AS_STRIDE + kp + 4];
                af[mt][3] = As[(row + 8) * AS_STRIDE + kp + 4];
            }
            uint32_t bf[8][2];
#pragma unroll
            for (int nt = 0; nt < 8; nt++) {
                const int col = warpN * 64 + nt * 8 + lrow;
                bf[nt][0] = Bs[kp * BS_STRIDE + col];
                bf[nt][1] = Bs[(kp + 4) * BS_STRIDE + col];
            }
#pragma unroll
            for (int mt = 0; mt < 4; mt++)
#pragma unroll
                for (int nt = 0; nt < 8; nt++)
                    mma_f16(acc[mt][nt], af[mt], bf[nt]);
        }
    }

#pragma unroll
    for (int mt = 0; mt < 4; mt++) {
        const int r0 = bm + warpM * 64 + mt * 16 + lrow;
#pragma unroll
        for (int half = 0; half < 2; half++) {
            const int row = r0 + half * 8;
            if (row >= Nrows) continue;
#pragma unroll
            for (int nt = 0; nt < 8; nt++) {
                const int col = warpN * 64 + nt * 8 + 2 * lcol;
                float vx = acc[mt][nt][half * 2 + 0] + bv[nt].x;
                float vy = acc[mt][nt][half * 2 + 1] + bv[nt].y;
                if (doRelu) { vx = fmaxf(vx, 0.f); vy = fmaxf(vy, 0.f); }
                *(__half2*)(C + (size_t)row * 256 + col) = __floats2half2_rn(vx, vy);
            }
        }
    }
}

// ---------------- weight composition (transposed, packed, half) ----------------
__global__ void compose_kernel(const float* __restrict__ Wd1,
                               const float* __restrict__ Wlin_s,
                               const float* __restrict__ Wlin_t,
                               const float* __restrict__ blin_s,
                               const float* __restrict__ blin_t,
                               const float* __restrict__ bd1,
                               __half* WcsT, __half* WctT, float* bdc) {
    int i = blockIdx.x;      // decoder row (output n)
    int m = threadIdx.x;     // input col (k)
    float ss = 0.f, st = 0.f;
    for (int k = 0; k < HID; k++) {
        float wl = Wd1[i * 2 * HID + k];
        float wr = Wd1[i * 2 * HID + HID + k];
        ss += wl * Wlin_s[k * HID + m];
        st += wr * Wlin_t[k * HID + m];
    }
    size_t idx = (size_t)(m >> 1) * 512 + i * 2 + (m & 1);
    WcsT[idx] = __float2half_rn(ss);
    WctT[idx] = __float2half_rn(st);
    if (m == 0) {
        float b = bd1[i];
        for (int k = 0; k < HID; k++) {
            b += Wd1[i * 2 * HID + k] * blin_s[k];
            b += Wd1[i * 2 * HID + HID + k] * blin_t[k];
        }
        bdc[i] = b;
    }
}

// ---------------- decoder ----------------
__global__ void decode_kernel(const __half* __restrict__ us, const __half* __restrict__ ut,
                              const int* __restrict__ ls, const int* __restrict__ ld,
                              const float4* __restrict__ bdc, const float4* __restrict__ wd2,
                              const float* __restrict__ bd2,
                              float* __restrict__ out, int EL) {
    int g = blockIdx.x * blockDim.x + threadIdx.x;
    int w = g >> 5, lane = g & 31;
    if (w >= EL) return;
    const uint4* a = (const uint4*)(us + (size_t)__ldg(ls + w) * HID);
    const uint4* b = (const uint4*)(ut + (size_t)__ldg(ld + w) * HID);
    uint4 ua = a[lane], ub = b[lane];          // 8 halves each
    float4 c0 = bdc[lane * 2], c1 = bdc[lane * 2 + 1];
    float4 w0 = wd2[lane * 2], w1 = wd2[lane * 2 + 1];
    float2 a0 = __half22float2(*(__half2*)&ua.x), b0 = __half22float2(*(__half2*)&ub.x);
    float2 a1 = __half22float2(*(__half2*)&ua.y), b1 = __half22float2(*(__half2*)&ub.y);
    float2 a2 = __half22float2(*(__half2*)&ua.z), b2 = __half22float2(*(__half2*)&ub.z);
    float2 a3 = __half22float2(*(__half2*)&ua.w), b3 = __half22float2(*(__half2*)&ub.w);
    float sum =
        fmaxf(a0.x + b0.x + c0.x, 0.f) * w0.x + fmaxf(a0.y + b0.y + c0.y, 0.f) * w0.y +
        fmaxf(a1.x + b1.x + c0.z, 0.f) * w0.z + fmaxf(a1.y + b1.y + c0.w, 0.f) * w0.w +
        fmaxf(a2.x + b2.x + c1.x, 0.f) * w1.x + fmaxf(a2.y + b2.y + c1.y, 0.f) * w1.y +
        fmaxf(a3.x + b3.x + c1.z, 0.f) * w1.z + fmaxf(a3.y + b3.y + c1.w, 0.f) * w1.w;
#pragma unroll
    for (int o = 16; o; o >>= 1) sum += __shfl_xor_sync(0xffffffffu, sum, o);
    if (lane == 0) out[w] = sum + bd2[0];
}

// ---------------- launcher ----------------
extern "C" void kernel_launch(void* const* d_in, const int* in_sizes, int n_in,
                              void* d_out, int out_size) {
    const float* x_sotu  = (const float*)d_in[0];
    const float* x_taxon = (const float*)d_in[1];
    const int*   esrc    = (const int*)d_in[2];
    const int*   edst    = (const int*)d_in[3];
    const int*   lsrc    = (const int*)d_in[4];
    const int*   ldst    = (const int*)d_in[5];
    const float* Wl1_st  = (const float*)d_in[6];
    const float* bl1_st  = (const float*)d_in[7];
    const float* Wr1_st  = (const float*)d_in[8];
    const float* Wl1_ts  = (const float*)d_in[9];
    const float* bl1_ts  = (const float*)d_in[10];
    const float* Wr1_ts  = (const float*)d_in[11];
    const float* Wl2_st  = (const float*)d_in[12];
    const float* bl2_st  = (const float*)d_in[13];
    const float* Wr2_st  = (const float*)d_in[14];
    const float* Wl2_ts  = (const float*)d_in[15];
    const float* bl2_ts  = (const float*)d_in[16];
    const float* Wr2_ts  = (const float*)d_in[17];
    const float* Wlin_s  = (const float*)d_in[18];
    const float* blin_s  = (const float*)d_in[19];
    const float* Wlin_t  = (const float*)d_in[20];
    const float* blin_t  = (const float*)d_in[21];
    const float* Wd1     = (const float*)d_in[22];
    const float* bd1     = (const float*)d_in[23];
    const float* Wd2     = (const float*)d_in[24];
    const float* bd2     = (const float*)d_in[25];
    float* out = (float*)d_out;

    float *scratch, *bdc;
    __half *aggTh, *aggSh, *h1t, *h1s, *h2t, *h2s, *us, *ut;
    __half *xrs, *xrt, *wt1st, *wt1ts, *wt2st, *wt2ts, *wcsT, *wctT;
    cudaGetSymbolAddress((void**)&scratch, g_scratch);
    cudaGetSymbolAddress((void**)&aggTh, g_aggTh);
    cudaGetSymbolAddress((void**)&aggSh, g_aggSh);
    cudaGetSymbolAddress((void**)&h1t, g_h1t);
    cudaGetSymbolAddress((void**)&h1s, g_h1s);
    cudaGetSymbolAddress((void**)&h2t, g_h2t);
    cudaGetSymbolAddress((void**)&h2s, g_h2s);
    cudaGetSymbolAddress((void**)&us,  g_us);
    cudaGetSymbolAddress((void**)&ut,  g_ut);
    cudaGetSymbolAddress((void**)&xrs, g_xr_s);
    cudaGetSymbolAddress((void**)&xrt, g_xr_t);
    cudaGetSymbolAddress((void**)&wt1st, g_wt1_st);
    cudaGetSymbolAddress((void**)&wt1ts, g_wt1_ts);
    cudaGetSymbolAddress((void**)&wt2st, g_wt2_st);
    cudaGetSymbolAddress((void**)&wt2ts, g_wt2_ts);
    cudaGetSymbolAddress((void**)&wcsT, g_wcsT);
    cudaGetSymbolAddress((void**)&wctT, g_wctT);
    cudaGetSymbolAddress((void**)&bdc, g_bdc);

    static int smem_set = 0;
    if (!smem_set) {
        cudaFuncSetAttribute(gemm_h, cudaFuncAttributeMaxDynamicSharedMemorySize, GEMM_SMEM);
        smem_set = 1;
    }

    float* aggT = scratch;
    float* aggS = scratch + (size_t)N_TAXON * HID;
    float* cntT = aggS + (size_t)N_SOTU * HID;
    float* cntS = cntT + N_TAXON;

    const long long ZALL = (long long)N_TAXON * HID + (long long)N_SOTU * HID + N_TAXON + N_SOTU;
    const long long ZAGG = (long long)N_TAXON * HID + (long long)N_SOTU * HID;

    const unsigned gT = (N_TAXON + 127) / 128;   // 157
    const unsigned gS = (N_SOTU + 127) / 128;    // 782

    const long long aggT4 = (long long)N_TAXON * HID / 4;
    const long long aggS4 = (long long)N_SOTU * HID / 4;

    // ---- prep: half inputs + packed half weights ----
    long long nxs4 = (long long)N_SOTU * DS / 4, nxt4 = (long long)N_TAXON * DT / 4;
    tohalf_kernel<<<(unsigned)((nxs4 + 255) / 256), 256>>>((const float4*)x_sotu, (__half2*)xrs, nxs4);
    tohalf_kernel<<<(unsigned)((nxt4 + 255) / 256), 256>>>((const float4*)x_taxon, (__half2*)xrt, nxt4);
    wt_kernel<<<384, 256>>>(Wl1_st, DS, Wr1_st, DT, wt1st);
    wt_kernel<<<384, 256>>>(Wl1_ts, DT, Wr1_ts, DS, wt1ts);
    wt_kernel<<<512, 256>>>(Wl2_st, HID, Wr2_st, HID, wt2st);
    wt_kernel<<<512, 256>>>(Wl2_ts, HID, Wr2_ts, HID, wt2ts);
    compose_kernel<<<HID, HID>>>(Wd1, Wlin_s, Wlin_t, blin_s, blin_t, bd1, wcsT, wctT, bdc);

    // ---- layer 1 ----
    zero_kernel<<<(unsigned)((ZALL / 4 + 255) / 256), 256>>>((float4*)scratch, ZALL / 4);
    count_kernel<<<(NE + 255) / 256, 256>>>(esrc, edst, cntS, cntT, NE);

    long long totT = (long long)NE * (HID / 4);
    scatter_h<<<(unsigned)((totT + 255) / 256), 256>>>(
        (const __half2*)xrs, esrc, edst, (float4*)aggT, HID / 4, totT);
    long long totS1 = (long long)NE * (DT / 4);
    scatter_h<<<(unsigned)((totS1 + 255) / 256), 256>>>(
        (const __half2*)xrt, edst, esrc, (float4*)aggS, DT / 4, totS1);

    inv_kernel<<<(N_TAXON + N_SOTU + 255) / 256, 256>>>(cntT, N_TAXON + N_SOTU);
    scale_half_kernel<<<(unsigned)((aggT4 + 255) / 256), 256>>>(
        (const float4*)aggT, cntT, (__half2*)aggTh, aggT4, HID / 4);
    long long aggS4_1 = (long long)N_SOTU * DT / 4;
    scale_half_kernel<<<(unsigned)((aggS4_1 + 255) / 256), 256>>>(
        (const float4*)aggS, cntS, (__half2*)aggSh, aggS4_1, DT / 4);

    gemm_h<<<gT, 256, GEMM_SMEM>>>(aggTh, DS, xrt, DT, (const __half2*)wt1st, bl1_st, h1t, N_TAXON, 1);
    gemm_h<<<gS, 256, GEMM_SMEM>>>(aggSh, DT, xrs, DS, (const __half2*)wt1ts, bl1_ts, h1s, N_SOTU, 1);

    // ---- layer 2 ----
    zero_kernel<<<(unsigned)((ZAGG / 4 + 255) / 256), 256>>>((float4*)scratch, ZAGG / 4);
    scatter_h<<<(unsigned)((totT + 255) / 256), 256>>>(
        (const __half2*)h1s, esrc, edst, (float4*)aggT, HID / 4, totT);
    long long totS2 = (long long)NE * (HID / 4);
    scatter_h<<<(unsigned)((totS2 + 255) / 256), 256>>>(
        (const __half2*)h1t, edst, esrc, (float4*)aggS, HID / 4, totS2);

    scale_half_kernel<<<(unsigned)((aggT4 + 255) / 256), 256>>>(
        (const float4*)aggT, cntT, (__half2*)aggTh, aggT4, HID / 4);
    scale_half_kernel<<<(unsigned)((aggS4 + 255) / 256), 256>>>(
        (const float4*)aggS, cntS, (__half2*)aggSh, aggS4, HID / 4);

    gemm_h<<<gT, 256, GEMM_SMEM>>>(aggTh, HID, h1t, HID, (const __half2*)wt2st, bl2_st, h2t, N_TAXON, 1);
    gemm_h<<<gS, 256, GEMM_SMEM>>>(aggSh, HID, h1s, HID, (const __half2*)wt2ts, bl2_ts, h2s, N_SOTU, 1);

    // ---- composed projection (Wlin folded; bias folded into bdc) ----
    gemm_h<<<gS, 256, GEMM_SMEM>>>(h2s, HID, (const __half*)nullptr, 0, (const __half2*)wcsT, nullptr, us, N_SOTU, 0);
    gemm_h<<<gT, 256, GEMM_SMEM>>>(h2t, HID, (const __half*)nullptr, 0, (const __half2*)wctT, nullptr, ut, N_TAXON, 0);

    // ---- decoder ----
    decode_kernel<<<(NEL * 32 + 255) / 256, 256>>>(
        us, ut, lsrc, ldst,
        (const float4*)bdc, (const float4*)Wd2, bd2, out, NEL);
}

// round 6
// speedup vs baseline: 4.3800x; 1.6900x over previous
#include <cuda_runtime.h>
#include <cuda_fp16.h>
#include <cstdint>

#define N_SOTU  100000
#define N_TAXON 20000
#define NE      800000
#define NEL     200000
#define DS      256
#define DT      128
#define HID     256

// ---------------- scratch (device globals; no allocation) ----------------
__device__ __align__(128) __half g_aggTh[(size_t)N_TAXON*HID];
__device__ __align__(128) __half g_aggSh[(size_t)N_SOTU*HID];
__device__ __align__(128) __half g_h1t[(size_t)N_TAXON*HID];
__device__ __align__(128) __half g_h1s[(size_t)N_SOTU*HID];
__device__ __align__(128) __half g_h2t[(size_t)N_TAXON*HID];
__device__ __align__(128) __half g_h2s[(size_t)N_SOTU*HID];
__device__ __align__(128) __half g_us[(size_t)N_SOTU*HID];
__device__ __align__(128) __half g_ut[(size_t)N_TAXON*HID];
__device__ __align__(128) __half g_xr_s[(size_t)N_SOTU*DS];
__device__ __align__(128) __half g_xr_t[(size_t)N_TAXON*DT];
__device__ __align__(128) __half g_wt1_st[384*256];
__device__ __align__(128) __half g_wt1_ts[384*256];
__device__ __align__(128) __half g_wt2_st[512*256];
__device__ __align__(128) __half g_wt2_ts[512*256];
__device__ __align__(128) __half g_wcsT[256*256];
__device__ __align__(128) __half g_wctT[256*256];
__device__ __align__(128) float  g_bdc[256];
// CSR
__device__ int g_rowT[N_TAXON + 1];
__device__ int g_rowS[N_SOTU + 1];
__device__ int g_curT[N_TAXON];
__device__ int g_curS[N_SOTU];
__device__ int g_adjT[NE];
__device__ int g_adjS[NE];

// ---------------- prep kernels ----------------
__global__ void tohalf_kernel(const float4* __restrict__ in, __half2* __restrict__ out, long long n4) {
    long long i = blockIdx.x * (long long)blockDim.x + threadIdx.x;
    if (i >= n4) return;
    float4 v = in[i];
    out[i * 2 + 0] = __floats2half2_rn(v.x, v.y);
    out[i * 2 + 1] = __floats2half2_rn(v.z, v.w);
}

// pack concat(W1,W2) transposed, k-pair interleaved
__global__ void wt_kernel(const float* __restrict__ W1, int K1,
                          const float* __restrict__ W2, int K2,
                          __half* __restrict__ WTp) {
    int k = blockIdx.x, h = threadIdx.x;
    float v = (k < K1) ? W1[h * K1 + k] : W2[h * K2 + (k - K1)];
    WTp[(size_t)(k >> 1) * 512 + h * 2 + (k & 1)] = __float2half_rn(v);
}

// ---------------- CSR build ----------------
__global__ void zero_int_kernel(int* p, int n) {
    int i = blockIdx.x * blockDim.x + threadIdx.x;
    if (i < n) p[i] = 0;
}

__global__ void hist_kernel(const int* __restrict__ src, const int* __restrict__ dst,
                            int* curS, int* curT, int E) {
    int e = blockIdx.x * blockDim.x + threadIdx.x;
    if (e < E) {
        atomicAdd(curT + dst[e], 1);
        atomicAdd(curS + src[e], 1);
    }
}

// single-block exclusive scan, warp-shuffle based; row[n] = total
__global__ void __launch_bounds__(1024)
scan_kernel(const int* __restrict__ cnt, int* __restrict__ row, int n) {
    __shared__ int wsum[32];
    __shared__ int carry;
    int tid = threadIdx.x, lane = tid & 31, wid = tid >> 5;
    if (tid == 0) carry = 0;
    __syncthreads();
    for (int base = 0; base < n; base += 1024) {
        int v = (base + tid < n) ? cnt[base + tid] : 0;
        int x = v;
#pragma unroll
        for (int o = 1; o < 32; o <<= 1) {
            int t = __shfl_up_sync(0xffffffffu, x, o);
            if (lane >= o) x += t;
        }
        if (lane == 31) wsum[wid] = x;
        __syncthreads();
        if (wid == 0) {
            int y = wsum[lane];
#pragma unroll
            for (int o = 1; o < 32; o <<= 1) {
                int t = __shfl_up_sync(0xffffffffu, y, o);
                if (lane >= o) y += t;
            }
            wsum[lane] = y;
        }
        __syncthreads();
        int incl = x + (wid ? wsum[wid - 1] : 0) + carry;
        if (base + tid < n) row[base + tid] = incl - v;
        __syncthreads();
        if (tid == 1023) carry = incl;
        __syncthreads();
    }
    if (tid == 0) row[n] = carry;
}

__global__ void fill_kernel(const int* __restrict__ src, const int* __restrict__ dst,
                            const int* __restrict__ rowT, int* curT, int* adjT,
                            const int* __restrict__ rowS, int* curS, int* adjS, int E) {
    int e = blockIdx.x * blockDim.x + threadIdx.x;
    if (e >= E) return;
    int s = src[e], d = dst[e];
    int pT = __ldg(rowT + d) + atomicAdd(curT + d, 1);
    adjT[pT] = s;
    int pS = __ldg(rowS + s) + atomicAdd(curS + s, 1);
    adjS[pS] = d;
}

// ---------------- warp-per-node mean aggregation ----------------
__global__ void agg256_kernel(const __half* __restrict__ feat,
                              const int* __restrict__ rowp,
                              const int* __restrict__ adj,
                              __half* __restrict__ out, int nNodes) {
    int gw = (blockIdx.x * blockDim.x + threadIdx.x) >> 5;
    int lane = threadIdx.x & 31;
    if (gw >= nNodes) return;
    int s = __ldg(rowp + gw), e = __ldg(rowp + gw + 1);
    float acc[8] = {0.f, 0.f, 0.f, 0.f, 0.f, 0.f, 0.f, 0.f};
    const size_t lo = (size_t)lane * 8;
    int i = s;
    for (; i + 2 <= e; i += 2) {
        int n0 = __ldg(adj + i), n1 = __ldg(adj + i + 1);
        uint4 u0 = *(const uint4*)(feat + (size_t)n0 * 256 + lo);
        uint4 u1 = *(const uint4*)(feat + (size_t)n1 * 256 + lo);
        const __half2* h0 = (const __half2*)&u0;
        const __half2* h1 = (const __half2*)&u1;
#pragma unroll
        for (int j = 0; j < 4; j++) {
            float2 f0 = __half22float2(h0[j]);
            float2 f1 = __half22float2(h1[j]);
            acc[2 * j]     += f0.x + f1.x;
            acc[2 * j + 1] += f0.y + f1.y;
        }
    }
    if (i < e) {
        int n0 = __ldg(adj + i);
        uint4 u0 = *(const uint4*)(feat + (size_t)n0 * 256 + lo);
        const __half2* h0 = (const __half2*)&u0;
#pragma unroll
        for (int j = 0; j < 4; j++) {
            float2 f0 = __half22float2(h0[j]);
            acc[2 * j]     += f0.x;
            acc[2 * j + 1] += f0.y;
        }
    }
    float inv = 1.f / fmaxf((float)(e - s), 1.f);
    __half2 o[4];
#pragma unroll
    for (int j = 0; j < 4; j++)
        o[j] = __floats2half2_rn(acc[2 * j] * inv, acc[2 * j + 1] * inv);
    *(uint4*)(out + (size_t)gw * 256 + lo) = *(uint4*)o;
}

__global__ void agg128_kernel(const __half* __restrict__ feat,
                              const int* __restrict__ rowp,
                              const int* __restrict__ adj,
                              __half* __restrict__ out, int nNodes) {
    int gw = (blockIdx.x * blockDim.x + threadIdx.x) >> 5;
    int lane = threadIdx.x & 31;
    if (gw >= nNodes) return;
    int s = __ldg(rowp + gw), e = __ldg(rowp + gw + 1);
    float acc[4] = {0.f, 0.f, 0.f, 0.f};
    const size_t lo = (size_t)lane * 4;
    int i = s;
    for (; i + 2 <= e; i += 2) {
        int n0 = __ldg(adj + i), n1 = __ldg(adj + i + 1);
        uint2 u0 = *(const uint2*)(feat + (size_t)n0 * 128 + lo);
        uint2 u1 = *(const uint2*)(feat + (size_t)n1 * 128 + lo);
        const __half2* h0 = (const __half2*)&u0;
        const __half2* h1 = (const __half2*)&u1;
#pragma unroll
        for (int j = 0; j < 2; j++) {
            float2 f0 = __half22float2(h0[j]);
            float2 f1 = __half22float2(h1[j]);
            acc[2 * j]     += f0.x + f1.x;
            acc[2 * j + 1] += f0.y + f1.y;
        }
    }
    if (i < e) {
        int n0 = __ldg(adj + i);
        uint2 u0 = *(const uint2*)(feat + (size_t)n0 * 128 + lo);
        const __half2* h0 = (const __half2*)&u0;
#pragma unroll
        for (int j = 0; j < 2; j++) {
            float2 f0 = __half22float2(h0[j]);
            acc[2 * j]     += f0.x;
            acc[2 * j + 1] += f0.y;
        }
    }
    float inv = 1.f / fmaxf((float)(e - s), 1.f);
    __half2 o[2];
#pragma unroll
    for (int j = 0; j < 2; j++)
        o[j] = __floats2half2_rn(acc[2 * j] * inv, acc[2 * j + 1] * inv);
    *(uint2*)(out + (size_t)gw * 128 + lo) = *(uint2*)o;
}

// ---------------- fp16 HMMA GEMM, 4-stage cp.async pipeline ----------------
#define AS_STRIDE 20
#define BS_STRIDE 264
#define A_STAGE_B (128*AS_STRIDE*4)
#define B_STAGE_B (16*BS_STRIDE*4)
#define STAGE_B   (A_STAGE_B + B_STAGE_B)
#define GEMM_SMEM (4*STAGE_B)

__device__ __forceinline__ void mma_f16(float* d, const uint32_t* a, const uint32_t* b) {
    asm volatile(
        "mma.sync.aligned.m16n8k16.row.col.f32.f16.f16.f32 "
        "{%0,%1,%2,%3}, {%4,%5,%6,%7}, {%8,%9}, {%0,%1,%2,%3};"
        : "+f"(d[0]), "+f"(d[1]), "+f"(d[2]), "+f"(d[3])
        : "r"(a[0]), "r"(a[1]), "r"(a[2]), "r"(a[3]), "r"(b[0]), "r"(b[1]));
}

__global__ void __launch_bounds__(256)
gemm_h(const __half* __restrict__ A1, int K1,
       const __half* __restrict__ A2, int K2,
       const __half2* __restrict__ WTp,
       const float* __restrict__ bias,
       __half* __restrict__ C, int Nrows, int doRelu) {
    extern __shared__ char sm[];
    const int tid = threadIdx.x;
    const int wid = tid >> 5, lane = tid & 31;
    const int warpM = wid >> 2, warpN = wid & 3;
    const int lrow = lane >> 2, lcol = lane & 3;
    const int bm = blockIdx.x * 128;
    const int nch = (K1 + K2) >> 5;

    uint32_t sbase = (uint32_t)__cvta_generic_to_shared(sm);

    float2 bv[8];
#pragma unroll
    for (int nt = 0; nt < 8; nt++) {
        int col = warpN * 64 + nt * 8 + 2 * lcol;
        if (bias) { bv[nt].x = __ldg(bias + col); bv[nt].y = __ldg(bias + col + 1); }
        else      { bv[nt].x = 0.f; bv[nt].y = 0.f; }
    }

    float acc[4][8][4];
#pragma unroll
    for (int i = 0; i < 4; i++)
#pragma unroll
        for (int j = 0; j < 8; j++)
#pragma unroll
            for (int q = 0; q < 4; q++) acc[i][j][q] = 0.f;

    auto issue = [&](int c) {
        int slot = c & 3;
        uint32_t aoff = sbase + slot * STAGE_B;
        uint32_t boff = aoff + A_STAGE_B;
        int k0 = c << 5;
        bool inA1 = (k0 < K1);
#pragma unroll
        for (int i = 0; i < 2; i++) {
            int idx = tid + i * 256;
            int row = idx >> 2, seg8 = (idx & 3) * 8;
            int grow = bm + row;
            bool ok = grow < Nrows;
            int gr = ok ? grow : 0;
            const __half* src = inA1 ? A1 + (size_t)gr * K1 + k0 + seg8
                                     : A2 + (size_t)gr * K2 + (k0 - K1) + seg8;
            uint32_t dst = aoff + (uint32_t)(row * (AS_STRIDE * 4) + seg8 * 2);
            int sz = ok ? 16 : 0;
            asm volatile("cp.async.cg.shared.global [%0], [%1], 16, %2;"
                         :: "r"(dst), "l"(src), "r"(sz));
        }
        int kp0 = k0 >> 1;
#pragma unroll
        for (int i = 0; i < 4; i++) {
            int idx = tid + i * 256;
            int kr = idx >> 6, seg = (idx & 63) * 4;
            const __half2* src = WTp + (size_t)(kp0 + kr) * 256 + seg;
            uint32_t dst = boff + (uint32_t)(kr * BS_STRIDE + seg) * 4;
            asm volatile("cp.async.cg.shared.global [%0], [%1], 16;"
                         :: "r"(dst), "l"(src));
        }
        asm volatile("cp.async.commit_group;");
    };

    issue(0); issue(1); issue(2);

    for (int c = 0; c < nch; c++) {
        asm volatile("cp.async.wait_group 2;");
        __syncthreads();
        if (c + 3 < nch) issue(c + 3);
        else asm volatile("cp.async.commit_group;");

        int slot = c & 3;
        const uint32_t* As = (const uint32_t*)(sm + slot * STAGE_B);
        const uint32_t* Bs = (const uint32_t*)(sm + slot * STAGE_B + A_STAGE_B);
#pragma unroll
        for (int s = 0; s < 2; s++) {
            const int kp = s * 8 + lcol;
            uint32_t af[4][4];
#pragma unroll
            for (int mt = 0; mt < 4; mt++) {
                const int row = warpM * 64 + mt * 16 + lrow;
                af[mt][0] = As[row * AS_STRIDE + kp];
                af[mt][1] = As[(row + 8) * AS_STRIDE + kp];
                af[mt][2] = As[row * AS_STRIDE + kp + 4];
                af[mt][3] = As[(row + 8) * AS_STRIDE + kp + 4];
            }
            uint32_t bf[8][2];
#pragma unroll
            for (int nt = 0; nt < 8; nt++) {
                const int col = warpN * 64 + nt * 8 + lrow;
                bf[nt][0] = Bs[kp * BS_STRIDE + col];
                bf[nt][1] = Bs[(kp + 4) * BS_STRIDE + col];
            }
#pragma unroll
            for (int mt = 0; mt < 4; mt++)
#pragma unroll
                for (int nt = 0; nt < 8; nt++)
                    mma_f16(acc[mt][nt], af[mt], bf[nt]);
        }
    }

#pragma unroll
    for (int mt = 0; mt < 4; mt++) {
        const int r0 = bm + warpM * 64 + mt * 16 + lrow;
#pragma unroll
        for (int half = 0; half < 2; half++) {
            const int row = r0 + half * 8;
            if (row >= Nrows) continue;
#pragma unroll
            for (int nt = 0; nt < 8; nt++) {
                const int col = warpN * 64 + nt * 8 + 2 * lcol;
                float vx = acc[mt][nt][half * 2 + 0] + bv[nt].x;
                float vy = acc[mt][nt][half * 2 + 1] + bv[nt].y;
                if (doRelu) { vx = fmaxf(vx, 0.f); vy = fmaxf(vy, 0.f); }
                *(__half2*)(C + (size_t)row * 256 + col) = __floats2half2_rn(vx, vy);
            }
        }
    }
}

// ---------------- weight composition (transposed, packed, half) ----------------
__global__ void compose_kernel(const float* __restrict__ Wd1,
                               const float* __restrict__ Wlin_s,
                               const float* __restrict__ Wlin_t,
                               const float* __restrict__ blin_s,
                               const float* __restrict__ blin_t,
                               const float* __restrict__ bd1,
                               __half* WcsT, __half* WctT, float* bdc) {
    int i = blockIdx.x;
    int m = threadIdx.x;
    float ss = 0.f, st = 0.f;
    for (int k = 0; k < HID; k++) {
        float wl = Wd1[i * 2 * HID + k];
        float wr = Wd1[i * 2 * HID + HID + k];
        ss += wl * Wlin_s[k * HID + m];
        st += wr * Wlin_t[k * HID + m];
    }
    size_t idx = (size_t)(m >> 1) * 512 + i * 2 + (m & 1);
    WcsT[idx] = __float2half_rn(ss);
    WctT[idx] = __float2half_rn(st);
    if (m == 0) {
        float b = bd1[i];
        for (int k = 0; k < HID; k++) {
            b += Wd1[i * 2 * HID + k] * blin_s[k];
            b += Wd1[i * 2 * HID + HID + k] * blin_t[k];
        }
        bdc[i] = b;
    }
}

// ---------------- decoder ----------------
__global__ void decode_kernel(const __half* __restrict__ us, const __half* __restrict__ ut,
                              const int* __restrict__ ls, const int* __restrict__ ld,
                              const float4* __restrict__ bdc, const float4* __restrict__ wd2,
                              const float* __restrict__ bd2,
                              float* __restrict__ out, int EL) {
    int g = blockIdx.x * blockDim.x + threadIdx.x;
    int w = g >> 5, lane = g & 31;
    if (w >= EL) return;
    const uint4* a = (const uint4*)(us + (size_t)__ldg(ls + w) * HID);
    const uint4* b = (const uint4*)(ut + (size_t)__ldg(ld + w) * HID);
    uint4 ua = a[lane], ub = b[lane];
    float4 c0 = bdc[lane * 2], c1 = bdc[lane * 2 + 1];
    float4 w0 = wd2[lane * 2], w1 = wd2[lane * 2 + 1];
    float2 a0 = __half22float2(*(__half2*)&ua.x), b0 = __half22float2(*(__half2*)&ub.x);
    float2 a1 = __half22float2(*(__half2*)&ua.y), b1 = __half22float2(*(__half2*)&ub.y);
    float2 a2 = __half22float2(*(__half2*)&ua.z), b2 = __half22float2(*(__half2*)&ub.z);
    float2 a3 = __half22float2(*(__half2*)&ua.w), b3 = __half22float2(*(__half2*)&ub.w);
    float sum =
        fmaxf(a0.x + b0.x + c0.x, 0.f) * w0.x + fmaxf(a0.y + b0.y + c0.y, 0.f) * w0.y +
        fmaxf(a1.x + b1.x + c0.z, 0.f) * w0.z + fmaxf(a1.y + b1.y + c0.w, 0.f) * w0.w +
        fmaxf(a2.x + b2.x + c1.x, 0.f) * w1.x + fmaxf(a2.y + b2.y + c1.y, 0.f) * w1.y +
        fmaxf(a3.x + b3.x + c1.z, 0.f) * w1.z + fmaxf(a3.y + b3.y + c1.w, 0.f) * w1.w;
#pragma unroll
    for (int o = 16; o; o >>= 1) sum += __shfl_xor_sync(0xffffffffu, sum, o);
    if (lane == 0) out[w] = sum + bd2[0];
}

// ---------------- launcher ----------------
extern "C" void kernel_launch(void* const* d_in, const int* in_sizes, int n_in,
                              void* d_out, int out_size) {
    const float* x_sotu  = (const float*)d_in[0];
    const float* x_taxon = (const float*)d_in[1];
    const int*   esrc    = (const int*)d_in[2];
    const int*   edst    = (const int*)d_in[3];
    const int*   lsrc    = (const int*)d_in[4];
    const int*   ldst    = (const int*)d_in[5];
    const float* Wl1_st  = (const float*)d_in[6];
    const float* bl1_st  = (const float*)d_in[7];
    const float* Wr1_st  = (const float*)d_in[8];
    const float* Wl1_ts  = (const float*)d_in[9];
    const float* bl1_ts  = (const float*)d_in[10];
    const float* Wr1_ts  = (const float*)d_in[11];
    const float* Wl2_st  = (const float*)d_in[12];
    const float* bl2_st  = (const float*)d_in[13];
    const float* Wr2_st  = (const float*)d_in[14];
    const float* Wl2_ts  = (const float*)d_in[15];
    const float* bl2_ts  = (const float*)d_in[16];
    const float* Wr2_ts  = (const float*)d_in[17];
    const float* Wlin_s  = (const float*)d_in[18];
    const float* blin_s  = (const float*)d_in[19];
    const float* Wlin_t  = (const float*)d_in[20];
    const float* blin_t  = (const float*)d_in[21];
    const float* Wd1     = (const float*)d_in[22];
    const float* bd1     = (const float*)d_in[23];
    const float* Wd2     = (const float*)d_in[24];
    const float* bd2     = (const float*)d_in[25];
    float* out = (float*)d_out;

    float *bdc;
    __half *aggTh, *aggSh, *h1t, *h1s, *h2t, *h2s, *us, *ut;
    __half *xrs, *xrt, *wt1st, *wt1ts, *wt2st, *wt2ts, *wcsT, *wctT;
    int *rowT, *rowS, *curT, *curS, *adjT, *adjS;
    cudaGetSymbolAddress((void**)&aggTh, g_aggTh);
    cudaGetSymbolAddress((void**)&aggSh, g_aggSh);
    cudaGetSymbolAddress((void**)&h1t, g_h1t);
    cudaGetSymbolAddress((void**)&h1s, g_h1s);
    cudaGetSymbolAddress((void**)&h2t, g_h2t);
    cudaGetSymbolAddress((void**)&h2s, g_h2s);
    cudaGetSymbolAddress((void**)&us,  g_us);
    cudaGetSymbolAddress((void**)&ut,  g_ut);
    cudaGetSymbolAddress((void**)&xrs, g_xr_s);
    cudaGetSymbolAddress((void**)&xrt, g_xr_t);
    cudaGetSymbolAddress((void**)&wt1st, g_wt1_st);
    cudaGetSymbolAddress((void**)&wt1ts, g_wt1_ts);
    cudaGetSymbolAddress((void**)&wt2st, g_wt2_st);
    cudaGetSymbolAddress((void**)&wt2ts, g_wt2_ts);
    cudaGetSymbolAddress((void**)&wcsT, g_wcsT);
    cudaGetSymbolAddress((void**)&wctT, g_wctT);
    cudaGetSymbolAddress((void**)&bdc, g_bdc);
    cudaGetSymbolAddress((void**)&rowT, g_rowT);
    cudaGetSymbolAddress((void**)&rowS, g_rowS);
    cudaGetSymbolAddress((void**)&curT, g_curT);
    cudaGetSymbolAddress((void**)&curS, g_curS);
    cudaGetSymbolAddress((void**)&adjT, g_adjT);
    cudaGetSymbolAddress((void**)&adjS, g_adjS);

    static int smem_set = 0;
    if (!smem_set) {
        cudaFuncSetAttribute(gemm_h, cudaFuncAttributeMaxDynamicSharedMemorySize, GEMM_SMEM);
        smem_set = 1;
    }

    const unsigned gT = (N_TAXON + 127) / 128;
    const unsigned gS = (N_SOTU + 127) / 128;
    const unsigned wT = (N_TAXON * 32 + 255) / 256;   // warp-per-node grids
    const unsigned wS = (N_SOTU * 32 + 255) / 256;

    // ---- prep: half inputs + packed half weights (independent of graph) ----
    long long nxs4 = (long long)N_SOTU * DS / 4, nxt4 = (long long)N_TAXON * DT / 4;
    tohalf_kernel<<<(unsigned)((nxs4 + 255) / 256), 256>>>((const float4*)x_sotu, (__half2*)xrs, nxs4);
    tohalf_kernel<<<(unsigned)((nxt4 + 255) / 256), 256>>>((const float4*)x_taxon, (__half2*)xrt, nxt4);
    wt_kernel<<<384, 256>>>(Wl1_st, DS, Wr1_st, DT, wt1st);
    wt_kernel<<<384, 256>>>(Wl1_ts, DT, Wr1_ts, DS, wt1ts);
    wt_kernel<<<512, 256>>>(Wl2_st, HID, Wr2_st, HID, wt2st);
    wt_kernel<<<512, 256>>>(Wl2_ts, HID, Wr2_ts, HID, wt2ts);
    compose_kernel<<<HID, HID>>>(Wd1, Wlin_s, Wlin_t, blin_s, blin_t, bd1, wcsT, wctT, bdc);

    // ---- CSR build (graph static across layers) ----
    zero_int_kernel<<<(N_TAXON + 255) / 256, 256>>>(curT, N_TAXON);
    zero_int_kernel<<<(N_SOTU + 255) / 256, 256>>>(curS, N_SOTU);
    hist_kernel<<<(NE + 255) / 256, 256>>>(esrc, edst, curS, curT, NE);
    scan_kernel<<<1, 1024>>>(curT, rowT, N_TAXON);
    scan_kernel<<<1, 1024>>>(curS, rowS, N_SOTU);
    zero_int_kernel<<<(N_TAXON + 255) / 256, 256>>>(curT, N_TAXON);
    zero_int_kernel<<<(N_SOTU + 255) / 256, 256>>>(curS, N_SOTU);
    fill_kernel<<<(NE + 255) / 256, 256>>>(esrc, edst, rowT, curT, adjT, rowS, curS, adjS, NE);

    // ---- layer 1: gather-aggregate + GEMM ----
    agg256_kernel<<<wT, 256>>>(xrs, rowT, adjT, aggTh, N_TAXON);
    agg128_kernel<<<wS, 256>>>(xrt, rowS, adjS, aggSh, N_SOTU);

    gemm_h<<<gT, 256, GEMM_SMEM>>>(aggTh, DS, xrt, DT, (const __half2*)wt1st, bl1_st, h1t, N_TAXON, 1);
    gemm_h<<<gS, 256, GEMM_SMEM>>>(aggSh, DT, xrs, DS, (const __half2*)wt1ts, bl1_ts, h1s, N_SOTU, 1);

    // ---- layer 2 ----
    agg256_kernel<<<wT, 256>>>(h1s, rowT, adjT, aggTh, N_TAXON);
    agg256_kernel<<<wS, 256>>>(h1t, rowS, adjS, aggSh, N_SOTU);

    gemm_h<<<gT, 256, GEMM_SMEM>>>(aggTh, HID, h1t, HID, (const __half2*)wt2st, bl2_st, h2t, N_TAXON, 1);
    gemm_h<<<gS, 256, GEMM_SMEM>>>(aggSh, HID, h1s, HID, (const __half2*)wt2ts, bl2_ts, h2s, N_SOTU, 1);

    // ---- composed projection ----
    gemm_h<<<gS, 256, GEMM_SMEM>>>(h2s, HID, (const __half*)nullptr, 0, (const __half2*)wcsT, nullptr, us, N_SOTU, 0);
    gemm_h<<<gT, 256, GEMM_SMEM>>>(h2t, HID, (const __half*)nullptr, 0, (const __half2*)wctT, nullptr, ut, N_TAXON, 0);

    // ---- decoder ----
    decode_kernel<<<(NEL * 32 + 255) / 256, 256>>>(
        us, ut, lsrc, ldst,
        (const float4*)bdc, (const float4*)Wd2, bd2, out, NEL);
}

// round 7
// speedup vs baseline: 4.9038x; 1.1196x over previous
#include <cuda_runtime.h>
#include <cuda_fp16.h>
#include <cstdint>

#define N_SOTU  100000
#define N_TAXON 20000
#define NE      800000
#define NEL     200000
#define DS      256
#define DT      128
#define HID     256

// ---------------- scratch (device globals; no allocation) ----------------
__device__ __align__(128) __half g_aggTh[(size_t)N_TAXON*HID];
__device__ __align__(128) __half g_aggSh[(size_t)N_SOTU*HID];
__device__ __align__(128) __half g_h1t[(size_t)N_TAXON*HID];
__device__ __align__(128) __half g_h1s[(size_t)N_SOTU*HID];
__device__ __align__(128) __half g_us[(size_t)N_SOTU*HID];
__device__ __align__(128) __half g_ut[(size_t)N_TAXON*HID];
__device__ __align__(128) __half g_xr_s[(size_t)N_SOTU*DS];
__device__ __align__(128) __half g_xr_t[(size_t)N_TAXON*DT];
__device__ __align__(128) __half g_wt1_st[384*256];
__device__ __align__(128) __half g_wt1_ts[384*256];
__device__ __align__(128) __half g_wt2_st[512*256];
__device__ __align__(128) __half g_wt2_ts[512*256];
__device__ __align__(128) __half g_wcsT[256*256];
__device__ __align__(128) __half g_wctT[256*256];
__device__ __align__(128) float  g_bdc[256];
// CSR
__device__ int g_rowT[N_TAXON + 1];
__device__ int g_rowS[N_SOTU + 1];
__device__ int g_curT[N_TAXON];
__device__ int g_curS[N_SOTU];
__device__ int g_adjT[NE];
__device__ int g_adjS[NE];

// ---------------- prep kernels ----------------
__global__ void tohalf_kernel(const float4* __restrict__ in, __half2* __restrict__ out, long long n4) {
    long long i = blockIdx.x * (long long)blockDim.x + threadIdx.x;
    if (i >= n4) return;
    float4 v = in[i];
    out[i * 2 + 0] = __floats2half2_rn(v.x, v.y);
    out[i * 2 + 1] = __floats2half2_rn(v.z, v.w);
}

// pack concat(W1,W2) transposed, k-pair interleaved
__global__ void wt_kernel(const float* __restrict__ W1, int K1,
                          const float* __restrict__ W2, int K2,
                          __half* __restrict__ WTp) {
    int k = blockIdx.x, h = threadIdx.x;
    float v = (k < K1) ? W1[h * K1 + k] : W2[h * K2 + (k - K1)];
    WTp[(size_t)(k >> 1) * 512 + h * 2 + (k & 1)] = __float2half_rn(v);
}

// ---------------- CSR build ----------------
__global__ void zero_int_kernel(int* p, int n) {
    int i = blockIdx.x * blockDim.x + threadIdx.x;
    if (i < n) p[i] = 0;
}

__global__ void hist_kernel(const int* __restrict__ src, const int* __restrict__ dst,
                            int* curS, int* curT, int E) {
    int e = blockIdx.x * blockDim.x + threadIdx.x;
    if (e < E) {
        atomicAdd(curT + dst[e], 1);
        atomicAdd(curS + src[e], 1);
    }
}

__global__ void __launch_bounds__(1024)
scan_kernel(const int* __restrict__ cnt, int* __restrict__ row, int n) {
    __shared__ int wsum[32];
    __shared__ int carry;
    int tid = threadIdx.x, lane = tid & 31, wid = tid >> 5;
    if (tid == 0) carry = 0;
    __syncthreads();
    for (int base = 0; base < n; base += 1024) {
        int v = (base + tid < n) ? cnt[base + tid] : 0;
        int x = v;
#pragma unroll
        for (int o = 1; o < 32; o <<= 1) {
            int t = __shfl_up_sync(0xffffffffu, x, o);
            if (lane >= o) x += t;
        }
        if (lane == 31) wsum[wid] = x;
        __syncthreads();
        if (wid == 0) {
            int y = wsum[lane];
#pragma unroll
            for (int o = 1; o < 32; o <<= 1) {
                int t = __shfl_up_sync(0xffffffffu, y, o);
                if (lane >= o) y += t;
            }
            wsum[lane] = y;
        }
        __syncthreads();
        int incl = x + (wid ? wsum[wid - 1] : 0) + carry;
        if (base + tid < n) row[base + tid] = incl - v;
        __syncthreads();
        if (tid == 1023) carry = incl;
        __syncthreads();
    }
    if (tid == 0) row[n] = carry;
}

__global__ void fill_kernel(const int* __restrict__ src, const int* __restrict__ dst,
                            const int* __restrict__ rowT, int* curT, int* adjT,
                            const int* __restrict__ rowS, int* curS, int* adjS, int E) {
    int e = blockIdx.x * blockDim.x + threadIdx.x;
    if (e >= E) return;
    int s = src[e], d = dst[e];
    int pT = __ldg(rowT + d) + atomicAdd(curT + d, 1);
    adjT[pT] = s;
    int pS = __ldg(rowS + s) + atomicAdd(curS + s, 1);
    adjS[pS] = d;
}

// ---------------- warp-per-node mean aggregation ----------------
__device__ __forceinline__ void agg256_body(const __half* __restrict__ feat,
                                            const int* __restrict__ rowp,
                                            const int* __restrict__ adj,
                                            __half* __restrict__ out, int node, int lane) {
    int s = __ldg(rowp + node), e = __ldg(rowp + node + 1);
    float acc[8] = {0.f, 0.f, 0.f, 0.f, 0.f, 0.f, 0.f, 0.f};
    const size_t lo = (size_t)lane * 8;
    int i = s;
    for (; i + 2 <= e; i += 2) {
        int n0 = __ldg(adj + i), n1 = __ldg(adj + i + 1);
        uint4 u0 = *(const uint4*)(feat + (size_t)n0 * 256 + lo);
        uint4 u1 = *(const uint4*)(feat + (size_t)n1 * 256 + lo);
        const __half2* h0 = (const __half2*)&u0;
        const __half2* h1 = (const __half2*)&u1;
#pragma unroll
        for (int j = 0; j < 4; j++) {
            float2 f0 = __half22float2(h0[j]);
            float2 f1 = __half22float2(h1[j]);
            acc[2 * j]     += f0.x + f1.x;
            acc[2 * j + 1] += f0.y + f1.y;
        }
    }
    if (i < e) {
        int n0 = __ldg(adj + i);
        uint4 u0 = *(const uint4*)(feat + (size_t)n0 * 256 + lo);
        const __half2* h0 = (const __half2*)&u0;
#pragma unroll
        for (int j = 0; j < 4; j++) {
            float2 f0 = __half22float2(h0[j]);
            acc[2 * j]     += f0.x;
            acc[2 * j + 1] += f0.y;
        }
    }
    float inv = 1.f / fmaxf((float)(e - s), 1.f);
    __half2 o[4];
#pragma unroll
    for (int j = 0; j < 4; j++)
        o[j] = __floats2half2_rn(acc[2 * j] * inv, acc[2 * j + 1] * inv);
    *(uint4*)(out + (size_t)node * 256 + lo) = *(uint4*)o;
}

__global__ void agg256_kernel(const __half* __restrict__ feat,
                              const int* __restrict__ rowp,
                              const int* __restrict__ adj,
                              __half* __restrict__ out, int nNodes) {
    int gw = (blockIdx.x * blockDim.x + threadIdx.x) >> 5;
    int lane = threadIdx.x & 31;
    if (gw >= nNodes) return;
    agg256_body(feat, rowp, adj, out, gw, lane);
}

// dual-segment agg256 (layer 2: taxon then sotu in one launch)
__global__ void agg256_dual(const __half* fA, const int* rA, const int* aA, __half* oA, int nA,
                            const __half* fB, const int* rB, const int* aB, __half* oB, int nB) {
    int gw = (blockIdx.x * blockDim.x + threadIdx.x) >> 5;
    int lane = threadIdx.x & 31;
    if (gw < nA) agg256_body(fA, rA, aA, oA, gw, lane);
    else if (gw < nA + nB) agg256_body(fB, rB, aB, oB, gw - nA, lane);
}

__global__ void agg128_kernel(const __half* __restrict__ feat,
                              const int* __restrict__ rowp,
                              const int* __restrict__ adj,
                              __half* __restrict__ out, int nNodes) {
    int gw = (blockIdx.x * blockDim.x + threadIdx.x) >> 5;
    int lane = threadIdx.x & 31;
    if (gw >= nNodes) return;
    int s = __ldg(rowp + gw), e = __ldg(rowp + gw + 1);
    float acc[4] = {0.f, 0.f, 0.f, 0.f};
    const size_t lo = (size_t)lane * 4;
    int i = s;
    for (; i + 2 <= e; i += 2) {
        int n0 = __ldg(adj + i), n1 = __ldg(adj + i + 1);
        uint2 u0 = *(const uint2*)(feat + (size_t)n0 * 128 + lo);
        uint2 u1 = *(const uint2*)(feat + (size_t)n1 * 128 + lo);
        const __half2* h0 = (const __half2*)&u0;
        const __half2* h1 = (const __half2*)&u1;
#pragma unroll
        for (int j = 0; j < 2; j++) {
            float2 f0 = __half22float2(h0[j]);
            float2 f1 = __half22float2(h1[j]);
            acc[2 * j]     += f0.x + f1.x;
            acc[2 * j + 1] += f0.y + f1.y;
        }
    }
    if (i < e) {
        int n0 = __ldg(adj + i);
        uint2 u0 = *(const uint2*)(feat + (size_t)n0 * 128 + lo);
        const __half2* h0 = (const __half2*)&u0;
#pragma unroll
        for (int j = 0; j < 2; j++) {
            float2 f0 = __half22float2(h0[j]);
            acc[2 * j]     += f0.x;
            acc[2 * j + 1] += f0.y;
        }
    }
    float inv = 1.f / fmaxf((float)(e - s), 1.f);
    __half2 o[2];
#pragma unroll
    for (int j = 0; j < 2; j++)
        o[j] = __floats2half2_rn(acc[2 * j] * inv, acc[2 * j + 1] * inv);
    *(uint2*)(out + (size_t)gw * 128 + lo) = *(uint2*)o;
}

// ---------------- fp16 HMMA GEMM machinery ----------------
#define AS_STRIDE 20
#define BS_STRIDE 264
#define A_STAGE_B (128*AS_STRIDE*4)
#define B_STAGE_B (16*BS_STRIDE*4)
#define STAGE_B   (A_STAGE_B + B_STAGE_B)
#define GEMM1_SMEM (4*STAGE_B)
#define H2_STRIDE 132                       // half2 units per h2-tile row
#define H2_TILE_B (128*H2_STRIDE*4)
#define GEMM2_SMEM (4*STAGE_B + H2_TILE_B)  // 176128 B

__device__ __forceinline__ void mma_f16(float* d, const uint32_t* a, const uint32_t* b) {
    asm volatile(
        "mma.sync.aligned.m16n8k16.row.col.f32.f16.f16.f32 "
        "{%0,%1,%2,%3}, {%4,%5,%6,%7}, {%8,%9}, {%0,%1,%2,%3};"
        : "+f"(d[0]), "+f"(d[1]), "+f"(d[2]), "+f"(d[3])
        : "r"(a[0]), "r"(a[1]), "r"(a[2]), "r"(a[3]), "r"(b[0]), "r"(b[1]));
}

// issue one A+B chunk into stage slot
__device__ __forceinline__ void issue_ab(uint32_t sbase, int c, int k0, int K1,
                                         const __half* A1, const __half* A2, int K2,
                                         const __half2* WTp, int bm, int Nrows, int tid) {
    int slot = c & 3;
    uint32_t aoff = sbase + slot * STAGE_B;
    uint32_t boff = aoff + A_STAGE_B;
    bool inA1 = (k0 < K1);
#pragma unroll
    for (int i = 0; i < 2; i++) {
        int idx = tid + i * 256;
        int row = idx >> 2, seg8 = (idx & 3) * 8;
        int grow = bm + row;
        bool ok = grow < Nrows;
        int gr = ok ? grow : 0;
        const __half* src = inA1 ? A1 + (size_t)gr * K1 + k0 + seg8
                                 : A2 + (size_t)gr * K2 + (k0 - K1) + seg8;
        uint32_t dst = aoff + (uint32_t)(row * (AS_STRIDE * 4) + seg8 * 2);
        int sz = ok ? 16 : 0;
        asm volatile("cp.async.cg.shared.global [%0], [%1], 16, %2;"
                     :: "r"(dst), "l"(src), "r"(sz));
    }
    int kp0 = k0 >> 1;
#pragma unroll
    for (int i = 0; i < 4; i++) {
        int idx = tid + i * 256;
        int kr = idx >> 6, seg = (idx & 63) * 4;
        const __half2* src = WTp + (size_t)(kp0 + kr) * 256 + seg;
        uint32_t dst = boff + (uint32_t)(kr * BS_STRIDE + seg) * 4;
        asm volatile("cp.async.cg.shared.global [%0], [%1], 16;"
                     :: "r"(dst), "l"(src));
    }
    asm volatile("cp.async.commit_group;");
}

// issue one B-only chunk (projection loop)
__device__ __forceinline__ void issue_b(uint32_t sbase, int c, const __half2* P, int tid) {
    int slot = c & 3;
    uint32_t boff = sbase + slot * STAGE_B + A_STAGE_B;
    int kp0 = c << 4;
#pragma unroll
    for (int i = 0; i < 4; i++) {
        int idx = tid + i * 256;
        int kr = idx >> 6, seg = (idx & 63) * 4;
        const __half2* src = P + (size_t)(kp0 + kr) * 256 + seg;
        uint32_t dst = boff + (uint32_t)(kr * BS_STRIDE + seg) * 4;
        asm volatile("cp.async.cg.shared.global [%0], [%1], 16;"
                     :: "r"(dst), "l"(src));
    }
    asm volatile("cp.async.commit_group;");
}

__device__ __forceinline__ void mma_chunk(const uint32_t* As, const uint32_t* Bs,
                                          int warpM, int warpN, int lrow, int lcol,
                                          float acc[4][8][4]) {
#pragma unroll
    for (int s = 0; s < 2; s++) {
        const int kp = s * 8 + lcol;
        uint32_t af[4][4];
#pragma unroll
        for (int mt = 0; mt < 4; mt++) {
            const int row = warpM * 64 + mt * 16 + lrow;
            af[mt][0] = As[row * AS_STRIDE + kp];
            af[mt][1] = As[(row + 8) * AS_STRIDE + kp];
            af[mt][2] = As[row * AS_STRIDE + kp + 4];
            af[mt][3] = As[(row + 8) * AS_STRIDE + kp + 4];
        }
        uint32_t bf[8][2];
#pragma unroll
        for (int nt = 0; nt < 8; nt++) {
            const int col = warpN * 64 + nt * 8 + lrow;
            bf[nt][0] = Bs[kp * BS_STRIDE + col];
            bf[nt][1] = Bs[(kp + 4) * BS_STRIDE + col];
        }
#pragma unroll
        for (int mt = 0; mt < 4; mt++)
#pragma unroll
            for (int nt = 0; nt < 8; nt++)
                mma_f16(acc[mt][nt], af[mt], bf[nt]);
    }
}

// ---------------- layer-1 GEMM: dual segment, relu epilogue ----------------
__global__ void __launch_bounds__(256)
gemm_l1(const __half* aT1, int kT1, const __half* aT2, int kT2,
        const __half2* wT, const float* bT, __half* cT, int nT, int gridT,
        const __half* aS1, int kS1, const __half* aS2, int kS2,
        const __half2* wS, const float* bS, __half* cS, int nS) {
    extern __shared__ char sm[];
    const int tid = threadIdx.x;
    const int wid = tid >> 5, lane = tid & 31;
    const int warpM = wid >> 2, warpN = wid & 3;
    const int lrow = lane >> 2, lcol = lane & 3;

    const __half *A1, *A2; const __half2* W; const float* bias; __half* C;
    int K1, K2, Nrows, bm;
    if ((int)blockIdx.x < gridT) {
        A1 = aT1; K1 = kT1; A2 = aT2; K2 = kT2; W = wT; bias = bT; C = cT; Nrows = nT;
        bm = blockIdx.x * 128;
    } else {
        A1 = aS1; K1 = kS1; A2 = aS2; K2 = kS2; W = wS; bias = bS; C = cS; Nrows = nS;
        bm = (blockIdx.x - gridT) * 128;
    }
    const int nch = (K1 + K2) >> 5;

    uint32_t sbase = (uint32_t)__cvta_generic_to_shared(sm);

    float2 bv[8];
#pragma unroll
    for (int nt = 0; nt < 8; nt++) {
        int col = warpN * 64 + nt * 8 + 2 * lcol;
        bv[nt].x = __ldg(bias + col); bv[nt].y = __ldg(bias + col + 1);
    }

    float acc[4][8][4];
#pragma unroll
    for (int i = 0; i < 4; i++)
#pragma unroll
        for (int j = 0; j < 8; j++)
#pragma unroll
            for (int q = 0; q < 4; q++) acc[i][j][q] = 0.f;

    issue_ab(sbase, 0, 0, K1, A1, A2, K2, W, bm, Nrows, tid);
    issue_ab(sbase, 1, 32, K1, A1, A2, K2, W, bm, Nrows, tid);
    issue_ab(sbase, 2, 64, K1, A1, A2, K2, W, bm, Nrows, tid);

    for (int c = 0; c < nch; c++) {
        asm volatile("cp.async.wait_group 2;");
        __syncthreads();
        if (c + 3 < nch) issue_ab(sbase, c + 3, (c + 3) << 5, K1, A1, A2, K2, W, bm, Nrows, tid);
        else asm volatile("cp.async.commit_group;");
        int slot = c & 3;
        const uint32_t* As = (const uint32_t*)(sm + slot * STAGE_B);
        const uint32_t* Bs = (const uint32_t*)(sm + slot * STAGE_B + A_STAGE_B);
        mma_chunk(As, Bs, warpM, warpN, lrow, lcol, acc);
    }

#pragma unroll
    for (int mt = 0; mt < 4; mt++) {
        const int r0 = bm + warpM * 64 + mt * 16 + lrow;
#pragma unroll
        for (int half = 0; half < 2; half++) {
            const int row = r0 + half * 8;
            if (row >= Nrows) continue;
#pragma unroll
            for (int nt = 0; nt < 8; nt++) {
                const int col = warpN * 64 + nt * 8 + 2 * lcol;
                float vx = fmaxf(acc[mt][nt][half * 2 + 0] + bv[nt].x, 0.f);
                float vy = fmaxf(acc[mt][nt][half * 2 + 1] + bv[nt].y, 0.f);
                *(__half2*)(C + (size_t)row * 256 + col) = __floats2half2_rn(vx, vy);
            }
        }
    }
}

// ---------------- layer-2 GEMM + fused projection: dual segment ----------------
// mainloop: h2 = relu(concat(agg,h1) @ W2T + b2)  (kept in smem, never written to gmem)
// proj:     u  = h2 @ PcT                           (written half)
__global__ void __launch_bounds__(256)
gemm_l2p(const __half* aT1, const __half* aT2, const __half2* wT, const float* bT,
         const __half2* pT, __half* uT, int nT, int gridT,
         const __half* aS1, const __half* aS2, const __half2* wS, const float* bS,
         const __half2* pS, __half* uS, int nS) {
    extern __shared__ char sm[];
    const int tid = threadIdx.x;
    const int wid = tid >> 5, lane = tid & 31;
    const int warpM = wid >> 2, warpN = wid & 3;
    const int lrow = lane >> 2, lcol = lane & 3;

    const __half *A1, *A2; const __half2 *W, *P; const float* bias; __half* U;
    int Nrows, bm;
    if ((int)blockIdx.x < gridT) {
        A1 = aT1; A2 = aT2; W = wT; bias = bT; P = pT; U = uT; Nrows = nT;
        bm = blockIdx.x * 128;
    } else {
        A1 = aS1; A2 = aS2; W = wS; bias = bS; P = pS; U = uS; Nrows = nS;
        bm = (blockIdx.x - gridT) * 128;
    }
    const int K1 = HID;           // agg part
    const int nch = 16;           // K = 512

    uint32_t sbase = (uint32_t)__cvta_generic_to_shared(sm);
    uint32_t* H2 = (uint32_t*)(sm + 4 * STAGE_B);   // [128][H2_STRIDE] half2

    float2 bv[8];
#pragma unroll
    for (int nt = 0; nt < 8; nt++) {
        int col = warpN * 64 + nt * 8 + 2 * lcol;
        bv[nt].x = __ldg(bias + col); bv[nt].y = __ldg(bias + col + 1);
    }

    float acc[4][8][4];
#pragma unroll
    for (int i = 0; i < 4; i++)
#pragma unroll
        for (int j = 0; j < 8; j++)
#pragma unroll
            for (int q = 0; q < 4; q++) acc[i][j][q] = 0.f;

    issue_ab(sbase, 0, 0, K1, A1, A2, HID, W, bm, Nrows, tid);
    issue_ab(sbase, 1, 32, K1, A1, A2, HID, W, bm, Nrows, tid);
    issue_ab(sbase, 2, 64, K1, A1, A2, HID, W, bm, Nrows, tid);

    for (int c = 0; c < nch; c++) {
        asm volatile("cp.async.wait_group 2;");
        __syncthreads();
        if (c + 3 < nch) issue_ab(sbase, c + 3, (c + 3) << 5, K1, A1, A2, HID, W, bm, Nrows, tid);
        else asm volatile("cp.async.commit_group;");
        int slot = c & 3;
        const uint32_t* As = (const uint32_t*)(sm + slot * STAGE_B);
        const uint32_t* Bs = (const uint32_t*)(sm + slot * STAGE_B + A_STAGE_B);
        mma_chunk(As, Bs, warpM, warpN, lrow, lcol, acc);
    }

    // ---- store h2 tile (bias+relu, half) into smem; re-zero acc ----
#pragma unroll
    for (int mt = 0; mt < 4; mt++) {
#pragma unroll
        for (int half = 0; half < 2; half++) {
            const int row = warpM * 64 + mt * 16 + lrow + half * 8;
#pragma unroll
            for (int nt = 0; nt < 8; nt++) {
                const int col2 = warpN * 32 + nt * 4 + lcol;
                float vx = fmaxf(acc[mt][nt][half * 2 + 0] + bv[nt].x, 0.f);
                float vy = fmaxf(acc[mt][nt][half * 2 + 1] + bv[nt].y, 0.f);
                __half2 hv = __floats2half2_rn(vx, vy);
                H2[row * H2_STRIDE + col2] = *(uint32_t*)&hv;
            }
        }
    }
#pragma unroll
    for (int i = 0; i < 4; i++)
#pragma unroll
        for (int j = 0; j < 8; j++)
#pragma unroll
            for (int q = 0; q < 4; q++) acc[i][j][q] = 0.f;
    __syncthreads();

    // ---- projection loop: u = h2 @ P (K=256, 8 chunks), A from H2 tile ----
    issue_b(sbase, 0, P, tid);
    issue_b(sbase, 1, P, tid);
    issue_b(sbase, 2, P, tid);

    for (int c = 0; c < 8; c++) {
        asm volatile("cp.async.wait_group 2;");
        __syncthreads();
        if (c + 3 < 8) issue_b(sbase, c + 3, P, tid);
        else asm volatile("cp.async.commit_group;");
        int slot = c & 3;
        const uint32_t* Bs = (const uint32_t*)(sm + slot * STAGE_B + A_STAGE_B);
#pragma unroll
        for (int s = 0; s < 2; s++) {
            const int kp = c * 16 + s * 8 + lcol;
            uint32_t af[4][4];
#pragma unroll
            for (int mt = 0; mt < 4; mt++) {
                const int row = warpM * 64 + mt * 16 + lrow;
                af[mt][0] = H2[row * H2_STRIDE + kp];
                af[mt][1] = H2[(row + 8) * H2_STRIDE + kp];
                af[mt][2] = H2[row * H2_STRIDE + kp + 4];
                af[mt][3] = H2[(row + 8) * H2_STRIDE + kp + 4];
            }
            const int kpl = s * 8 + lcol;
            uint32_t bf[8][2];
#pragma unroll
            for (int nt = 0; nt < 8; nt++) {
                const int col = warpN * 64 + nt * 8 + lrow;
                bf[nt][0] = Bs[kpl * BS_STRIDE + col];
                bf[nt][1] = Bs[(kpl + 4) * BS_STRIDE + col];
            }
#pragma unroll
            for (int mt = 0; mt < 4; mt++)
#pragma unroll
                for (int nt = 0; nt < 8; nt++)
                    mma_f16(acc[mt][nt], af[mt], bf[nt]);
        }
    }

    // ---- epilogue: write u (no bias/relu here; bias folded into bdc) ----
#pragma unroll
    for (int mt = 0; mt < 4; mt++) {
        const int r0 = bm + warpM * 64 + mt * 16 + lrow;
#pragma unroll
        for (int half = 0; half < 2; half++) {
            const int row = r0 + half * 8;
            if (row >= Nrows) continue;
#pragma unroll
            for (int nt = 0; nt < 8; nt++) {
                const int col = warpN * 64 + nt * 8 + 2 * lcol;
                *(__half2*)(U + (size_t)row * 256 + col) =
                    __floats2half2_rn(acc[mt][nt][half * 2 + 0], acc[mt][nt][half * 2 + 1]);
            }
        }
    }
}

// ---------------- weight composition (transposed, packed, half) ----------------
__global__ void compose_kernel(const float* __restrict__ Wd1,
                               const float* __restrict__ Wlin_s,
                               const float* __restrict__ Wlin_t,
                               const float* __restrict__ blin_s,
                               const float* __restrict__ blin_t,
                               const float* __restrict__ bd1,
                               __half* WcsT, __half* WctT, float* bdc) {
    int i = blockIdx.x;
    int m = threadIdx.x;
    float ss = 0.f, st = 0.f;
    for (int k = 0; k < HID; k++) {
        float wl = Wd1[i * 2 * HID + k];
        float wr = Wd1[i * 2 * HID + HID + k];
        ss += wl * Wlin_s[k * HID + m];
        st += wr * Wlin_t[k * HID + m];
    }
    size_t idx = (size_t)(m >> 1) * 512 + i * 2 + (m & 1);
    WcsT[idx] = __float2half_rn(ss);
    WctT[idx] = __float2half_rn(st);
    if (m == 0) {
        float b = bd1[i];
        for (int k = 0; k < HID; k++) {
            b += Wd1[i * 2 * HID + k] * blin_s[k];
            b += Wd1[i * 2 * HID + HID + k] * blin_t[k];
        }
        bdc[i] = b;
    }
}

// ---------------- decoder ----------------
__global__ void decode_kernel(const __half* __restrict__ us, const __half* __restrict__ ut,
                              const int* __restrict__ ls, const int* __restrict__ ld,
                              const float4* __restrict__ bdc, const float4* __restrict__ wd2,
                              const float* __restrict__ bd2,
                              float* __restrict__ out, int EL) {
    int g = blockIdx.x * blockDim.x + threadIdx.x;
    int w = g >> 5, lane = g & 31;
    if (w >= EL) return;
    const uint4* a = (const uint4*)(us + (size_t)__ldg(ls + w) * HID);
    const uint4* b = (const uint4*)(ut + (size_t)__ldg(ld + w) * HID);
    uint4 ua = a[lane], ub = b[lane];
    float4 c0 = bdc[lane * 2], c1 = bdc[lane * 2 + 1];
    float4 w0 = wd2[lane * 2], w1 = wd2[lane * 2 + 1];
    float2 a0 = __half22float2(*(__half2*)&ua.x), b0 = __half22float2(*(__half2*)&ub.x);
    float2 a1 = __half22float2(*(__half2*)&ua.y), b1 = __half22float2(*(__half2*)&ub.y);
    float2 a2 = __half22float2(*(__half2*)&ua.z), b2 = __half22float2(*(__half2*)&ub.z);
    float2 a3 = __half22float2(*(__half2*)&ua.w), b3 = __half22float2(*(__half2*)&ub.w);
    float sum =
        fmaxf(a0.x + b0.x + c0.x, 0.f) * w0.x + fmaxf(a0.y + b0.y + c0.y, 0.f) * w0.y +
        fmaxf(a1.x + b1.x + c0.z, 0.f) * w0.z + fmaxf(a1.y + b1.y + c0.w, 0.f) * w0.w +
        fmaxf(a2.x + b2.x + c1.x, 0.f) * w1.x + fmaxf(a2.y + b2.y + c1.y, 0.f) * w1.y +
        fmaxf(a3.x + b3.x + c1.z, 0.f) * w1.z + fmaxf(a3.y + b3.y + c1.w, 0.f) * w1.w;
#pragma unroll
    for (int o = 16; o; o >>= 1) sum += __shfl_xor_sync(0xffffffffu, sum, o);
    if (lane == 0) out[w] = sum + bd2[0];
}

// ---------------- launcher ----------------
extern "C" void kernel_launch(void* const* d_in, const int* in_sizes, int n_in,
                              void* d_out, int out_size) {
    const float* x_sotu  = (const float*)d_in[0];
    const float* x_taxon = (const float*)d_in[1];
    const int*   esrc    = (const int*)d_in[2];
    const int*   edst    = (const int*)d_in[3];
    const int*   lsrc    = (const int*)d_in[4];
    const int*   ldst    = (const int*)d_in[5];
    const float* Wl1_st  = (const float*)d_in[6];
    const float* bl1_st  = (const float*)d_in[7];
    const float* Wr1_st  = (const float*)d_in[8];
    const float* Wl1_ts  = (const float*)d_in[9];
    const float* bl1_ts  = (const float*)d_in[10];
    const float* Wr1_ts  = (const float*)d_in[11];
    const float* Wl2_st  = (const float*)d_in[12];
    const float* bl2_st  = (const float*)d_in[13];
    const float* Wr2_st  = (const float*)d_in[14];
    const float* Wl2_ts  = (const float*)d_in[15];
    const float* bl2_ts  = (const float*)d_in[16];
    const float* Wr2_ts  = (const float*)d_in[17];
    const float* Wlin_s  = (const float*)d_in[18];
    const float* blin_s  = (const float*)d_in[19];
    const float* Wlin_t  = (const float*)d_in[20];
    const float* blin_t  = (const float*)d_in[21];
    const float* Wd1     = (const float*)d_in[22];
    const float* bd1     = (const float*)d_in[23];
    const float* Wd2     = (const float*)d_in[24];
    const float* bd2     = (const float*)d_in[25];
    float* out = (float*)d_out;

    float *bdc;
    __half *aggTh, *aggSh, *h1t, *h1s, *us, *ut;
    __half *xrs, *xrt, *wt1st, *wt1ts, *wt2st, *wt2ts, *wcsT, *wctT;
    int *rowT, *rowS, *curT, *curS, *adjT, *adjS;
    cudaGetSymbolAddress((void**)&aggTh, g_aggTh);
    cudaGetSymbolAddress((void**)&aggSh, g_aggSh);
    cudaGetSymbolAddress((void**)&h1t, g_h1t);
    cudaGetSymbolAddress((void**)&h1s, g_h1s);
    cudaGetSymbolAddress((void**)&us,  g_us);
    cudaGetSymbolAddress((void**)&ut,  g_ut);
    cudaGetSymbolAddress((void**)&xrs, g_xr_s);
    cudaGetSymbolAddress((void**)&xrt, g_xr_t);
    cudaGetSymbolAddress((void**)&wt1st, g_wt1_st);
    cudaGetSymbolAddress((void**)&wt1ts, g_wt1_ts);
    cudaGetSymbolAddress((void**)&wt2st, g_wt2_st);
    cudaGetSymbolAddress((void**)&wt2ts, g_wt2_ts);
    cudaGetSymbolAddress((void**)&wcsT, g_wcsT);
    cudaGetSymbolAddress((void**)&wctT, g_wctT);
    cudaGetSymbolAddress((void**)&bdc, g_bdc);
    cudaGetSymbolAddress((void**)&rowT, g_rowT);
    cudaGetSymbolAddress((void**)&rowS, g_rowS);
    cudaGetSymbolAddress((void**)&curT, g_curT);
    cudaGetSymbolAddress((void**)&curS, g_curS);
    cudaGetSymbolAddress((void**)&adjT, g_adjT);
    cudaGetSymbolAddress((void**)&adjS, g_adjS);

    static int smem_set = 0;
    if (!smem_set) {
        cudaFuncSetAttribute(gemm_l1, cudaFuncAttributeMaxDynamicSharedMemorySize, GEMM1_SMEM);
        cudaFuncSetAttribute(gemm_l2p, cudaFuncAttributeMaxDynamicSharedMemorySize, GEMM2_SMEM);
        smem_set = 1;
    }

    const int gT = (N_TAXON + 127) / 128;   // 157
    const int gS = (N_SOTU + 127) / 128;    // 782
    const unsigned wT = (N_TAXON * 32 + 255) / 256;
    const unsigned wS = (N_SOTU * 32 + 255) / 256;

    // ---- prep ----
    long long nxs4 = (long long)N_SOTU * DS / 4, nxt4 = (long long)N_TAXON * DT / 4;
    tohalf_kernel<<<(unsigned)((nxs4 + 255) / 256), 256>>>((const float4*)x_sotu, (__half2*)xrs, nxs4);
    tohalf_kernel<<<(unsigned)((nxt4 + 255) / 256), 256>>>((const float4*)x_taxon, (__half2*)xrt, nxt4);
    wt_kernel<<<384, 256>>>(Wl1_st, DS, Wr1_st, DT, wt1st);
    wt_kernel<<<384, 256>>>(Wl1_ts, DT, Wr1_ts, DS, wt1ts);
    wt_kernel<<<512, 256>>>(Wl2_st, HID, Wr2_st, HID, wt2st);
    wt_kernel<<<512, 256>>>(Wl2_ts, HID, Wr2_ts, HID, wt2ts);
    compose_kernel<<<HID, HID>>>(Wd1, Wlin_s, Wlin_t, blin_s, blin_t, bd1, wcsT, wctT, bdc);

    // ---- CSR build ----
    zero_int_kernel<<<(N_TAXON + 255) / 256, 256>>>(curT, N_TAXON);
    zero_int_kernel<<<(N_SOTU + 255) / 256, 256>>>(curS, N_SOTU);
    hist_kernel<<<(NE + 255) / 256, 256>>>(esrc, edst, curS, curT, NE);
    scan_kernel<<<1, 1024>>>(curT, rowT, N_TAXON);
    scan_kernel<<<1, 1024>>>(curS, rowS, N_SOTU);
    zero_int_kernel<<<(N_TAXON + 255) / 256, 256>>>(curT, N_TAXON);
    zero_int_kernel<<<(N_SOTU + 255) / 256, 256>>>(curS, N_SOTU);
    fill_kernel<<<(NE + 255) / 256, 256>>>(esrc, edst, rowT, curT, adjT, rowS, curS, adjS, NE);

    // ---- layer 1 ----
    agg256_kernel<<<wT, 256>>>(xrs, rowT, adjT, aggTh, N_TAXON);
    agg128_kernel<<<wS, 256>>>(xrt, rowS, adjS, aggSh, N_SOTU);

    gemm_l1<<<(unsigned)(gT + gS), 256, GEMM1_SMEM>>>(
        aggTh, DS, xrt, DT, (const __half2*)wt1st, bl1_st, h1t, N_TAXON, gT,
        aggSh, DT, xrs, DS, (const __half2*)wt1ts, bl1_ts, h1s, N_SOTU);

    // ---- layer 2 (agg merged; GEMM + projection fused) ----
    agg256_dual<<<(unsigned)(wT + wS), 256>>>(
        h1s, rowT, adjT, aggTh, N_TAXON,
        h1t, rowS, adjS, aggSh, N_SOTU);

    gemm_l2p<<<(unsigned)(gT + gS), 256, GEMM2_SMEM>>>(
        aggTh, h1t, (const __half2*)wt2st, bl2_st, (const __half2*)wctT, ut, N_TAXON, gT,
        aggSh, h1s, (const __half2*)wt2ts, bl2_ts, (const __half2*)wcsT, us, N_SOTU);

    // ---- decoder ----
    decode_kernel<<<(NEL * 32 + 255) / 256, 256>>>(
        us, ut, lsrc, ldst,
        (const float4*)bdc, (const float4*)Wd2, bd2, out, NEL);
}

// round 8
// speedup vs baseline: 5.2640x; 1.0734x over previous
#include <cuda_runtime.h>
#include <cuda_fp16.h>
#include <cstdint>

#define N_SOTU  100000
#define N_TAXON 20000
#define NE      800000
#define NEL     200000
#define DS      256
#define DT      128
#define HID     256

#define WROW 264   // halves per weight row (256 data + 8 pad), k-major

// ---------------- scratch (device globals; no allocation) ----------------
__device__ __align__(128) __half g_aggTh[(size_t)N_TAXON*HID];
__device__ __align__(128) __half g_aggSh[(size_t)N_SOTU*HID];
__device__ __align__(128) __half g_h1t[(size_t)N_TAXON*HID];
__device__ __align__(128) __half g_h1s[(size_t)N_SOTU*HID];
__device__ __align__(128) __half g_us[(size_t)N_SOTU*HID];
__device__ __align__(128) __half g_ut[(size_t)N_TAXON*HID];
__device__ __align__(128) __half g_xr_s[(size_t)N_SOTU*DS];
__device__ __align__(128) __half g_xr_t[(size_t)N_TAXON*DT];
__device__ __align__(128) __half g_wt1_st[384*WROW];
__device__ __align__(128) __half g_wt1_ts[384*WROW];
__device__ __align__(128) __half g_wt2_st[512*WROW];
__device__ __align__(128) __half g_wt2_ts[512*WROW];
__device__ __align__(128) __half g_wcsT[256*WROW];
__device__ __align__(128) __half g_wctT[256*WROW];
__device__ __align__(128) float  g_bdc[256];
// CSR
__device__ int g_rowT[N_TAXON + 1];
__device__ int g_rowS[N_SOTU + 1];
__device__ int g_curT[N_TAXON];
__device__ int g_curS[N_SOTU];
__device__ int g_adjT[NE];
__device__ int g_adjS[NE];

// ---------------- prep kernels ----------------
// dual tohalf: seg A = x_sotu, seg B = x_taxon
__global__ void tohalf_dual(const float4* inA, __half2* outA, long long nA4,
                            const float4* inB, __half2* outB, long long nB4) {
    long long i = blockIdx.x * (long long)blockDim.x + threadIdx.x;
    const float4* in; __half2* out; long long idx;
    if (i < nA4) { in = inA; out = outA; idx = i; }
    else if (i - nA4 < nB4) { in = inB; out = outB; idx = i - nA4; }
    else return;
    float4 v = in[idx];
    out[idx * 2 + 0] = __floats2half2_rn(v.x, v.y);
    out[idx * 2 + 1] = __floats2half2_rn(v.z, v.w);
}

// all 4 weight packs in one launch; k-major output [k][WROW]
__global__ void wt_all(const float* W1a, const float* W2a, __half* Oa,   // 384 rows (K1=256,K2=128)
                       const float* W1b, const float* W2b, __half* Ob,   // 384 rows (K1=128,K2=256)
                       const float* W1c, const float* W2c, __half* Oc,   // 512
                       const float* W1d, const float* W2d, __half* Od) { // 512
    int b = blockIdx.x, h = threadIdx.x;
    const float* W1; const float* W2; __half* O; int K1, K2, k;
    if (b < 384)        { W1 = W1a; W2 = W2a; O = Oa; K1 = 256; K2 = 128; k = b; }
    else if (b < 768)   { W1 = W1b; W2 = W2b; O = Ob; K1 = 128; K2 = 256; k = b - 384; }
    else if (b < 1280)  { W1 = W1c; W2 = W2c; O = Oc; K1 = 256; K2 = 256; k = b - 768; }
    else                { W1 = W1d; W2 = W2d; O = Od; K1 = 256; K2 = 256; k = b - 1280; }
    float v = (k < K1) ? W1[h * K1 + k] : W2[h * K2 + (k - K1)];
    O[(size_t)k * WROW + h] = __float2half_rn(v);
}

// ---------------- CSR build ----------------
__global__ void zero_dual(int* a, int na, int* b, int nb) {
    int i = blockIdx.x * blockDim.x + threadIdx.x;
    if (i < na) a[i] = 0;
    if (i < nb) b[i] = 0;
}

__global__ void hist_kernel(const int* __restrict__ src, const int* __restrict__ dst,
                            int* curS, int* curT, int E) {
    int e = blockIdx.x * blockDim.x + threadIdx.x;
    if (e < E) {
        atomicAdd(curT + dst[e], 1);
        atomicAdd(curS + src[e], 1);
    }
}

// dual exclusive scan: block 0 -> (cntA,rowA), block 1 -> (cntB,rowB); zeros cnt after read
__global__ void __launch_bounds__(1024)
scan_dual(int* cntA, int* rowA, int nA, int* cntB, int* rowB, int nB) {
    int* cnt = blockIdx.x ? cntB : cntA;
    int* row = blockIdx.x ? rowB : rowA;
    int n = blockIdx.x ? nB : nA;
    __shared__ int wsum[32];
    __shared__ int carry;
    int tid = threadIdx.x, lane = tid & 31, wid = tid >> 5;
    if (tid == 0) carry = 0;
    __syncthreads();
    for (int base = 0; base < n; base += 1024) {
        int v = (base + tid < n) ? cnt[base + tid] : 0;
        int x = v;
#pragma unroll
        for (int o = 1; o < 32; o <<= 1) {
            int t = __shfl_up_sync(0xffffffffu, x, o);
            if (lane >= o) x += t;
        }
        if (lane == 31) wsum[wid] = x;
        __syncthreads();
        if (wid == 0) {
            int y = wsum[lane];
#pragma unroll
            for (int o = 1; o < 32; o <<= 1) {
                int t = __shfl_up_sync(0xffffffffu, y, o);
                if (lane >= o) y += t;
            }
            wsum[lane] = y;
        }
        __syncthreads();
        int incl = x + (wid ? wsum[wid - 1] : 0) + carry;
        if (base + tid < n) { row[base + tid] = incl - v; cnt[base + tid] = 0; }
        __syncthreads();
        if (tid == 1023) carry = incl;
        __syncthreads();
    }
    if (tid == 0) row[n] = carry;
}

__global__ void fill_kernel(const int* __restrict__ src, const int* __restrict__ dst,
                            const int* __restrict__ rowT, int* curT, int* adjT,
                            const int* __restrict__ rowS, int* curS, int* adjS, int E) {
    int e = blockIdx.x * blockDim.x + threadIdx.x;
    if (e >= E) return;
    int s = src[e], d = dst[e];
    int pT = __ldg(rowT + d) + atomicAdd(curT + d, 1);
    adjT[pT] = s;
    int pS = __ldg(rowS + s) + atomicAdd(curS + s, 1);
    adjS[pS] = d;
}

// ---------------- warp-per-node mean aggregation ----------------
__device__ __forceinline__ void agg256_body(const __half* __restrict__ feat,
                                            const int* __restrict__ rowp,
                                            const int* __restrict__ adj,
                                            __half* __restrict__ out, int node, int lane) {
    int s = __ldg(rowp + node), e = __ldg(rowp + node + 1);
    float acc[8] = {0.f, 0.f, 0.f, 0.f, 0.f, 0.f, 0.f, 0.f};
    const size_t lo = (size_t)lane * 8;
    int i = s;
    for (; i + 2 <= e; i += 2) {
        int n0 = __ldg(adj + i), n1 = __ldg(adj + i + 1);
        uint4 u0 = *(const uint4*)(feat + (size_t)n0 * 256 + lo);
        uint4 u1 = *(const uint4*)(feat + (size_t)n1 * 256 + lo);
        const __half2* h0 = (const __half2*)&u0;
        const __half2* h1 = (const __half2*)&u1;
#pragma unroll
        for (int j = 0; j < 4; j++) {
            float2 f0 = __half22float2(h0[j]);
            float2 f1 = __half22float2(h1[j]);
            acc[2 * j]     += f0.x + f1.x;
            acc[2 * j + 1] += f0.y + f1.y;
        }
    }
    if (i < e) {
        int n0 = __ldg(adj + i);
        uint4 u0 = *(const uint4*)(feat + (size_t)n0 * 256 + lo);
        const __half2* h0 = (const __half2*)&u0;
#pragma unroll
        for (int j = 0; j < 4; j++) {
            float2 f0 = __half22float2(h0[j]);
            acc[2 * j]     += f0.x;
            acc[2 * j + 1] += f0.y;
        }
    }
    float inv = 1.f / fmaxf((float)(e - s), 1.f);
    __half2 o[4];
#pragma unroll
    for (int j = 0; j < 4; j++)
        o[j] = __floats2half2_rn(acc[2 * j] * inv, acc[2 * j + 1] * inv);
    *(uint4*)(out + (size_t)node * 256 + lo) = *(uint4*)o;
}

__device__ __forceinline__ void agg128_body(const __half* __restrict__ feat,
                                            const int* __restrict__ rowp,
                                            const int* __restrict__ adj,
                                            __half* __restrict__ out, int node, int lane) {
    int s = __ldg(rowp + node), e = __ldg(rowp + node + 1);
    float acc[4] = {0.f, 0.f, 0.f, 0.f};
    const size_t lo = (size_t)lane * 4;
    int i = s;
    for (; i + 2 <= e; i += 2) {
        int n0 = __ldg(adj + i), n1 = __ldg(adj + i + 1);
        uint2 u0 = *(const uint2*)(feat + (size_t)n0 * 128 + lo);
        uint2 u1 = *(const uint2*)(feat + (size_t)n1 * 128 + lo);
        const __half2* h0 = (const __half2*)&u0;
        const __half2* h1 = (const __half2*)&u1;
#pragma unroll
        for (int j = 0; j < 2; j++) {
            float2 f0 = __half22float2(h0[j]);
            float2 f1 = __half22float2(h1[j]);
            acc[2 * j]     += f0.x + f1.x;
            acc[2 * j + 1] += f0.y + f1.y;
        }
    }
    if (i < e) {
        int n0 = __ldg(adj + i);
        uint2 u0 = *(const uint2*)(feat + (size_t)n0 * 128 + lo);
        const __half2* h0 = (const __half2*)&u0;
#pragma unroll
        for (int j = 0; j < 2; j++) {
            float2 f0 = __half22float2(h0[j]);
            acc[2 * j]     += f0.x;
            acc[2 * j + 1] += f0.y;
        }
    }
    float inv = 1.f / fmaxf((float)(e - s), 1.f);
    __half2 o[2];
#pragma unroll
    for (int j = 0; j < 2; j++)
        o[j] = __floats2half2_rn(acc[2 * j] * inv, acc[2 * j + 1] * inv);
    *(uint2*)(out + (size_t)node * 128 + lo) = *(uint2*)o;
}

// layer-1 agg: taxon(256-wide) then sotu(128-wide) in one launch
__global__ void agg_l1(const __half* fT, const int* rT, const int* aT, __half* oT, int nT,
                       const __half* fS, const int* rS, const int* aS, __half* oS, int nS) {
    int gw = (blockIdx.x * blockDim.x + threadIdx.x) >> 5;
    int lane = threadIdx.x & 31;
    if (gw < nT) agg256_body(fT, rT, aT, oT, gw, lane);
    else if (gw - nT < nS) agg128_body(fS, rS, aS, oS, gw - nT, lane);
}

// layer-2 agg: both 256-wide
__global__ void agg256_dual(const __half* fA, const int* rA, const int* aA, __half* oA, int nA,
                            const __half* fB, const int* rB, const int* aB, __half* oB, int nB) {
    int gw = (blockIdx.x * blockDim.x + threadIdx.x) >> 5;
    int lane = threadIdx.x & 31;
    if (gw < nA) agg256_body(fA, rA, aA, oA, gw, lane);
    else if (gw - nA < nB) agg256_body(fB, rB, aB, oB, gw - nA, lane);
}

// ---------------- fp16 HMMA GEMM machinery (ldmatrix fragments) ----------------
#define A_ROW_B 80                       // bytes per A smem row (32 halves + 8 pad)
#define B_ROW_B 528                      // bytes per B smem row (256 halves + 8 pad)
#define A_STAGE_B (128*A_ROW_B)          // 10240
#define B_STAGE_B (32*B_ROW_B)           // 16896
#define STAGE_B   (A_STAGE_B + B_STAGE_B)
#define GEMM1_SMEM (4*STAGE_B)
#define H2_ROW_B 528
#define H2_TILE_B (128*H2_ROW_B)
#define GEMM2_SMEM (4*STAGE_B + H2_TILE_B)

__device__ __forceinline__ void mma_f16(float* d, const uint32_t* a, const uint32_t* b) {
    asm volatile(
        "mma.sync.aligned.m16n8k16.row.col.f32.f16.f16.f32 "
        "{%0,%1,%2,%3}, {%4,%5,%6,%7}, {%8,%9}, {%0,%1,%2,%3};"
        : "+f"(d[0]), "+f"(d[1]), "+f"(d[2]), "+f"(d[3])
        : "r"(a[0]), "r"(a[1]), "r"(a[2]), "r"(a[3]), "r"(b[0]), "r"(b[1]));
}
__device__ __forceinline__ void ldm_x4(uint32_t* r, uint32_t addr) {
    asm volatile("ldmatrix.sync.aligned.m8n8.x4.shared.b16 {%0,%1,%2,%3}, [%4];"
        : "=r"(r[0]), "=r"(r[1]), "=r"(r[2]), "=r"(r[3]) : "r"(addr));
}
__device__ __forceinline__ void ldm_x4t(uint32_t* r, uint32_t addr) {
    asm volatile("ldmatrix.sync.aligned.m8n8.x4.trans.shared.b16 {%0,%1,%2,%3}, [%4];"
        : "=r"(r[0]), "=r"(r[1]), "=r"(r[2]), "=r"(r[3]) : "r"(addr));
}

// issue one A+B chunk (BK=32) into stage slot
__device__ __forceinline__ void issue_ab(uint32_t sbase, int c, int k0, int K1,
                                         const __half* A1, const __half* A2, int K2,
                                         const __half* WTk, int bm, int Nrows, int tid) {
    int slot = c & 3;
    uint32_t aoff = sbase + slot * STAGE_B;
    uint32_t boff = aoff + A_STAGE_B;
    bool inA1 = (k0 < K1);
#pragma unroll
    for (int i = 0; i < 2; i++) {
        int idx = tid + i * 256;
        int row = idx >> 2, seg8 = (idx & 3) * 8;
        int grow = bm + row;
        bool ok = grow < Nrows;
        int gr = ok ? grow : 0;
        const __half* src = inA1 ? A1 + (size_t)gr * K1 + k0 + seg8
                                 : A2 + (size_t)gr * K2 + (k0 - K1) + seg8;
        uint32_t dst = aoff + (uint32_t)(row * A_ROW_B + seg8 * 2);
        int sz = ok ? 16 : 0;
        asm volatile("cp.async.cg.shared.global [%0], [%1], 16, %2;"
                     :: "r"(dst), "l"(src), "r"(sz));
    }
#pragma unroll
    for (int i = 0; i < 4; i++) {
        int idx = tid + i * 256;
        int kr = idx >> 5, seg = idx & 31;       // 16B units along n
        const __half* src = WTk + (size_t)(k0 + kr) * WROW + seg * 8;
        uint32_t dst = boff + (uint32_t)(kr * B_ROW_B + seg * 16);
        asm volatile("cp.async.cg.shared.global [%0], [%1], 16;"
                     :: "r"(dst), "l"(src));
    }
    asm volatile("cp.async.commit_group;");
}

// issue one B-only chunk (projection loop)
__device__ __forceinline__ void issue_b(uint32_t sbase, int c, const __half* P, int tid) {
    int slot = c & 3;
    uint32_t boff = sbase + slot * STAGE_B + A_STAGE_B;
    int k0 = c << 5;
#pragma unroll
    for (int i = 0; i < 4; i++) {
        int idx = tid + i * 256;
        int kr = idx >> 5, seg = idx & 31;
        const __half* src = P + (size_t)(k0 + kr) * WROW + seg * 8;
        uint32_t dst = boff + (uint32_t)(kr * B_ROW_B + seg * 16);
        asm volatile("cp.async.cg.shared.global [%0], [%1], 16;"
                     :: "r"(dst), "l"(src));
    }
    asm volatile("cp.async.commit_group;");
}

// mainloop chunk: A/B fragments via ldmatrix
// aBase: lane-adjusted A base (this slot); bBase: lane-adjusted B base (this slot)
__device__ __forceinline__ void mma_chunk(uint32_t aBase, uint32_t bBase, float acc[4][8][4]) {
#pragma unroll
    for (int s = 0; s < 2; s++) {
        uint32_t af[4][4], bf[4][4];
#pragma unroll
        for (int mt = 0; mt < 4; mt++)
            ldm_x4(af[mt], aBase + mt * (16 * A_ROW_B) + s * 32);
#pragma unroll
        for (int p = 0; p < 4; p++)
            ldm_x4t(bf[p], bBase + s * (16 * B_ROW_B) + p * 32);
#pragma unroll
        for (int mt = 0; mt < 4; mt++)
#pragma unroll
            for (int p = 0; p < 4; p++) {
                mma_f16(acc[mt][2 * p],     af[mt], &bf[p][0]);
                mma_f16(acc[mt][2 * p + 1], af[mt], &bf[p][2]);
            }
    }
}

// ---------------- layer-1 GEMM: dual segment, relu epilogue ----------------
__global__ void __launch_bounds__(256)
gemm_l1(const __half* aT1, int kT1, const __half* aT2, int kT2,
        const __half* wT, const float* bT, __half* cT, int nT, int gridT,
        const __half* aS1, int kS1, const __half* aS2, int kS2,
        const __half* wS, const float* bS, __half* cS, int nS) {
    extern __shared__ char sm[];
    const int tid = threadIdx.x;
    const int wid = tid >> 5, lane = tid & 31;
    const int warpM = wid >> 2, warpN = wid & 3;
    const int lrow = lane >> 2, lcol = lane & 3;

    const __half *A1, *A2, *W; const float* bias; __half* C;
    int K1, K2, Nrows, bm;
    if ((int)blockIdx.x < gridT) {
        A1 = aT1; K1 = kT1; A2 = aT2; K2 = kT2; W = wT; bias = bT; C = cT; Nrows = nT;
        bm = blockIdx.x * 128;
    } else {
        A1 = aS1; K1 = kS1; A2 = aS2; K2 = kS2; W = wS; bias = bS; C = cS; Nrows = nS;
        bm = (blockIdx.x - gridT) * 128;
    }
    const int nch = (K1 + K2) >> 5;

    uint32_t sbase = (uint32_t)__cvta_generic_to_shared(sm);
    // lane-adjusted fragment bases (slot 0)
    const uint32_t aLane = (uint32_t)((warpM * 64 + (lane & 15)) * A_ROW_B + ((lane & 16) ? 16 : 0));
    const uint32_t bLane = (uint32_t)((lane & 15) * B_ROW_B + (warpN * 64 + ((lane & 16) ? 8 : 0)) * 2);

    float2 bv[8];
#pragma unroll
    for (int nt = 0; nt < 8; nt++) {
        int col = warpN * 64 + nt * 8 + 2 * lcol;
        bv[nt].x = __ldg(bias + col); bv[nt].y = __ldg(bias + col + 1);
    }

    float acc[4][8][4];
#pragma unroll
    for (int i = 0; i < 4; i++)
#pragma unroll
        for (int j = 0; j < 8; j++)
#pragma unroll
            for (int q = 0; q < 4; q++) acc[i][j][q] = 0.f;

    issue_ab(sbase, 0, 0, K1, A1, A2, K2, W, bm, Nrows, tid);
    issue_ab(sbase, 1, 32, K1, A1, A2, K2, W, bm, Nrows, tid);
    issue_ab(sbase, 2, 64, K1, A1, A2, K2, W, bm, Nrows, tid);

    for (int c = 0; c < nch; c++) {
        asm volatile("cp.async.wait_group 2;");
        __syncthreads();
        if (c + 3 < nch) issue_ab(sbase, c + 3, (c + 3) << 5, K1, A1, A2, K2, W, bm, Nrows, tid);
        else asm volatile("cp.async.commit_group;");
        int slot = c & 3;
        mma_chunk(sbase + slot * STAGE_B + aLane,
                  sbase + slot * STAGE_B + A_STAGE_B + bLane, acc);
    }

#pragma unroll
    for (int mt = 0; mt < 4; mt++) {
        const int r0 = bm + warpM * 64 + mt * 16 + lrow;
#pragma unroll
        for (int half = 0; half < 2; half++) {
            const int row = r0 + half * 8;
            if (row >= Nrows) continue;
#pragma unroll
            for (int nt = 0; nt < 8; nt++) {
                const int col = warpN * 64 + nt * 8 + 2 * lcol;
                float vx = fmaxf(acc[mt][nt][half * 2 + 0] + bv[nt].x, 0.f);
                float vy = fmaxf(acc[mt][nt][half * 2 + 1] + bv[nt].y, 0.f);
                *(__half2*)(C + (size_t)row * 256 + col) = __floats2half2_rn(vx, vy);
            }
        }
    }
}

// ---------------- layer-2 GEMM + fused projection: dual segment ----------------
__global__ void __launch_bounds__(256)
gemm_l2p(const __half* aT1, const __half* aT2, const __half* wT, const float* bT,
         const __half* pT, __half* uT, int nT, int gridT,
         const __half* aS1, const __half* aS2, const __half* wS, const float* bS,
         const __half* pS, __half* uS, int nS) {
    extern __shared__ char sm[];
    const int tid = threadIdx.x;
    const int wid = tid >> 5, lane = tid & 31;
    const int warpM = wid >> 2, warpN = wid & 3;
    const int lrow = lane >> 2, lcol = lane & 3;

    const __half *A1, *A2, *W, *P; const float* bias; __half* U;
    int Nrows, bm;
    if ((int)blockIdx.x < gridT) {
        A1 = aT1; A2 = aT2; W = wT; bias = bT; P = pT; U = uT; Nrows = nT;
        bm = blockIdx.x * 128;
    } else {
        A1 = aS1; A2 = aS2; W = wS; bias = bS; P = pS; U = uS; Nrows = nS;
        bm = (blockIdx.x - gridT) * 128;
    }
    const int K1 = HID;
    const int nch = 16;   // K = 512

    uint32_t sbase = (uint32_t)__cvta_generic_to_shared(sm);
    uint32_t* H2 = (uint32_t*)(sm + 4 * STAGE_B);
    const uint32_t h2base = sbase + 4 * STAGE_B;
    const uint32_t aLane = (uint32_t)((warpM * 64 + (lane & 15)) * A_ROW_B + ((lane & 16) ? 16 : 0));
    const uint32_t bLane = (uint32_t)((lane & 15) * B_ROW_B + (warpN * 64 + ((lane & 16) ? 8 : 0)) * 2);
    const uint32_t h2Lane = h2base + (uint32_t)((warpM * 64 + (lane & 15)) * H2_ROW_B + ((lane & 16) ? 16 : 0));

    float2 bv[8];
#pragma unroll
    for (int nt = 0; nt < 8; nt++) {
        int col = warpN * 64 + nt * 8 + 2 * lcol;
        bv[nt].x = __ldg(bias + col); bv[nt].y = __ldg(bias + col + 1);
    }

    float acc[4][8][4];
#pragma unroll
    for (int i = 0; i < 4; i++)
#pragma unroll
        for (int j = 0; j < 8; j++)
#pragma unroll
            for (int q = 0; q < 4; q++) acc[i][j][q] = 0.f;

    issue_ab(sbase, 0, 0, K1, A1, A2, HID, W, bm, Nrows, tid);
    issue_ab(sbase, 1, 32, K1, A1, A2, HID, W, bm, Nrows, tid);
    issue_ab(sbase, 2, 64, K1, A1, A2, HID, W, bm, Nrows, tid);

    for (int c = 0; c < nch; c++) {
        asm volatile("cp.async.wait_group 2;");
        __syncthreads();
        if (c + 3 < nch) issue_ab(sbase, c + 3, (c + 3) << 5, K1, A1, A2, HID, W, bm, Nrows, tid);
        else asm volatile("cp.async.commit_group;");
        int slot = c & 3;
        mma_chunk(sbase + slot * STAGE_B + aLane,
                  sbase + slot * STAGE_B + A_STAGE_B + bLane, acc);
    }

    // ---- store h2 tile (bias+relu, half) into smem; re-zero acc ----
#pragma unroll
    for (int mt = 0; mt < 4; mt++) {
#pragma unroll
        for (int half = 0; half < 2; half++) {
            const int row = warpM * 64 + mt * 16 + lrow + half * 8;
#pragma unroll
            for (int nt = 0; nt < 8; nt++) {
                const int col2 = warpN * 32 + nt * 4 + lcol;       // half2 units
                float vx = fmaxf(acc[mt][nt][half * 2 + 0] + bv[nt].x, 0.f);
                float vy = fmaxf(acc[mt][nt][half * 2 + 1] + bv[nt].y, 0.f);
                __half2 hv = __floats2half2_rn(vx, vy);
                H2[row * (H2_ROW_B / 4) + col2] = *(uint32_t*)&hv;
            }
        }
    }
#pragma unroll
    for (int i = 0; i < 4; i++)
#pragma unroll
        for (int j = 0; j < 8; j++)
#pragma unroll
            for (int q = 0; q < 4; q++) acc[i][j][q] = 0.f;
    __syncthreads();

    // ---- projection loop: u = h2 @ P (K=256, 8 chunks), A fragments from H2 tile ----
    issue_b(sbase, 0, P, tid);
    issue_b(sbase, 1, P, tid);
    issue_b(sbase, 2, P, tid);

    for (int c = 0; c < 8; c++) {
        asm volatile("cp.async.wait_group 2;");
        __syncthreads();
        if (c + 3 < 8) issue_b(sbase, c + 3, P, tid);
        else asm volatile("cp.async.commit_group;");
        int slot = c & 3;
        uint32_t bB = sbase + slot * STAGE_B + A_STAGE_B + bLane;
#pragma unroll
        for (int s = 0; s < 2; s++) {
            uint32_t af[4][4], bf[4][4];
#pragma unroll
            for (int mt = 0; mt < 4; mt++)
                ldm_x4(af[mt], h2Lane + mt * (16 * H2_ROW_B) + c * 64 + s * 32);
#pragma unroll
            for (int p = 0; p < 4; p++)
                ldm_x4t(bf[p], bB + s * (16 * B_ROW_B) + p * 32);
#pragma unroll
            for (int mt = 0; mt < 4; mt++)
#pragma unroll
                for (int p = 0; p < 4; p++) {
                    mma_f16(acc[mt][2 * p],     af[mt], &bf[p][0]);
                    mma_f16(acc[mt][2 * p + 1], af[mt], &bf[p][2]);
                }
        }
    }

    // ---- epilogue: write u ----
#pragma unroll
    for (int mt = 0; mt < 4; mt++) {
        const int r0 = bm + warpM * 64 + mt * 16 + lrow;
#pragma unroll
        for (int half = 0; half < 2; half++) {
            const int row = r0 + half * 8;
            if (row >= Nrows) continue;
#pragma unroll
            for (int nt = 0; nt < 8; nt++) {
                const int col = warpN * 64 + nt * 8 + 2 * lcol;
                *(__half2*)(U + (size_t)row * 256 + col) =
                    __floats2half2_rn(acc[mt][nt][half * 2 + 0], acc[mt][nt][half * 2 + 1]);
            }
        }
    }
}

// ---------------- weight composition (k-major half output) ----------------
__global__ void compose_kernel(const float* __restrict__ Wd1,
                               const float* __restrict__ Wlin_s,
                               const float* __restrict__ Wlin_t,
                               const float* __restrict__ blin_s,
                               const float* __restrict__ blin_t,
                               const float* __restrict__ bd1,
                               __half* WcsT, __half* WctT, float* bdc) {
    int i = blockIdx.x;      // output n
    int m = threadIdx.x;     // input k
    float ss = 0.f, st = 0.f;
    for (int k = 0; k < HID; k++) {
        float wl = Wd1[i * 2 * HID + k];
        float wr = Wd1[i * 2 * HID + HID + k];
        ss += wl * Wlin_s[k * HID + m];
        st += wr * Wlin_t[k * HID + m];
    }
    WcsT[(size_t)m * WROW + i] = __float2half_rn(ss);
    WctT[(size_t)m * WROW + i] = __float2half_rn(st);
    if (m == 0) {
        float b = bd1[i];
        for (int k = 0; k < HID; k++) {
            b += Wd1[i * 2 * HID + k] * blin_s[k];
            b += Wd1[i * 2 * HID + HID + k] * blin_t[k];
        }
        bdc[i] = b;
    }
}

// ---------------- decoder ----------------
__global__ void decode_kernel(const __half* __restrict__ us, const __half* __restrict__ ut,
                              const int* __restrict__ ls, const int* __restrict__ ld,
                              const float4* __restrict__ bdc, const float4* __restrict__ wd2,
                              const float* __restrict__ bd2,
                              float* __restrict__ out, int EL) {
    int g = blockIdx.x * blockDim.x + threadIdx.x;
    int w = g >> 5, lane = g & 31;
    if (w >= EL) return;
    const uint4* a = (const uint4*)(us + (size_t)__ldg(ls + w) * HID);
    const uint4* b = (const uint4*)(ut + (size_t)__ldg(ld + w) * HID);
    uint4 ua = a[lane], ub = b[lane];
    float4 c0 = bdc[lane * 2], c1 = bdc[lane * 2 + 1];
    float4 w0 = wd2[lane * 2], w1 = wd2[lane * 2 + 1];
    float2 a0 = __half22float2(*(__half2*)&ua.x), b0 = __half22float2(*(__half2*)&ub.x);
    float2 a1 = __half22float2(*(__half2*)&ua.y), b1 = __half22float2(*(__half2*)&ub.y);
    float2 a2 = __half22float2(*(__half2*)&ua.z), b2 = __half22float2(*(__half2*)&ub.z);
    float2 a3 = __half22float2(*(__half2*)&ua.w), b3 = __half22float2(*(__half2*)&ub.w);
    float sum =
        fmaxf(a0.x + b0.x + c0.x, 0.f) * w0.x + fmaxf(a0.y + b0.y + c0.y, 0.f) * w0.y +
        fmaxf(a1.x + b1.x + c0.z, 0.f) * w0.z + fmaxf(a1.y + b1.y + c0.w, 0.f) * w0.w +
        fmaxf(a2.x + b2.x + c1.x, 0.f) * w1.x + fmaxf(a2.y + b2.y + c1.y, 0.f) * w1.y +
        fmaxf(a3.x + b3.x + c1.z, 0.f) * w1.z + fmaxf(a3.y + b3.y + c1.w, 0.f) * w1.w;
#pragma unroll
    for (int o = 16; o; o >>= 1) sum += __shfl_xor_sync(0xffffffffu, sum, o);
    if (lane == 0) out[w] = sum + bd2[0];
}

// ---------------- launcher ----------------
extern "C" void kernel_launch(void* const* d_in, const int* in_sizes, int n_in,
                              void* d_out, int out_size) {
    const float* x_sotu  = (const float*)d_in[0];
    const float* x_taxon = (const float*)d_in[1];
    const int*   esrc    = (const int*)d_in[2];
    const int*   edst    = (const int*)d_in[3];
    const int*   lsrc    = (const int*)d_in[4];
    const int*   ldst    = (const int*)d_in[5];
    const float* Wl1_st  = (const float*)d_in[6];
    const float* bl1_st  = (const float*)d_in[7];
    const float* Wr1_st  = (const float*)d_in[8];
    const float* Wl1_ts  = (const float*)d_in[9];
    const float* bl1_ts  = (const float*)d_in[10];
    const float* Wr1_ts  = (const float*)d_in[11];
    const float* Wl2_st  = (const float*)d_in[12];
    const float* bl2_st  = (const float*)d_in[13];
    const float* Wr2_st  = (const float*)d_in[14];
    const float* Wl2_ts  = (const float*)d_in[15];
    const float* bl2_ts  = (const float*)d_in[16];
    const float* Wr2_ts  = (const float*)d_in[17];
    const float* Wlin_s  = (const float*)d_in[18];
    const float* blin_s  = (const float*)d_in[19];
    const float* Wlin_t  = (const float*)d_in[20];
    const float* blin_t  = (const float*)d_in[21];
    const float* Wd1     = (const float*)d_in[22];
    const float* bd1     = (const float*)d_in[23];
    const float* Wd2     = (const float*)d_in[24];
    const float* bd2     = (const float*)d_in[25];
    float* out = (float*)d_out;

    float *bdc;
    __half *aggTh, *aggSh, *h1t, *h1s, *us, *ut;
    __half *xrs, *xrt, *wt1st, *wt1ts, *wt2st, *wt2ts, *wcsT, *wctT;
    int *rowT, *rowS, *curT, *curS, *adjT, *adjS;
    cudaGetSymbolAddress((void**)&aggTh, g_aggTh);
    cudaGetSymbolAddress((void**)&aggSh, g_aggSh);
    cudaGetSymbolAddress((void**)&h1t, g_h1t);
    cudaGetSymbolAddress((void**)&h1s, g_h1s);
    cudaGetSymbolAddress((void**)&us,  g_us);
    cudaGetSymbolAddress((void**)&ut,  g_ut);
    cudaGetSymbolAddress((void**)&xrs, g_xr_s);
    cudaGetSymbolAddress((void**)&xrt, g_xr_t);
    cudaGetSymbolAddress((void**)&wt1st, g_wt1_st);
    cudaGetSymbolAddress((void**)&wt1ts, g_wt1_ts);
    cudaGetSymbolAddress((void**)&wt2st, g_wt2_st);
    cudaGetSymbolAddress((void**)&wt2ts, g_wt2_ts);
    cudaGetSymbolAddress((void**)&wcsT, g_wcsT);
    cudaGetSymbolAddress((void**)&wctT, g_wctT);
    cudaGetSymbolAddress((void**)&bdc, g_bdc);
    cudaGetSymbolAddress((void**)&rowT, g_rowT);
    cudaGetSymbolAddress((void**)&rowS, g_rowS);
    cudaGetSymbolAddress((void**)&curT, g_curT);
    cudaGetSymbolAddress((void**)&curS, g_curS);
    cudaGetSymbolAddress((void**)&adjT, g_adjT);
    cudaGetSymbolAddress((void**)&adjS, g_adjS);

    static int smem_set = 0;
    if (!smem_set) {
        cudaFuncSetAttribute(gemm_l1, cudaFuncAttributeMaxDynamicSharedMemorySize, GEMM1_SMEM);
        cudaFuncSetAttribute(gemm_l2p, cudaFuncAttributeMaxDynamicSharedMemorySize, GEMM2_SMEM);
        smem_set = 1;
    }

    const int gT = (N_TAXON + 127) / 128;   // 157
    const int gS = (N_SOTU + 127) / 128;    // 782
    const unsigned wAll = ((N_TAXON + N_SOTU) * 32 + 255) / 256;

    // ---- prep (3 launches) ----
    long long nxs4 = (long long)N_SOTU * DS / 4, nxt4 = (long long)N_TAXON * DT / 4;
    tohalf_dual<<<(unsigned)((nxs4 + nxt4 + 255) / 256), 256>>>(
        (const float4*)x_sotu, (__half2*)xrs, nxs4,
        (const float4*)x_taxon, (__half2*)xrt, nxt4);
    wt_all<<<1792, 256>>>(Wl1_st, Wr1_st, wt1st,
                          Wl1_ts, Wr1_ts, wt1ts,
                          Wl2_st, Wr2_st, wt2st,
                          Wl2_ts, Wr2_ts, wt2ts);
    compose_kernel<<<HID, HID>>>(Wd1, Wlin_s, Wlin_t, blin_s, blin_t, bd1, wcsT, wctT, bdc);

    // ---- CSR build (4 launches) ----
    zero_dual<<<(N_SOTU + 255) / 256, 256>>>(curT, N_TAXON, curS, N_SOTU);
    hist_kernel<<<(NE + 255) / 256, 256>>>(esrc, edst, curS, curT, NE);
    scan_dual<<<2, 1024>>>(curT, rowT, N_TAXON, curS, rowS, N_SOTU);
    fill_kernel<<<(NE + 255) / 256, 256>>>(esrc, edst, rowT, curT, adjT, rowS, curS, adjS, NE);

    // ---- layer 1 ----
    agg_l1<<<wAll, 256>>>(xrs, rowT, adjT, aggTh, N_TAXON,
                          xrt, rowS, adjS, aggSh, N_SOTU);
    gemm_l1<<<(unsigned)(gT + gS), 256, GEMM1_SMEM>>>(
        aggTh, DS, xrt, DT, wt1st, bl1_st, h1t, N_TAXON, gT,
        aggSh, DT, xrs, DS, wt1ts, bl1_ts, h1s, N_SOTU);

    // ---- layer 2 (agg merged; GEMM + projection fused) ----
    agg256_dual<<<wAll, 256>>>(h1s, rowT, adjT, aggTh, N_TAXON,
                               h1t, rowS, adjS, aggSh, N_SOTU);
    gemm_l2p<<<(unsigned)(gT + gS), 256, GEMM2_SMEM>>>(
        aggTh, h1t, wt2st, bl2_st, wctT, ut, N_TAXON, gT,
        aggSh, h1s, wt2ts, bl2_ts, wcsT, us, N_SOTU);

    // ---- decoder ----
    decode_kernel<<<(NEL * 32 + 255) / 256, 256>>>(
        us, ut, lsrc, ldst,
        (const float4*)bdc, (const float4*)Wd2, bd2, out, NEL);
}

// round 9
// speedup vs baseline: 5.7939x; 1.1007x over previous
#include <cuda_runtime.h>
#include <cuda_fp16.h>
#include <cstdint>

#define N_SOTU  100000
#define N_TAXON 20000
#define NE      800000
#define NEL     200000
#define DS      256
#define DT      128
#define HID     256

#define WROW 264   // halves per weight row (256 data + 8 pad), k-major

// ---------------- scratch (device globals; no allocation) ----------------
__device__ __align__(128) __half g_aggTh[(size_t)N_TAXON*HID];
__device__ __align__(128) __half g_aggSh[(size_t)N_SOTU*HID];
__device__ __align__(128) __half g_h1t[(size_t)N_TAXON*HID];
__device__ __align__(128) __half g_h1s[(size_t)N_SOTU*HID];
__device__ __align__(128) __half g_us[(size_t)N_SOTU*HID];
__device__ __align__(128) __half g_ut[(size_t)N_TAXON*HID];
__device__ __align__(128) __half g_xr_s[(size_t)N_SOTU*DS];
__device__ __align__(128) __half g_xr_t[(size_t)N_TAXON*DT];
__device__ __align__(128) __half g_wt1_st[384*WROW];
__device__ __align__(128) __half g_wt1_ts[384*WROW];
__device__ __align__(128) __half g_wt2_st[512*WROW];
__device__ __align__(128) __half g_wt2_ts[512*WROW];
__device__ __align__(128) __half g_wcsT[256*WROW];
__device__ __align__(128) __half g_wctT[256*WROW];
__device__ __align__(128) float  g_bdc[256];
// CSR
__device__ int g_rowT[N_TAXON + 1];
__device__ int g_rowS[N_SOTU + 1];
__device__ int g_curT[N_TAXON];
__device__ int g_curS[N_SOTU];
__device__ int g_adjT[NE];
__device__ int g_adjS[NE];

// ---------------- prep kernels ----------------
__global__ void tohalf_dual(const float4* inA, __half2* outA, long long nA4,
                            const float4* inB, __half2* outB, long long nB4) {
    long long i = blockIdx.x * (long long)blockDim.x + threadIdx.x;
    const float4* in; __half2* out; long long idx;
    if (i < nA4) { in = inA; out = outA; idx = i; }
    else if (i - nA4 < nB4) { in = inB; out = outB; idx = i - nA4; }
    else return;
    float4 v = in[idx];
    out[idx * 2 + 0] = __floats2half2_rn(v.x, v.y);
    out[idx * 2 + 1] = __floats2half2_rn(v.z, v.w);
}

__global__ void wt_all(const float* W1a, const float* W2a, __half* Oa,
                       const float* W1b, const float* W2b, __half* Ob,
                       const float* W1c, const float* W2c, __half* Oc,
                       const float* W1d, const float* W2d, __half* Od) {
    int b = blockIdx.x, h = threadIdx.x;
    const float* W1; const float* W2; __half* O; int K1, K2, k;
    if (b < 384)        { W1 = W1a; W2 = W2a; O = Oa; K1 = 256; K2 = 128; k = b; }
    else if (b < 768)   { W1 = W1b; W2 = W2b; O = Ob; K1 = 128; K2 = 256; k = b - 384; }
    else if (b < 1280)  { W1 = W1c; W2 = W2c; O = Oc; K1 = 256; K2 = 256; k = b - 768; }
    else                { W1 = W1d; W2 = W2d; O = Od; K1 = 256; K2 = 256; k = b - 1280; }
    float v = (k < K1) ? W1[h * K1 + k] : W2[h * K2 + (k - K1)];
    O[(size_t)k * WROW + h] = __float2half_rn(v);
}

// ---------------- CSR build ----------------
__global__ void zero_dual(int* a, int na, int* b, int nb) {
    int i = blockIdx.x * blockDim.x + threadIdx.x;
    if (i < na) a[i] = 0;
    if (i < nb) b[i] = 0;
}

__global__ void hist_kernel(const int* __restrict__ src, const int* __restrict__ dst,
                            int* curS, int* curT, int E) {
    int e = blockIdx.x * blockDim.x + threadIdx.x;
    if (e < E) {
        atomicAdd(curT + dst[e], 1);
        atomicAdd(curS + src[e], 1);
    }
}

__global__ void __launch_bounds__(1024)
scan_dual(int* cntA, int* rowA, int nA, int* cntB, int* rowB, int nB) {
    int* cnt = blockIdx.x ? cntB : cntA;
    int* row = blockIdx.x ? rowB : rowA;
    int n = blockIdx.x ? nB : nA;
    __shared__ int wsum[32];
    __shared__ int carry;
    int tid = threadIdx.x, lane = tid & 31, wid = tid >> 5;
    if (tid == 0) carry = 0;
    __syncthreads();
    for (int base = 0; base < n; base += 1024) {
        int v = (base + tid < n) ? cnt[base + tid] : 0;
        int x = v;
#pragma unroll
        for (int o = 1; o < 32; o <<= 1) {
            int t = __shfl_up_sync(0xffffffffu, x, o);
            if (lane >= o) x += t;
        }
        if (lane == 31) wsum[wid] = x;
        __syncthreads();
        if (wid == 0) {
            int y = wsum[lane];
#pragma unroll
            for (int o = 1; o < 32; o <<= 1) {
                int t = __shfl_up_sync(0xffffffffu, y, o);
                if (lane >= o) y += t;
            }
            wsum[lane] = y;
        }
        __syncthreads();
        int incl = x + (wid ? wsum[wid - 1] : 0) + carry;
        if (base + tid < n) { row[base + tid] = incl - v; cnt[base + tid] = 0; }
        __syncthreads();
        if (tid == 1023) carry = incl;
        __syncthreads();
    }
    if (tid == 0) row[n] = carry;
}

__global__ void fill_kernel(const int* __restrict__ src, const int* __restrict__ dst,
                            const int* __restrict__ rowT, int* curT, int* adjT,
                            const int* __restrict__ rowS, int* curS, int* adjS, int E) {
    int e = blockIdx.x * blockDim.x + threadIdx.x;
    if (e >= E) return;
    int s = src[e], d = dst[e];
    int pT = __ldg(rowT + d) + atomicAdd(curT + d, 1);
    adjT[pT] = s;
    int pS = __ldg(rowS + s) + atomicAdd(curS + s, 1);
    adjS[pS] = d;
}

// ---------------- warp-per-node mean aggregation ----------------
__global__ void agg256_kernel(const __half* __restrict__ feat,
                              const int* __restrict__ rowp,
                              const int* __restrict__ adj,
                              __half* __restrict__ out, int nNodes) {
    int gw = (blockIdx.x * blockDim.x + threadIdx.x) >> 5;
    int lane = threadIdx.x & 31;
    if (gw >= nNodes) return;
    int s = __ldg(rowp + gw), e = __ldg(rowp + gw + 1);
    float acc[8] = {0.f, 0.f, 0.f, 0.f, 0.f, 0.f, 0.f, 0.f};
    const size_t lo = (size_t)lane * 8;
    int i = s;
    for (; i + 2 <= e; i += 2) {
        int n0 = __ldg(adj + i), n1 = __ldg(adj + i + 1);
        uint4 u0 = *(const uint4*)(feat + (size_t)n0 * 256 + lo);
        uint4 u1 = *(const uint4*)(feat + (size_t)n1 * 256 + lo);
        const __half2* h0 = (const __half2*)&u0;
        const __half2* h1 = (const __half2*)&u1;
#pragma unroll
        for (int j = 0; j < 4; j++) {
            float2 f0 = __half22float2(h0[j]);
            float2 f1 = __half22float2(h1[j]);
            acc[2 * j]     += f0.x + f1.x;
            acc[2 * j + 1] += f0.y + f1.y;
        }
    }
    if (i < e) {
        int n0 = __ldg(adj + i);
        uint4 u0 = *(const uint4*)(feat + (size_t)n0 * 256 + lo);
        const __half2* h0 = (const __half2*)&u0;
#pragma unroll
        for (int j = 0; j < 4; j++) {
            float2 f0 = __half22float2(h0[j]);
            acc[2 * j]     += f0.x;
            acc[2 * j + 1] += f0.y;
        }
    }
    float inv = 1.f / fmaxf((float)(e - s), 1.f);
    __half2 o[4];
#pragma unroll
    for (int j = 0; j < 4; j++)
        o[j] = __floats2half2_rn(acc[2 * j] * inv, acc[2 * j + 1] * inv);
    *(uint4*)(out + (size_t)gw * 256 + lo) = *(uint4*)o;
}

__global__ void agg128_kernel(const __half* __restrict__ feat,
                              const int* __restrict__ rowp,
                              const int* __restrict__ adj,
                              __half* __restrict__ out, int nNodes) {
    int gw = (blockIdx.x * blockDim.x + threadIdx.x) >> 5;
    int lane = threadIdx.x & 31;
    if (gw >= nNodes) return;
    int s = __ldg(rowp + gw), e = __ldg(rowp + gw + 1);
    float acc[4] = {0.f, 0.f, 0.f, 0.f};
    const size_t lo = (size_t)lane * 4;
    int i = s;
    for (; i + 2 <= e; i += 2) {
        int n0 = __ldg(adj + i), n1 = __ldg(adj + i + 1);
        uint2 u0 = *(const uint2*)(feat + (size_t)n0 * 128 + lo);
        uint2 u1 = *(const uint2*)(feat + (size_t)n1 * 128 + lo);
        const __half2* h0 = (const __half2*)&u0;
        const __half2* h1 = (const __half2*)&u1;
#pragma unroll
        for (int j = 0; j < 2; j++) {
            float2 f0 = __half22float2(h0[j]);
            float2 f1 = __half22float2(h1[j]);
            acc[2 * j]     += f0.x + f1.x;
            acc[2 * j + 1] += f0.y + f1.y;
        }
    }
    if (i < e) {
        int n0 = __ldg(adj + i);
        uint2 u0 = *(const uint2*)(feat + (size_t)n0 * 128 + lo);
        const __half2* h0 = (const __half2*)&u0;
#pragma unroll
        for (int j = 0; j < 2; j++) {
            float2 f0 = __half22float2(h0[j]);
            acc[2 * j]     += f0.x;
            acc[2 * j + 1] += f0.y;
        }
    }
    float inv = 1.f / fmaxf((float)(e - s), 1.f);
    __half2 o[2];
#pragma unroll
    for (int j = 0; j < 2; j++)
        o[j] = __floats2half2_rn(acc[2 * j] * inv, acc[2 * j + 1] * inv);
    *(uint2*)(out + (size_t)gw * 128 + lo) = *(uint2*)o;
}

// ---------------- fp16 HMMA GEMM machinery (ldmatrix fragments) ----------------
#define A_ROW_B 80
#define B_ROW_B 528
#define A_STAGE_B (128*A_ROW_B)
#define B_STAGE_B (32*B_ROW_B)
#define STAGE_B   (A_STAGE_B + B_STAGE_B)
#define GEMM1_SMEM (4*STAGE_B)
#define H2_ROW_B 528
#define H2_TILE_B (128*H2_ROW_B)
#define GEMM2_SMEM (4*STAGE_B + H2_TILE_B)

__device__ __forceinline__ void mma_f16(float* d, const uint32_t* a, const uint32_t* b) {
    asm volatile(
        "mma.sync.aligned.m16n8k16.row.col.f32.f16.f16.f32 "
        "{%0,%1,%2,%3}, {%4,%5,%6,%7}, {%8,%9}, {%0,%1,%2,%3};"
        : "+f"(d[0]), "+f"(d[1]), "+f"(d[2]), "+f"(d[3])
        : "r"(a[0]), "r"(a[1]), "r"(a[2]), "r"(a[3]), "r"(b[0]), "r"(b[1]));
}
__device__ __forceinline__ void ldm_x4(uint32_t* r, uint32_t addr) {
    asm volatile("ldmatrix.sync.aligned.m8n8.x4.shared.b16 {%0,%1,%2,%3}, [%4];"
        : "=r"(r[0]), "=r"(r[1]), "=r"(r[2]), "=r"(r[3]) : "r"(addr));
}
__device__ __forceinline__ void ldm_x4t(uint32_t* r, uint32_t addr) {
    asm volatile("ldmatrix.sync.aligned.m8n8.x4.trans.shared.b16 {%0,%1,%2,%3}, [%4];"
        : "=r"(r[0]), "=r"(r[1]), "=r"(r[2]), "=r"(r[3]) : "r"(addr));
}

__device__ __forceinline__ void issue_ab(uint32_t sbase, int c, int k0, int K1,
                                         const __half* A1, const __half* A2, int K2,
                                         const __half* WTk, int bm, int Nrows, int tid) {
    int slot = c & 3;
    uint32_t aoff = sbase + slot * STAGE_B;
    uint32_t boff = aoff + A_STAGE_B;
    bool inA1 = (k0 < K1);
#pragma unroll
    for (int i = 0; i < 2; i++) {
        int idx = tid + i * 256;
        int row = idx >> 2, seg8 = (idx & 3) * 8;
        int grow = bm + row;
        bool ok = grow < Nrows;
        int gr = ok ? grow : 0;
        const __half* src = inA1 ? A1 + (size_t)gr * K1 + k0 + seg8
                                 : A2 + (size_t)gr * K2 + (k0 - K1) + seg8;
        uint32_t dst = aoff + (uint32_t)(row * A_ROW_B + seg8 * 2);
        int sz = ok ? 16 : 0;
        asm volatile("cp.async.cg.shared.global [%0], [%1], 16, %2;"
                     :: "r"(dst), "l"(src), "r"(sz));
    }
#pragma unroll
    for (int i = 0; i < 4; i++) {
        int idx = tid + i * 256;
        int kr = idx >> 5, seg = idx & 31;
        const __half* src = WTk + (size_t)(k0 + kr) * WROW + seg * 8;
        uint32_t dst = boff + (uint32_t)(kr * B_ROW_B + seg * 16);
        asm volatile("cp.async.cg.shared.global [%0], [%1], 16;"
                     :: "r"(dst), "l"(src));
    }
    asm volatile("cp.async.commit_group;");
}

__device__ __forceinline__ void issue_b(uint32_t sbase, int c, const __half* P, int tid) {
    int slot = c & 3;
    uint32_t boff = sbase + slot * STAGE_B + A_STAGE_B;
    int k0 = c << 5;
#pragma unroll
    for (int i = 0; i < 4; i++) {
        int idx = tid + i * 256;
        int kr = idx >> 5, seg = idx & 31;
        const __half* src = P + (size_t)(k0 + kr) * WROW + seg * 8;
        uint32_t dst = boff + (uint32_t)(kr * B_ROW_B + seg * 16);
        asm volatile("cp.async.cg.shared.global [%0], [%1], 16;"
                     :: "r"(dst), "l"(src));
    }
    asm volatile("cp.async.commit_group;");
}

__device__ __forceinline__ void mma_chunk(uint32_t aBase, uint32_t bBase, float acc[4][8][4]) {
#pragma unroll
    for (int s = 0; s < 2; s++) {
        uint32_t af[4][4], bf[4][4];
#pragma unroll
        for (int mt = 0; mt < 4; mt++)
            ldm_x4(af[mt], aBase + mt * (16 * A_ROW_B) + s * 32);
#pragma unroll
        for (int p = 0; p < 4; p++)
            ldm_x4t(bf[p], bBase + s * (16 * B_ROW_B) + p * 32);
#pragma unroll
        for (int mt = 0; mt < 4; mt++)
#pragma unroll
            for (int p = 0; p < 4; p++) {
                mma_f16(acc[mt][2 * p],     af[mt], &bf[p][0]);
                mma_f16(acc[mt][2 * p + 1], af[mt], &bf[p][2]);
            }
    }
}

// ---------------- layer-1 GEMM: single segment, relu epilogue ----------------
__global__ void __launch_bounds__(256)
gemm_sage(const __half* A1, int K1, const __half* A2, int K2,
          const __half* W, const float* bias, __half* C, int Nrows) {
    extern __shared__ char sm[];
    const int tid = threadIdx.x;
    const int wid = tid >> 5, lane = tid & 31;
    const int warpM = wid >> 2, warpN = wid & 3;
    const int lrow = lane >> 2, lcol = lane & 3;
    const int bm = blockIdx.x * 128;
    const int nch = (K1 + K2) >> 5;

    uint32_t sbase = (uint32_t)__cvta_generic_to_shared(sm);
    const uint32_t aLane = (uint32_t)((warpM * 64 + (lane & 15)) * A_ROW_B + ((lane & 16) ? 16 : 0));
    const uint32_t bLane = (uint32_t)((lane & 15) * B_ROW_B + (warpN * 64 + ((lane & 16) ? 8 : 0)) * 2);

    float2 bv[8];
#pragma unroll
    for (int nt = 0; nt < 8; nt++) {
        int col = warpN * 64 + nt * 8 + 2 * lcol;
        bv[nt].x = __ldg(bias + col); bv[nt].y = __ldg(bias + col + 1);
    }

    float acc[4][8][4];
#pragma unroll
    for (int i = 0; i < 4; i++)
#pragma unroll
        for (int j = 0; j < 8; j++)
#pragma unroll
            for (int q = 0; q < 4; q++) acc[i][j][q] = 0.f;

    issue_ab(sbase, 0, 0, K1, A1, A2, K2, W, bm, Nrows, tid);
    issue_ab(sbase, 1, 32, K1, A1, A2, K2, W, bm, Nrows, tid);
    issue_ab(sbase, 2, 64, K1, A1, A2, K2, W, bm, Nrows, tid);

    for (int c = 0; c < nch; c++) {
        asm volatile("cp.async.wait_group 2;");
        __syncthreads();
        if (c + 3 < nch) issue_ab(sbase, c + 3, (c + 3) << 5, K1, A1, A2, K2, W, bm, Nrows, tid);
        else asm volatile("cp.async.commit_group;");
        int slot = c & 3;
        mma_chunk(sbase + slot * STAGE_B + aLane,
                  sbase + slot * STAGE_B + A_STAGE_B + bLane, acc);
    }

#pragma unroll
    for (int mt = 0; mt < 4; mt++) {
        const int r0 = bm + warpM * 64 + mt * 16 + lrow;
#pragma unroll
        for (int half = 0; half < 2; half++) {
            const int row = r0 + half * 8;
            if (row >= Nrows) continue;
#pragma unroll
            for (int nt = 0; nt < 8; nt++) {
                const int col = warpN * 64 + nt * 8 + 2 * lcol;
                float vx = fmaxf(acc[mt][nt][half * 2 + 0] + bv[nt].x, 0.f);
                float vy = fmaxf(acc[mt][nt][half * 2 + 1] + bv[nt].y, 0.f);
                *(__half2*)(C + (size_t)row * 256 + col) = __floats2half2_rn(vx, vy);
            }
        }
    }
}

// ---------------- layer-2 GEMM + fused projection: single segment ----------------
__global__ void __launch_bounds__(256)
gemm_l2p(const __half* A1, const __half* A2, const __half* W, const float* bias,
         const __half* P, __half* U, int Nrows) {
    extern __shared__ char sm[];
    const int tid = threadIdx.x;
    const int wid = tid >> 5, lane = tid & 31;
    const int warpM = wid >> 2, warpN = wid & 3;
    const int lrow = lane >> 2, lcol = lane & 3;
    const int bm = blockIdx.x * 128;
    const int K1 = HID;
    const int nch = 16;

    uint32_t sbase = (uint32_t)__cvta_generic_to_shared(sm);
    uint32_t* H2 = (uint32_t*)(sm + 4 * STAGE_B);
    const uint32_t h2base = sbase + 4 * STAGE_B;
    const uint32_t aLane = (uint32_t)((warpM * 64 + (lane & 15)) * A_ROW_B + ((lane & 16) ? 16 : 0));
    const uint32_t bLane = (uint32_t)((lane & 15) * B_ROW_B + (warpN * 64 + ((lane & 16) ? 8 : 0)) * 2);
    const uint32_t h2Lane = h2base + (uint32_t)((warpM * 64 + (lane & 15)) * H2_ROW_B + ((lane & 16) ? 16 : 0));

    float2 bv[8];
#pragma unroll
    for (int nt = 0; nt < 8; nt++) {
        int col = warpN * 64 + nt * 8 + 2 * lcol;
        bv[nt].x = __ldg(bias + col); bv[nt].y = __ldg(bias + col + 1);
    }

    float acc[4][8][4];
#pragma unroll
    for (int i = 0; i < 4; i++)
#pragma unroll
        for (int j = 0; j < 8; j++)
#pragma unroll
            for (int q = 0; q < 4; q++) acc[i][j][q] = 0.f;

    issue_ab(sbase, 0, 0, K1, A1, A2, HID, W, bm, Nrows, tid);
    issue_ab(sbase, 1, 32, K1, A1, A2, HID, W, bm, Nrows, tid);
    issue_ab(sbase, 2, 64, K1, A1, A2, HID, W, bm, Nrows, tid);

    for (int c = 0; c < nch; c++) {
        asm volatile("cp.async.wait_group 2;");
        __syncthreads();
        if (c + 3 < nch) issue_ab(sbase, c + 3, (c + 3) << 5, K1, A1, A2, HID, W, bm, Nrows, tid);
        else asm volatile("cp.async.commit_group;");
        int slot = c & 3;
        mma_chunk(sbase + slot * STAGE_B + aLane,
                  sbase + slot * STAGE_B + A_STAGE_B + bLane, acc);
    }

    // store h2 tile (bias+relu, half) into smem; re-zero acc
#pragma unroll
    for (int mt = 0; mt < 4; mt++) {
#pragma unroll
        for (int half = 0; half < 2; half++) {
            const int row = warpM * 64 + mt * 16 + lrow + half * 8;
#pragma unroll
            for (int nt = 0; nt < 8; nt++) {
                const int col2 = warpN * 32 + nt * 4 + lcol;
                float vx = fmaxf(acc[mt][nt][half * 2 + 0] + bv[nt].x, 0.f);
                float vy = fmaxf(acc[mt][nt][half * 2 + 1] + bv[nt].y, 0.f);
                __half2 hv = __floats2half2_rn(vx, vy);
                H2[row * (H2_ROW_B / 4) + col2] = *(uint32_t*)&hv;
            }
        }
    }
#pragma unroll
    for (int i = 0; i < 4; i++)
#pragma unroll
        for (int j = 0; j < 8; j++)
#pragma unroll
            for (int q = 0; q < 4; q++) acc[i][j][q] = 0.f;
    __syncthreads();

    // projection loop: u = h2 @ P
    issue_b(sbase, 0, P, tid);
    issue_b(sbase, 1, P, tid);
    issue_b(sbase, 2, P, tid);

    for (int c = 0; c < 8; c++) {
        asm volatile("cp.async.wait_group 2;");
        __syncthreads();
        if (c + 3 < 8) issue_b(sbase, c + 3, P, tid);
        else asm volatile("cp.async.commit_group;");
        int slot = c & 3;
        uint32_t bB = sbase + slot * STAGE_B + A_STAGE_B + bLane;
#pragma unroll
        for (int s = 0; s < 2; s++) {
            uint32_t af[4][4], bf[4][4];
#pragma unroll
            for (int mt = 0; mt < 4; mt++)
                ldm_x4(af[mt], h2Lane + mt * (16 * H2_ROW_B) + c * 64 + s * 32);
#pragma unroll
            for (int p = 0; p < 4; p++)
                ldm_x4t(bf[p], bB + s * (16 * B_ROW_B) + p * 32);
#pragma unroll
            for (int mt = 0; mt < 4; mt++)
#pragma unroll
                for (int p = 0; p < 4; p++) {
                    mma_f16(acc[mt][2 * p],     af[mt], &bf[p][0]);
                    mma_f16(acc[mt][2 * p + 1], af[mt], &bf[p][2]);
                }
        }
    }

#pragma unroll
    for (int mt = 0; mt < 4; mt++) {
        const int r0 = bm + warpM * 64 + mt * 16 + lrow;
#pragma unroll
        for (int half = 0; half < 2; half++) {
            const int row = r0 + half * 8;
            if (row >= Nrows) continue;
#pragma unroll
            for (int nt = 0; nt < 8; nt++) {
                const int col = warpN * 64 + nt * 8 + 2 * lcol;
                *(__half2*)(U + (size_t)row * 256 + col) =
                    __floats2half2_rn(acc[mt][nt][half * 2 + 0], acc[mt][nt][half * 2 + 1]);
            }
        }
    }
}

// ---------------- weight composition (k-major half output) ----------------
__global__ void compose_kernel(const float* __restrict__ Wd1,
                               const float* __restrict__ Wlin_s,
                               const float* __restrict__ Wlin_t,
                               const float* __restrict__ blin_s,
                               const float* __restrict__ blin_t,
                               const float* __restrict__ bd1,
                               __half* WcsT, __half* WctT, float* bdc) {
    int i = blockIdx.x;
    int m = threadIdx.x;
    float ss = 0.f, st = 0.f;
    for (int k = 0; k < HID; k++) {
        float wl = Wd1[i * 2 * HID + k];
        float wr = Wd1[i * 2 * HID + HID + k];
        ss += wl * Wlin_s[k * HID + m];
        st += wr * Wlin_t[k * HID + m];
    }
    WcsT[(size_t)m * WROW + i] = __float2half_rn(ss);
    WctT[(size_t)m * WROW + i] = __float2half_rn(st);
    if (m == 0) {
        float b = bd1[i];
        for (int k = 0; k < HID; k++) {
            b += Wd1[i * 2 * HID + k] * blin_s[k];
            b += Wd1[i * 2 * HID + HID + k] * blin_t[k];
        }
        bdc[i] = b;
    }
}

// ---------------- decoder ----------------
__global__ void decode_kernel(const __half* __restrict__ us, const __half* __restrict__ ut,
                              const int* __restrict__ ls, const int* __restrict__ ld,
                              const float4* __restrict__ bdc, const float4* __restrict__ wd2,
                              const float* __restrict__ bd2,
                              float* __restrict__ out, int EL) {
    int g = blockIdx.x * blockDim.x + threadIdx.x;
    int w = g >> 5, lane = g & 31;
    if (w >= EL) return;
    const uint4* a = (const uint4*)(us + (size_t)__ldg(ls + w) * HID);
    const uint4* b = (const uint4*)(ut + (size_t)__ldg(ld + w) * HID);
    uint4 ua = a[lane], ub = b[lane];
    float4 c0 = bdc[lane * 2], c1 = bdc[lane * 2 + 1];
    float4 w0 = wd2[lane * 2], w1 = wd2[lane * 2 + 1];
    float2 a0 = __half22float2(*(__half2*)&ua.x), b0 = __half22float2(*(__half2*)&ub.x);
    float2 a1 = __half22float2(*(__half2*)&ua.y), b1 = __half22float2(*(__half2*)&ub.y);
    float2 a2 = __half22float2(*(__half2*)&ua.z), b2 = __half22float2(*(__half2*)&ub.z);
    float2 a3 = __half22float2(*(__half2*)&ua.w), b3 = __half22float2(*(__half2*)&ub.w);
    float sum =
        fmaxf(a0.x + b0.x + c0.x, 0.f) * w0.x + fmaxf(a0.y + b0.y + c0.y, 0.f) * w0.y +
        fmaxf(a1.x + b1.x + c0.z, 0.f) * w0.z + fmaxf(a1.y + b1.y + c0.w, 0.f) * w0.w +
        fmaxf(a2.x + b2.x + c1.x, 0.f) * w1.x + fmaxf(a2.y + b2.y + c1.y, 0.f) * w1.y +
        fmaxf(a3.x + b3.x + c1.z, 0.f) * w1.z + fmaxf(a3.y + b3.y + c1.w, 0.f) * w1.w;
#pragma unroll
    for (int o = 16; o; o >>= 1) sum += __shfl_xor_sync(0xffffffffu, sum, o);
    if (lane == 0) out[w] = sum + bd2[0];
}

// ---------------- launcher ----------------
extern "C" void kernel_launch(void* const* d_in, const int* in_sizes, int n_in,
                              void* d_out, int out_size) {
    const float* x_sotu  = (const float*)d_in[0];
    const float* x_taxon = (const float*)d_in[1];
    const int*   esrc    = (const int*)d_in[2];
    const int*   edst    = (const int*)d_in[3];
    const int*   lsrc    = (const int*)d_in[4];
    const int*   ldst    = (const int*)d_in[5];
    const float* Wl1_st  = (const float*)d_in[6];
    const float* bl1_st  = (const float*)d_in[7];
    const float* Wr1_st  = (const float*)d_in[8];
    const float* Wl1_ts  = (const float*)d_in[9];
    const float* bl1_ts  = (const float*)d_in[10];
    const float* Wr1_ts  = (const float*)d_in[11];
    const float* Wl2_st  = (const float*)d_in[12];
    const float* bl2_st  = (const float*)d_in[13];
    const float* Wr2_st  = (const float*)d_in[14];
    const float* Wl2_ts  = (const float*)d_in[15];
    const float* bl2_ts  = (const float*)d_in[16];
    const float* Wr2_ts  = (const float*)d_in[17];
    const float* Wlin_s  = (const float*)d_in[18];
    const float* blin_s  = (const float*)d_in[19];
    const float* Wlin_t  = (const float*)d_in[20];
    const float* blin_t  = (const float*)d_in[21];
    const float* Wd1     = (const float*)d_in[22];
    const float* bd1     = (const float*)d_in[23];
    const float* Wd2     = (const float*)d_in[24];
    const float* bd2     = (const float*)d_in[25];
    float* out = (float*)d_out;

    float *bdc;
    __half *aggTh, *aggSh, *h1t, *h1s, *us, *ut;
    __half *xrs, *xrt, *wt1st, *wt1ts, *wt2st, *wt2ts, *wcsT, *wctT;
    int *rowT, *rowS, *curT, *curS, *adjT, *adjS;
    cudaGetSymbolAddress((void**)&aggTh, g_aggTh);
    cudaGetSymbolAddress((void**)&aggSh, g_aggSh);
    cudaGetSymbolAddress((void**)&h1t, g_h1t);
    cudaGetSymbolAddress((void**)&h1s, g_h1s);
    cudaGetSymbolAddress((void**)&us,  g_us);
    cudaGetSymbolAddress((void**)&ut,  g_ut);
    cudaGetSymbolAddress((void**)&xrs, g_xr_s);
    cudaGetSymbolAddress((void**)&xrt, g_xr_t);
    cudaGetSymbolAddress((void**)&wt1st, g_wt1_st);
    cudaGetSymbolAddress((void**)&wt1ts, g_wt1_ts);
    cudaGetSymbolAddress((void**)&wt2st, g_wt2_st);
    cudaGetSymbolAddress((void**)&wt2ts, g_wt2_ts);
    cudaGetSymbolAddress((void**)&wcsT, g_wcsT);
    cudaGetSymbolAddress((void**)&wctT, g_wctT);
    cudaGetSymbolAddress((void**)&bdc, g_bdc);
    cudaGetSymbolAddress((void**)&rowT, g_rowT);
    cudaGetSymbolAddress((void**)&rowS, g_rowS);
    cudaGetSymbolAddress((void**)&curT, g_curT);
    cudaGetSymbolAddress((void**)&curS, g_curS);
    cudaGetSymbolAddress((void**)&adjT, g_adjT);
    cudaGetSymbolAddress((void**)&adjS, g_adjS);

    // one-time resources (created on the uncaptured correctness call)
    static cudaStream_t s2 = nullptr;
    static cudaEvent_t ev[8];
    static int inited = 0;
    if (!inited) {
        cudaFuncSetAttribute(gemm_sage, cudaFuncAttributeMaxDynamicSharedMemorySize, GEMM1_SMEM);
        cudaFuncSetAttribute(gemm_l2p, cudaFuncAttributeMaxDynamicSharedMemorySize, GEMM2_SMEM);
        cudaStreamCreateWithFlags(&s2, cudaStreamNonBlocking);
        for (int i = 0; i < 8; i++) cudaEventCreateWithFlags(&ev[i], cudaEventDisableTiming);
        inited = 1;
    }
    cudaStream_t s0 = 0;   // legacy default stream (the captured stream)

    const int gT = (N_TAXON + 127) / 128;   // 157
    const int gS = (N_SOTU + 127) / 128;    // 782
    const unsigned wT = (N_TAXON * 32 + 255) / 256;
    const unsigned wS = (N_SOTU * 32 + 255) / 256;

    // ---- fork 1: prep on s0 || CSR on s2 ----
    cudaEventRecord(ev[0], s0);
    cudaStreamWaitEvent(s2, ev[0], 0);

    long long nxs4 = (long long)N_SOTU * DS / 4, nxt4 = (long long)N_TAXON * DT / 4;
    tohalf_dual<<<(unsigned)((nxs4 + nxt4 + 255) / 256), 256, 0, s0>>>(
        (const float4*)x_sotu, (__half2*)xrs, nxs4,
        (const float4*)x_taxon, (__half2*)xrt, nxt4);
    wt_all<<<1792, 256, 0, s0>>>(Wl1_st, Wr1_st, wt1st,
                                 Wl1_ts, Wr1_ts, wt1ts,
                                 Wl2_st, Wr2_st, wt2st,
                                 Wl2_ts, Wr2_ts, wt2ts);
    compose_kernel<<<HID, HID, 0, s0>>>(Wd1, Wlin_s, Wlin_t, blin_s, blin_t, bd1, wcsT, wctT, bdc);

    zero_dual<<<(N_SOTU + 255) / 256, 256, 0, s2>>>(curT, N_TAXON, curS, N_SOTU);
    hist_kernel<<<(NE + 255) / 256, 256, 0, s2>>>(esrc, edst, curS, curT, NE);
    scan_dual<<<2, 1024, 0, s2>>>(curT, rowT, N_TAXON, curS, rowS, N_SOTU);
    fill_kernel<<<(NE + 255) / 256, 256, 0, s2>>>(esrc, edst, rowT, curT, adjT, rowS, curS, adjS, NE);

    // ---- join, then fork 2: layer-1 taxon chain on s0 || sotu chain on s2 ----
    cudaEventRecord(ev[1], s2);
    cudaStreamWaitEvent(s0, ev[1], 0);
    cudaEventRecord(ev[2], s0);
    cudaStreamWaitEvent(s2, ev[2], 0);

    agg256_kernel<<<wT, 256, 0, s0>>>(xrs, rowT, adjT, aggTh, N_TAXON);
    gemm_sage<<<(unsigned)gT, 256, GEMM1_SMEM, s0>>>(aggTh, DS, xrt, DT, wt1st, bl1_st, h1t, N_TAXON);

    agg128_kernel<<<wS, 256, 0, s2>>>(xrt, rowS, adjS, aggSh, N_SOTU);
    gemm_sage<<<(unsigned)gS, 256, GEMM1_SMEM, s2>>>(aggSh, DT, xrs, DS, wt1ts, bl1_ts, h1s, N_SOTU);

    // ---- join (layer 2 needs both h1t and h1s), fork 3 ----
    cudaEventRecord(ev[3], s2);
    cudaStreamWaitEvent(s0, ev[3], 0);
    cudaEventRecord(ev[4], s0);
    cudaStreamWaitEvent(s2, ev[4], 0);

    agg256_kernel<<<wT, 256, 0, s0>>>(h1s, rowT, adjT, aggTh, N_TAXON);
    gemm_l2p<<<(unsigned)gT, 256, GEMM2_SMEM, s0>>>(aggTh, h1t, wt2st, bl2_st, wctT, ut, N_TAXON);

    agg256_kernel<<<wS, 256, 0, s2>>>(h1t, rowS, adjS, aggSh, N_SOTU);
    gemm_l2p<<<(unsigned)gS, 256, GEMM2_SMEM, s2>>>(aggSh, h1s, wt2ts, bl2_ts, wcsT, us, N_SOTU);

    // ---- join, decode on s0 ----
    cudaEventRecord(ev[5], s2);
    cudaStreamWaitEvent(s0, ev[5], 0);

    decode_kernel<<<(NEL * 32 + 255) / 256, 256, 0, s0>>>(
        us, ut, lsrc, ldst,
        (const float4*)bdc, (const float4*)Wd2, bd2, out, NEL);
}